// round 10
// baseline (speedup 1.0000x reference)
#include <cuda_runtime.h>
#include <cuda_bf16.h>
#include <cuda_fp16.h>

#define Bb    2
#define NSEQ  8192
#define DIMV  512
#define NH    8
#define BHn   16
#define DHd   64
#define MLM   256
#define LGRP  32
#define KSZ   33
#define PADc  16
#define SCALE 0.125f

// ================= static device scratch =================
__device__ float g_xn[(size_t)Bb * NSEQ * DIMV];
__device__ float g_xnlm[512 * 512];
__device__ float g_ql[BHn * MLM * DHd];
__device__ float g_kl[BHn * MLM * DHd];
__device__ float g_attn2[BHn * MLM * MLM];
__device__ float g_Y[BHn * MLM * MLM];
__device__ float g_P[BHn * MLM * MLM];
__device__ float g_Qm[BHn * MLM * MLM];
__device__ float g_Za[BHn * MLM * MLM];
__device__ float g_Zb[BHn * MLM * MLM];
__device__ float g_W2[BHn * MLM * DHd];
__device__ float g_W3[BHn * MLM * DHd];
__device__ float g_Wpart[(size_t)BHn * 4 * MLM * DHd];
__device__ float g_Spart[BHn * 4 * MLM];
__device__ int   g_maxc_bits;

// bf16 hi/lo buffers (landmark GEMM)
__device__ __nv_bfloat16 g_Ahi[512 * 512];
__device__ __nv_bfloat16 g_Alo[512 * 512];
__device__ __nv_bfloat16 g_Bqh[1536 * 512];
__device__ __nv_bfloat16 g_Bql[1536 * 512];

// fp16 buffers
__device__ __half g_A16[(size_t)Bb * NSEQ * DIMV];
__device__ __half g_B16q[1536 * 512];
__device__ __half g_B16o[512 * 512];
__device__ __half g_qh[(size_t)BHn * NSEQ * DHd];
__device__ __half g_kh[(size_t)BHn * NSEQ * DHd];
__device__ __half g_vh[(size_t)BHn * NSEQ * DHd];
__device__ __half g_qlh[BHn * MLM * DHd];
__device__ __half g_klh[BHn * MLM * DHd];
__device__ __half g_W3T[BHn * DHd * MLM];

__global__ void reset_kernel() { g_maxc_bits = 0; }

// ================= mma.sync helpers =================
__device__ __forceinline__ unsigned smem_u32(const void* p) {
    unsigned a;
    asm("{ .reg .u64 t; cvta.to.shared.u64 t, %1; cvt.u32.u64 %0, t; }" : "=r"(a) : "l"(p));
    return a;
}
__device__ __forceinline__ void ldm4(unsigned* r, unsigned addr) {
    asm volatile("ldmatrix.sync.aligned.m8n8.x4.shared.b16 {%0,%1,%2,%3}, [%4];"
        : "=r"(r[0]), "=r"(r[1]), "=r"(r[2]), "=r"(r[3]) : "r"(addr));
}
__device__ __forceinline__ void mma16816(float* c, const unsigned* a, unsigned b0, unsigned b1) {
    asm volatile("mma.sync.aligned.m16n8k16.row.col.f32.bf16.bf16.f32 "
        "{%0,%1,%2,%3}, {%4,%5,%6,%7}, {%8,%9}, {%0,%1,%2,%3};"
        : "+f"(c[0]), "+f"(c[1]), "+f"(c[2]), "+f"(c[3])
        : "r"(a[0]), "r"(a[1]), "r"(a[2]), "r"(a[3]), "r"(b0), "r"(b1));
}
__device__ __forceinline__ void mmaf16(float* c, const unsigned* a, unsigned b0, unsigned b1) {
    asm volatile("mma.sync.aligned.m16n8k16.row.col.f32.f16.f16.f32 "
        "{%0,%1,%2,%3}, {%4,%5,%6,%7}, {%8,%9}, {%0,%1,%2,%3};"
        : "+f"(c[0]), "+f"(c[1]), "+f"(c[2]), "+f"(c[3])
        : "r"(a[0]), "r"(a[1]), "r"(a[2]), "r"(a[3]), "r"(b0), "r"(b1));
}
__device__ __forceinline__ void cpasync16(unsigned dst, const void* src) {
    asm volatile("cp.async.cg.shared.global [%0], [%1], 16;" :: "r"(dst), "l"(src));
}
#define CP_COMMIT() asm volatile("cp.async.commit_group;" ::: "memory")
__device__ __forceinline__ unsigned packh2(float a, float b) {
    __half2 h = __floats2half2_rn(a, b);
    return *(unsigned*)&h;
}
__device__ __forceinline__ float fexp(float x) {
    float t = x * 1.44269504f;
    float r = rintf(t);
    float f = t - r;
    float p = 1.33336e-3f;
    p = fmaf(p, f, 9.61813e-3f);
    p = fmaf(p, f, 5.55041e-2f);
    p = fmaf(p, f, 2.40226507e-1f);
    p = fmaf(p, f, 6.93147181e-1f);
    p = fmaf(p, f, 1.0f);
    int e = (int)r;
    return p * __int_as_float((e + 127) << 23);
}

// ================= layernorm (writes fp32 + fp16) =================
__global__ __launch_bounds__(128) void ln_kernel(const float* __restrict__ x,
                                                 const float* __restrict__ gam,
                                                 const float* __restrict__ bet) {
    int row = blockIdx.x;
    int tid = threadIdx.x;
    float4 v = ((const float4*)x)[(size_t)row * 128 + tid];
    float s1 = v.x + v.y + v.z + v.w;
    float s2 = v.x * v.x + v.y * v.y + v.z * v.z + v.w * v.w;
#pragma unroll
    for (int o = 16; o; o >>= 1) {
        s1 += __shfl_xor_sync(0xffffffffu, s1, o);
        s2 += __shfl_xor_sync(0xffffffffu, s2, o);
    }
    __shared__ float r1[4], r2[4];
    int w = tid >> 5;
    if ((tid & 31) == 0) { r1[w] = s1; r2[w] = s2; }
    __syncthreads();
    s1 = r1[0] + r1[1] + r1[2] + r1[3];
    s2 = r2[0] + r2[1] + r2[2] + r2[3];
    float mean = s1 * (1.f / 512.f);
    float var  = s2 * (1.f / 512.f) - mean * mean;
    float rstd = rsqrtf(var + 1e-5f);
    float4 g4 = ((const float4*)gam)[tid];
    float4 b4 = ((const float4*)bet)[tid];
    float4 o;
    o.x = (v.x - mean) * rstd * g4.x + b4.x;
    o.y = (v.y - mean) * rstd * g4.y + b4.y;
    o.z = (v.z - mean) * rstd * g4.z + b4.z;
    o.w = (v.w - mean) * rstd * g4.w + b4.w;
    ((float4*)g_xn)[(size_t)row * 128 + tid] = o;
    __half2* ph = (__half2*)(g_A16 + (size_t)row * 512 + tid * 4);
    ph[0] = __floats2half2_rn(o.x, o.y);
    ph[1] = __floats2half2_rn(o.z, o.w);
}

// ================= group means of xn (landmark pre-image) =================
__global__ void xnlm_kernel() {
    int idx = blockIdx.x * 256 + threadIdx.x;
    int row = idx >> 9;
    int d = idx & 511;
    int b = row >> 8, m = row & 255;
    const float* p = g_xn + ((size_t)(b * NSEQ) + m * LGRP) * DIMV + d;
    float s = 0.f;
#pragma unroll
    for (int i = 0; i < LGRP; i++) s += p[(size_t)i * DIMV];
    g_xnlm[idx] = s * (1.f / LGRP);
}

// ================= converters =================
__global__ __launch_bounds__(256) void convA_kernel(const float* __restrict__ src) {
    size_t i4 = ((size_t)blockIdx.x * 256 + threadIdx.x) * 4;
    float4 v = *(const float4*)(src + i4);
    __nv_bfloat16 h0 = __float2bfloat16(v.x), h1 = __float2bfloat16(v.y);
    __nv_bfloat16 h2 = __float2bfloat16(v.z), h3 = __float2bfloat16(v.w);
    __nv_bfloat16 l0 = __float2bfloat16(v.x - __bfloat162float(h0));
    __nv_bfloat16 l1 = __float2bfloat16(v.y - __bfloat162float(h1));
    __nv_bfloat16 l2 = __float2bfloat16(v.z - __bfloat162float(h2));
    __nv_bfloat16 l3 = __float2bfloat16(v.w - __bfloat162float(h3));
    __nv_bfloat162* ph = (__nv_bfloat162*)(g_Ahi + i4);
    __nv_bfloat162* pl = (__nv_bfloat162*)(g_Alo + i4);
    ph[0] = __nv_bfloat162(h0, h1); ph[1] = __nv_bfloat162(h2, h3);
    pl[0] = __nv_bfloat162(l0, l1); pl[1] = __nv_bfloat162(l2, l3);
}

__global__ __launch_bounds__(1024) void convW_kernel(const float* __restrict__ W, int N,
                                                     __nv_bfloat16* __restrict__ BThi,
                                                     __nv_bfloat16* __restrict__ BTlo) {
    __shared__ float sh[32][33];
    int n0 = blockIdx.x * 32, k0 = blockIdx.y * 32;
    int tx = threadIdx.x & 31, ty = threadIdx.x >> 5;
    sh[ty][tx] = W[(size_t)(k0 + ty) * N + n0 + tx];
    __syncthreads();
    float x = sh[tx][ty];
    __nv_bfloat16 h = __float2bfloat16(x);
    __nv_bfloat16 l = __float2bfloat16(x - __bfloat162float(h));
    BThi[(size_t)(n0 + ty) * 512 + k0 + tx] = h;
    BTlo[(size_t)(n0 + ty) * 512 + k0 + tx] = l;
}

__global__ __launch_bounds__(1024) void convW16_kernel(const float* __restrict__ W, int N,
                                                       __half* __restrict__ BT) {
    __shared__ float sh[32][33];
    int n0 = blockIdx.x * 32, k0 = blockIdx.y * 32;
    int tx = threadIdx.x & 31, ty = threadIdx.x >> 5;
    sh[ty][tx] = W[(size_t)(k0 + ty) * N + n0 + tx];
    __syncthreads();
    BT[(size_t)(n0 + ty) * 512 + k0 + tx] = __float2half(sh[tx][ty]);
}

// W3 -> W3T fp16 [bh][d][m]
__global__ void w3t_kernel() {
    int idx = blockIdx.x * 256 + threadIdx.x;
    int bh = idx >> 14;
    int m = (idx >> 6) & 255;
    int d = idx & 63;
    float v = g_W3[(bh * 256 + m) * 64 + d];
    g_W3T[((size_t)bh * 64 + d) * 256 + m] = __float2half(v);
}

// ================= fp16 single-pass dense GEMM (cp.async double-buffered) =================
__global__ __launch_bounds__(256) void gemm16_kernel(
    const __half* __restrict__ gBbase, int mode,
    const float* __restrict__ bout, float* __restrict__ outp) {
    extern __shared__ char smdyn[];
    unsigned sbase = smem_u32(smdyn);
    int tid = threadIdx.x, lane = tid & 31, wid = tid >> 5;
    int wm = wid & 3, wn = wid >> 2;
    int mBase = blockIdx.y * 128, nBase = blockIdx.x * 128;
    int lr = lane & 15, lh = lane >> 4;

    const __half* gA = g_A16 + (size_t)mBase * 512;
    const __half* gB = gBbase + (size_t)nBase * 512;

    float acc[2][8][4];
#pragma unroll
    for (int i = 0; i < 2; i++)
#pragma unroll
        for (int j = 0; j < 8; j++)
#pragma unroll
            for (int c = 0; c < 4; c++) acc[i][j][c] = 0.f;

    int r_ld = tid >> 1;
    int q2 = (tid & 1) * 4;

    auto load_stage = [&](int ch, unsigned st) {
#pragma unroll
        for (int u = 0; u < 4; u++) {
            unsigned soff = (unsigned)r_ld * 144u + (q2 + u) * 16u;
            size_t goff = (size_t)r_ld * 512 + ch * 64 + (q2 + u) * 8;
            cpasync16(sbase + st + soff, gA + goff);
            cpasync16(sbase + st + 18432u + soff, gB + goff);
        }
        CP_COMMIT();
    };

    load_stage(0, 0u);

    for (int ch = 0; ch < 8; ch++) {
        unsigned st = (unsigned)(ch & 1) * 36864u;
        if (ch + 1 < 8) {
            load_stage(ch + 1, (unsigned)((ch + 1) & 1) * 36864u);
            asm volatile("cp.async.wait_group 1;" ::: "memory");
        } else {
            asm volatile("cp.async.wait_group 0;" ::: "memory");
        }
        __syncthreads();

        unsigned aA = sbase + st;
        unsigned aB = aA + 18432u;
#pragma unroll
        for (int ks = 0; ks < 4; ks++) {
            unsigned kc2 = (unsigned)(ks * 16 + lh * 8) * 2u;
            unsigned ah[2][4];
#pragma unroll
            for (int mi = 0; mi < 2; mi++) {
                unsigned rowA = (unsigned)(wm * 32 + mi * 16 + lr) * 144u;
                ldm4(ah[mi], aA + rowA + kc2);
            }
#pragma unroll
            for (int nt = 0; nt < 4; nt++) {
                unsigned rowB = (unsigned)(wn * 64 + nt * 16 + lr) * 144u;
                unsigned bf[4];
                ldm4(bf, aB + rowB + kc2);
#pragma unroll
                for (int mi = 0; mi < 2; mi++) {
#pragma unroll
                    for (int ns = 0; ns < 2; ns++)
                        mmaf16(acc[mi][nt * 2 + ns], ah[mi], bf[ns], bf[ns + 2]);
                }
            }
        }
        __syncthreads();
    }

    int r0 = mBase + wm * 32 + (lane >> 2);
    if (mode == 0) {
        int sec = nBase >> 9;
        float sc = (sec == 0) ? SCALE : 1.f;
        __half* hdst = (sec == 0) ? g_qh : ((sec == 1) ? g_kh : g_vh);
        int h = ((nBase + wn * 64) >> 6) & 7;
#pragma unroll
        for (int mi = 0; mi < 2; mi++) {
#pragma unroll
            for (int jn = 0; jn < 8; jn++) {
                int d = jn * 8 + (lane & 3) * 2;
#pragma unroll
                for (int half = 0; half < 2; half++) {
                    int gr = r0 + mi * 16 + half * 8;
                    int bb = gr >> 13, n = gr & 8191;
                    size_t off = ((size_t)(bb * 8 + h) * NSEQ + n) * 64 + d;
                    *(__half2*)&hdst[off] = __floats2half2_rn(acc[mi][jn][half * 2] * sc,
                                                              acc[mi][jn][half * 2 + 1] * sc);
                }
            }
        }
    } else {
#pragma unroll
        for (int mi = 0; mi < 2; mi++) {
#pragma unroll
            for (int jn = 0; jn < 8; jn++) {
                int gc = nBase + wn * 64 + jn * 8 + (lane & 3) * 2;
#pragma unroll
                for (int half = 0; half < 2; half++) {
                    int gr = r0 + mi * 16 + half * 8;
                    float2 bo = *(const float2*)&bout[gc];
                    float2 xv = *(const float2*)&g_xn[(size_t)gr * 512 + gc];
                    float2 o = make_float2(acc[mi][jn][half * 2] + bo.x + xv.x,
                                           acc[mi][jn][half * 2 + 1] + bo.y + xv.y);
                    *(float2*)&outp[(size_t)gr * 512 + gc] = o;
                }
            }
        }
    }
}

// ================= bf16 split landmark GEMM (M=512, N=1024) =================
__global__ __launch_bounds__(256) void gemm_lm_kernel(
    const __nv_bfloat16* __restrict__ BThi, const __nv_bfloat16* __restrict__ BTlo) {
    extern __shared__ char smdyn[];
    unsigned sbase = smem_u32(smdyn);
    int tid = threadIdx.x, lane = tid & 31, wid = tid >> 5;
    int wm = wid & 3, wn = wid >> 2;
    int mBase = blockIdx.y * 128, nBase = blockIdx.x * 128;
    int lr = lane & 15, lh = lane >> 4;

    const __nv_bfloat16* gsrc[4];
    gsrc[0] = g_Ahi + (size_t)mBase * 512;
    gsrc[1] = g_Alo + (size_t)mBase * 512;
    gsrc[2] = BThi + (size_t)nBase * 512;
    gsrc[3] = BTlo + (size_t)nBase * 512;

    float acc[2][8][4];
#pragma unroll
    for (int i = 0; i < 2; i++)
#pragma unroll
        for (int j = 0; j < 8; j++)
#pragma unroll
            for (int c = 0; c < 4; c++) acc[i][j][c] = 0.f;

    int r_ld0 = tid >> 2, q_ld = tid & 3;
    unsigned so0 = (unsigned)r_ld0 * 80u + q_ld * 16u;
    unsigned so1 = (unsigned)(r_ld0 + 64) * 80u + q_ld * 16u;

    {
        size_t go0 = (size_t)r_ld0 * 512 + q_ld * 8;
        size_t go1 = (size_t)(r_ld0 + 64) * 512 + q_ld * 8;
#pragma unroll
        for (int a = 0; a < 4; a++) {
            cpasync16(sbase + a * 10240u + so0, gsrc[a] + go0);
            cpasync16(sbase + a * 10240u + so1, gsrc[a] + go1);
        }
        CP_COMMIT();
    }

    for (int ch = 0; ch < 16; ch++) {
        unsigned st = (unsigned)(ch & 1) * 40960u;
        if (ch + 1 < 16) {
            unsigned stn = (unsigned)((ch + 1) & 1) * 40960u;
            size_t go0 = (size_t)r_ld0 * 512 + (ch + 1) * 32 + q_ld * 8;
            size_t go1 = (size_t)(r_ld0 + 64) * 512 + (ch + 1) * 32 + q_ld * 8;
#pragma unroll
            for (int a = 0; a < 4; a++) {
                cpasync16(sbase + stn + a * 10240u + so0, gsrc[a] + go0);
                cpasync16(sbase + stn + a * 10240u + so1, gsrc[a] + go1);
            }
            CP_COMMIT();
            asm volatile("cp.async.wait_group 1;" ::: "memory");
        } else {
            asm volatile("cp.async.wait_group 0;" ::: "memory");
        }
        __syncthreads();

        unsigned aAh = sbase + st;
        unsigned aAl = aAh + 10240u;
        unsigned aBh = aAh + 20480u;
        unsigned aBl = aAh + 30720u;
#pragma unroll
        for (int ks = 0; ks < 2; ks++) {
            unsigned kc2 = (unsigned)(ks * 16 + lh * 8) * 2u;
            unsigned ah[2][4], al[2][4];
#pragma unroll
            for (int mi = 0; mi < 2; mi++) {
                unsigned rowA = (unsigned)(wm * 32 + mi * 16 + lr) * 80u;
                ldm4(ah[mi], aAh + rowA + kc2);
                ldm4(al[mi], aAl + rowA + kc2);
            }
#pragma unroll
            for (int nt = 0; nt < 4; nt++) {
                unsigned rowB = (unsigned)(wn * 64 + nt * 16 + lr) * 80u;
                unsigned bh[4], bl[4];
                ldm4(bh, aBh + rowB + kc2);
                ldm4(bl, aBl + rowB + kc2);
#pragma unroll
                for (int mi = 0; mi < 2; mi++) {
#pragma unroll
                    for (int ns = 0; ns < 2; ns++) {
                        float* cc = acc[mi][nt * 2 + ns];
                        mma16816(cc, ah[mi], bh[ns], bh[ns + 2]);
                        mma16816(cc, ah[mi], bl[ns], bl[ns + 2]);
                        mma16816(cc, al[mi], bh[ns], bh[ns + 2]);
                    }
                }
            }
        }
        __syncthreads();
    }

    int r0 = mBase + wm * 32 + (lane >> 2);
    int sec = nBase >> 9;
    float sc = (sec == 0) ? SCALE : 1.f;
    float* dst = (sec == 0) ? g_ql : g_kl;
    __half* hdst = (sec == 0) ? g_qlh : g_klh;
    int h = ((nBase + wn * 64) >> 6) & 7;
#pragma unroll
    for (int mi = 0; mi < 2; mi++) {
#pragma unroll
        for (int jn = 0; jn < 8; jn++) {
            int d = jn * 8 + (lane & 3) * 2;
#pragma unroll
            for (int half = 0; half < 2; half++) {
                int gr = r0 + mi * 16 + half * 8;
                int bb = gr >> 8, m = gr & 255;
                float2 o = make_float2(acc[mi][jn][half * 2] * sc,
                                       acc[mi][jn][half * 2 + 1] * sc);
                size_t off = ((size_t)(bb * 8 + h) * MLM + m) * 64 + d;
                *(float2*)&dst[off] = o;
                *(__half2*)&hdst[off] = __floats2half2_rn(o.x, o.y);
            }
        }
    }
}

// ================= attn2 = softmax(q_l k_l^T) =================
__global__ __launch_bounds__(256) void attn2_kernel() {
    int bh = blockIdx.x;
    int m = threadIdx.x;
    __shared__ float4 kls[1024];
    float4 q[16];
    const float4* qp = (const float4*)g_ql + (size_t)(bh * MLM + m) * 16;
#pragma unroll
    for (int i = 0; i < 16; i++) q[i] = qp[i];
    float sum = 0.f;
    float* arow = g_attn2 + (size_t)bh * 65536 + (size_t)m * 256;
    for (int tile = 0; tile < 4; tile++) {
        __syncthreads();
        const float4* src = (const float4*)g_kl + (size_t)(bh * MLM + tile * 64) * 16;
#pragma unroll
        for (int i = 0; i < 4; i++) kls[threadIdx.x + i * 256] = src[threadIdx.x + i * 256];
        __syncthreads();
        for (int j = 0; j < 64; j++) {
            const float4* kr = &kls[j * 16];
            float s = 0.f;
#pragma unroll
            for (int d = 0; d < 16; d++) {
                float4 a = q[d], b = kr[d];
                s += a.x * b.x + a.y * b.y + a.z * b.z + a.w * b.w;
            }
            float p = __expf(s);
            sum += p;
            arow[tile * 64 + j] = p;
        }
    }
    float inv = 1.f / sum;
    for (int j = 0; j < 256; j++) arow[j] *= inv;
}

// ================= max column-sum of attn2 =================
__global__ __launch_bounds__(256) void colmax_kernel() {
    int bh = blockIdx.x;
    int j = threadIdx.x;
    const float* a = g_attn2 + (size_t)bh * 65536;
    float s = 0.f;
    for (int m2 = 0; m2 < 256; m2++) s += a[m2 * 256 + j];
    __shared__ float red[256];
    red[j] = s;
    __syncthreads();
    for (int o = 128; o; o >>= 1) {
        if (j < o) red[j] = fmaxf(red[j], red[j + o]);
        __syncthreads();
    }
    if (j == 0) atomicMax(&g_maxc_bits, __float_as_int(red[0]));
}

__global__ void z0_kernel() {
    int idx = blockIdx.x * 256 + threadIdx.x;
    int bh = idx >> 16;
    int i = (idx >> 8) & 255;
    int j = idx & 255;
    float scale = 1.f / __int_as_float(g_maxc_bits);
    g_Za[idx] = g_attn2[(bh << 16) + (j << 8) + i] * scale;
}

// ================= buffer selector =================
__device__ __forceinline__ float* pickBuf(int id) {
    switch (id) {
        case 0: return g_attn2;
        case 1: return g_Y;
        case 2: return g_P;
        case 3: return g_Qm;
        case 4: return g_Za;
        case 5: return g_Zb;
        case 6: return g_W2;
        default: return g_W3;
    }
}

// ================= pinv batched GEMM, 64x64 tiles, 128 threads =================
// grid (4 n, 4 m, 16 bh) = 256 CTAs for occupancy.
__global__ __launch_bounds__(128) void gemm_pinv_mma(int cId, int aId, int bId,
                                                     float beta, float sgn, float alpha,
                                                     int passes) {
    __shared__ __align__(16) __nv_bfloat16 sAh[64][40];
    __shared__ __align__(16) __nv_bfloat16 sAl[64][40];
    __shared__ __align__(16) __nv_bfloat16 sBh[64][40];
    __shared__ __align__(16) __nv_bfloat16 sBl[64][40];

    int bh = blockIdx.z;
    int mBase = blockIdx.y * 64, nBase = blockIdx.x * 64;
    const float* A = pickBuf(aId) + (size_t)bh * 65536;
    const float* B = pickBuf(bId) + (size_t)bh * 65536;
    float*       C = pickBuf(cId) + (size_t)bh * 65536;

    int tid = threadIdx.x, lane = tid & 31, w = tid >> 5;
    int lr = lane & 15, lh = lane >> 4;
    bool full = (passes == 3);

    float acc[8][4];
#pragma unroll
    for (int j = 0; j < 8; j++)
#pragma unroll
        for (int c = 0; c < 4; c++) acc[j][c] = 0.f;

    for (int ch = 0; ch < 8; ch++) {
        if (ch) __syncthreads();
        // A tile 64x32 fp32 -> hi/lo
#pragma unroll
        for (int i = 0; i < 4; i++) {
            int idx = tid + i * 128;
            int r = idx >> 3, c4 = (idx & 7) * 4;
            float4 v = *(const float4*)&A[(size_t)(mBase + r) * 256 + ch * 32 + c4];
            __nv_bfloat16 h0 = __float2bfloat16(v.x), h1 = __float2bfloat16(v.y);
            __nv_bfloat16 h2 = __float2bfloat16(v.z), h3 = __float2bfloat16(v.w);
            sAh[r][c4 + 0] = h0; sAh[r][c4 + 1] = h1;
            sAh[r][c4 + 2] = h2; sAh[r][c4 + 3] = h3;
            if (full) {
                sAl[r][c4 + 0] = __float2bfloat16(v.x - __bfloat162float(h0));
                sAl[r][c4 + 1] = __float2bfloat16(v.y - __bfloat162float(h1));
                sAl[r][c4 + 2] = __float2bfloat16(v.z - __bfloat162float(h2));
                sAl[r][c4 + 3] = __float2bfloat16(v.w - __bfloat162float(h3));
            }
        }
        // B tile 32k x 64n fp32 fold -> transposed hi/lo
#pragma unroll
        for (int kl = 0; kl < 8; kl++) {
            int gk = ch * 32 + w * 8 + kl;
#pragma unroll
            for (int nh = 0; nh < 2; nh++) {
                int n = nh * 32 + lane;
                float v = B[(size_t)gk * 256 + nBase + n];
                v = sgn * v + ((gk == nBase + n) ? beta : 0.f);
                __nv_bfloat16 h = __float2bfloat16(v);
                sBh[n][w * 8 + kl] = h;
                if (full) sBl[n][w * 8 + kl] = __float2bfloat16(v - __bfloat162float(h));
            }
        }
        __syncthreads();
#pragma unroll
        for (int ks = 0; ks < 2; ks++) {
            int kc = ks * 16 + lh * 8;
            unsigned ah[4], al[4];
            int rowA = w * 16 + lr;
            ldm4(ah, smem_u32(&sAh[rowA][kc]));
            if (full) ldm4(al, smem_u32(&sAl[rowA][kc]));
#pragma unroll
            for (int nt = 0; nt < 4; nt++) {
                int rowB = nt * 16 + lr;
                unsigned bhf[4], blf[4];
                ldm4(bhf, smem_u32(&sBh[rowB][kc]));
                if (full) ldm4(blf, smem_u32(&sBl[rowB][kc]));
#pragma unroll
                for (int ns = 0; ns < 2; ns++) {
                    float* cc = acc[nt * 2 + ns];
                    mma16816(cc, ah, bhf[ns], bhf[ns + 2]);
                    if (full) {
                        mma16816(cc, ah, blf[ns], blf[ns + 2]);
                        mma16816(cc, al, bhf[ns], bhf[ns + 2]);
                    }
                }
            }
        }
    }
#pragma unroll
    for (int jn = 0; jn < 8; jn++) {
        int gc = nBase + jn * 8 + (lane & 3) * 2;
#pragma unroll
        for (int half = 0; half < 2; half++) {
            int gr = mBase + w * 16 + (lane >> 2) + half * 8;
            float2 o = make_float2(acc[jn][half * 2] * alpha,
                                   acc[jn][half * 2 + 1] * alpha);
            *(float2*)&C[(size_t)gr * 256 + gc] = o;
        }
    }
}

// ================= batched per-bh GEMM (scalar, kept for W3) =================
__global__ __launch_bounds__(256) void gemm_bh_kernel(int cId, int aId, int bId, int Nn,
                                                      float beta, float sgn, float alpha) {
    int bh = blockIdx.z, mt = blockIdx.y, nt = blockIdx.x;
    const float* A  = pickBuf(aId) + (size_t)bh * 65536;
    const float* Bp = pickBuf(bId) + (size_t)bh * 256 * Nn;
    float*       C  = pickBuf(cId) + (size_t)bh * 256 * Nn;
    __shared__ float As[16][64];
    __shared__ float Bs[16][64];
    int tid = threadIdx.x;
    int ar = tid >> 2, ac = (tid & 3) * 4;
    int br = tid >> 4, bc = (tid & 15) * 4;
    int ty = tid >> 4, tx = tid & 15;
    float acc[4][4];
#pragma unroll
    for (int i = 0; i < 4; i++)
#pragma unroll
        for (int j = 0; j < 4; j++) acc[i][j] = 0.f;

    for (int k0 = 0; k0 < 256; k0 += 16) {
        float4 av = *(const float4*)&A[(size_t)(mt * 64 + ar) * 256 + k0 + ac];
        As[ac + 0][ar] = av.x; As[ac + 1][ar] = av.y;
        As[ac + 2][ar] = av.z; As[ac + 3][ar] = av.w;
        int gk = k0 + br;
        int gc = nt * 64 + bc;
        float4 bv = *(const float4*)&Bp[(size_t)gk * Nn + gc];
        bv.x = sgn * bv.x + (gk == gc + 0 ? beta : 0.f);
        bv.y = sgn * bv.y + (gk == gc + 1 ? beta : 0.f);
        bv.z = sgn * bv.z + (gk == gc + 2 ? beta : 0.f);
        bv.w = sgn * bv.w + (gk == gc + 3 ? beta : 0.f);
        *(float4*)&Bs[br][bc] = bv;
        __syncthreads();
#pragma unroll
        for (int kk = 0; kk < 16; kk++) {
            float4 a4 = *(const float4*)&As[kk][ty * 4];
            float4 b4 = *(const float4*)&Bs[kk][tx * 4];
            acc[0][0] += a4.x * b4.x; acc[0][1] += a4.x * b4.y; acc[0][2] += a4.x * b4.z; acc[0][3] += a4.x * b4.w;
            acc[1][0] += a4.y * b4.x; acc[1][1] += a4.y * b4.y; acc[1][2] += a4.y * b4.z; acc[1][3] += a4.y * b4.w;
            acc[2][0] += a4.z * b4.x; acc[2][1] += a4.z * b4.y; acc[2][2] += a4.z * b4.z; acc[2][3] += a4.z * b4.w;
            acc[3][0] += a4.w * b4.x; acc[3][1] += a4.w * b4.y; acc[3][2] += a4.w * b4.z; acc[3][3] += a4.w * b4.w;
        }
        __syncthreads();
    }
#pragma unroll
    for (int i = 0; i < 4; i++) {
        float4 o = make_float4(acc[i][0] * alpha, acc[i][1] * alpha,
                               acc[i][2] * alpha, acc[i][3] * alpha);
        *(float4*)&C[(size_t)(mt * 64 + ty * 4 + i) * Nn + nt * 64 + tx * 4] = o;
    }
}

// ================= flash W2 on tensor cores =================
__global__ __launch_bounds__(256) void flash_w2_mma() {
    __shared__ __align__(16) __half sql[128][72];
    __shared__ __align__(16) __half sk[64][72];
    __shared__ __align__(16) __half svT[64][72];

    int tid = threadIdx.x, lane = tid & 31, w = tid >> 5;
    int chunk = blockIdx.x, mblk = blockIdx.y, bh = blockIdx.z;
    int lr = lane & 15, lh = lane >> 4;

    const __half* qlh = g_qlh + (size_t)(bh * MLM + mblk * 128) * 64;
#pragma unroll
    for (int i = 0; i < 4; i++) {
        int idx = tid + i * 256;
        int r = idx >> 3, c = (idx & 7) * 8;
        *(uint4*)&sql[r][c] = *(const uint4*)&qlh[(size_t)r * 64 + c];
    }
    __syncthreads();
    unsigned qa[4][4];
#pragma unroll
    for (int ks = 0; ks < 4; ks++)
        ldm4(qa[ks], smem_u32(&sql[w * 16 + lr][ks * 16 + lh * 8]));

    float outacc[8][4];
#pragma unroll
    for (int i = 0; i < 8; i++)
#pragma unroll
        for (int c = 0; c < 4; c++) outacc[i][c] = 0.f;
    float rsA = 0.f, rsB = 0.f;

    const __half* kb = g_kh + (size_t)bh * NSEQ * 64;
    const __half* vb = g_vh + (size_t)bh * NSEQ * 64;

    for (int it = 0; it < 32; it++) {
        int s0 = chunk * 2048 + it * 64;
        __syncthreads();
#pragma unroll
        for (int i = 0; i < 2; i++) {
            int idx = tid + i * 256;
            int r = idx >> 3, c = (idx & 7) * 8;
            *(uint4*)&sk[r][c] = *(const uint4*)&kb[(size_t)(s0 + r) * 64 + c];
            uint4 vv = *(const uint4*)&vb[(size_t)(s0 + r) * 64 + c];
            __half vh[8];
            *(uint4*)vh = vv;
#pragma unroll
            for (int j = 0; j < 8; j++) svT[c + j][r] = vh[j];
        }
        __syncthreads();
        float sf[8][4];
#pragma unroll
        for (int i = 0; i < 8; i++)
#pragma unroll
            for (int c = 0; c < 4; c++) sf[i][c] = 0.f;
#pragma unroll
        for (int ks = 0; ks < 4; ks++) {
#pragma unroll
            for (int nf4 = 0; nf4 < 4; nf4++) {
                unsigned bbf[4];
                ldm4(bbf, smem_u32(&sk[nf4 * 16 + lr][ks * 16 + lh * 8]));
                mmaf16(sf[nf4 * 2], qa[ks], bbf[0], bbf[2]);
                mmaf16(sf[nf4 * 2 + 1], qa[ks], bbf[1], bbf[3]);
            }
        }
#pragma unroll
        for (int nf = 0; nf < 8; nf++) {
            sf[nf][0] = fexp(sf[nf][0]); sf[nf][1] = fexp(sf[nf][1]);
            sf[nf][2] = fexp(sf[nf][2]); sf[nf][3] = fexp(sf[nf][3]);
            rsA += sf[nf][0] + sf[nf][1];
            rsB += sf[nf][2] + sf[nf][3];
        }
#pragma unroll
        for (int kk = 0; kk < 4; kk++) {
            unsigned pa[4];
            pa[0] = packh2(sf[2 * kk][0], sf[2 * kk][1]);
            pa[1] = packh2(sf[2 * kk][2], sf[2 * kk][3]);
            pa[2] = packh2(sf[2 * kk + 1][0], sf[2 * kk + 1][1]);
            pa[3] = packh2(sf[2 * kk + 1][2], sf[2 * kk + 1][3]);
#pragma unroll
            for (int nf4 = 0; nf4 < 4; nf4++) {
                unsigned bbf[4];
                ldm4(bbf, smem_u32(&svT[nf4 * 16 + lr][kk * 16 + lh * 8]));
                mmaf16(outacc[nf4 * 2], pa, bbf[0], bbf[2]);
                mmaf16(outacc[nf4 * 2 + 1], pa, bbf[1], bbf[3]);
            }
        }
    }
    rsA += __shfl_xor_sync(0xffffffffu, rsA, 1);
    rsA += __shfl_xor_sync(0xffffffffu, rsA, 2);
    rsB += __shfl_xor_sync(0xffffffffu, rsB, 1);
    rsB += __shfl_xor_sync(0xffffffffu, rsB, 2);

    int rA = mblk * 128 + w * 16 + (lane >> 2);
    int rB = rA + 8;
    float* wpA = g_Wpart + (size_t)((bh * 4 + chunk) * MLM + rA) * 64;
    float* wpB = g_Wpart + (size_t)((bh * 4 + chunk) * MLM + rB) * 64;
#pragma unroll
    for (int nf = 0; nf < 8; nf++) {
        int d = nf * 8 + (lane & 3) * 2;
        *(float2*)&wpA[d] = make_float2(outacc[nf][0], outacc[nf][1]);
        *(float2*)&wpB[d] = make_float2(outacc[nf][2], outacc[nf][3]);
    }
    if ((lane & 3) == 0) {
        g_Spart[(bh * 4 + chunk) * MLM + rA] = rsA;
        g_Spart[(bh * 4 + chunk) * MLM + rB] = rsB;
    }
}

__global__ void combine_w2_kernel() {
    int idx = blockIdx.x * 256 + threadIdx.x;
    int bh = idx >> 14;
    int m = (idx >> 6) & 255;
    int d = idx & 63;
    float num = 0.f, den = 0.f;
#pragma unroll
    for (int c = 0; c < 4; c++) {
        num += g_Wpart[(size_t)((bh * 4 + c) * MLM + m) * 64 + d];
        den += g_Spart[(bh * 4 + c) * MLM + m];
    }
    g_W2[(bh * MLM + m) * 64 + d] = num / den;
}

// ================= attn1 + conv on tensor cores (writes fp16 to g_A16) =================
__global__ __launch_bounds__(256) void attn1_mma(const float* __restrict__ convw) {
    extern __shared__ char smx[];
    __half (*sq)[72]  = (__half(*)[72])(smx);
    __half (*skl)[72] = (__half(*)[72])(smx + 18432);
    __half (*swT)[72] = (__half(*)[72])(smx + 27648);
    __half (*sv)[72]  = (__half(*)[72])(smx + 36864);
    float* cw = (float*)(smx + 59904);

    int tid = threadIdx.x, lane = tid & 31, w = tid >> 5;
    int ntile = blockIdx.x, bh = blockIdx.y;
    int h = bh & 7, bb2 = bh >> 3;
    int n0 = ntile * 128;
    int lr = lane & 15, lh = lane >> 4;

    if (tid < KSZ) cw[tid] = convw[h * KSZ + tid];

    const __half* qb = g_qh + ((size_t)bh * NSEQ + n0) * 64;
#pragma unroll
    for (int i = 0; i < 4; i++) {
        int idx = tid + i * 256;
        int r = idx >> 3, c = (idx & 7) * 8;
        *(uint4*)&sq[r][c] = *(const uint4*)&qb[(size_t)r * 64 + c];
    }
    const __half* vb2 = g_vh + (size_t)bh * NSEQ * 64;
#pragma unroll
    for (int i = 0; i < 5; i++) {
        int idx = tid + i * 256;
        int r = idx >> 3, c = (idx & 7) * 8;
        int gr = n0 - 16 + r;
        uint4 z = make_uint4(0u, 0u, 0u, 0u);
        if (gr >= 0 && gr < NSEQ) z = *(const uint4*)&vb2[(size_t)gr * 64 + c];
        *(uint4*)&sv[r][c] = z;
    }
    __syncthreads();

    unsigned qa[4][4];
#pragma unroll
    for (int ks = 0; ks < 4; ks++)
        ldm4(qa[ks], smem_u32(&sq[w * 16 + lr][ks * 16 + lh * 8]));

    float outacc[8][4];
#pragma unroll
    for (int i = 0; i < 8; i++)
#pragma unroll
        for (int c = 0; c < 4; c++) outacc[i][c] = 0.f;
    float rsA = 0.f, rsB = 0.f;

    const __half* klb = g_klh + (size_t)bh * MLM * 64;
    const __half* w3tb = g_W3T + (size_t)bh * 64 * 256;

    for (int lc = 0; lc < 4; lc++) {
        __syncthreads();
#pragma unroll
        for (int i = 0; i < 2; i++) {
            int idx = tid + i * 256;
            int r = idx >> 3, c = (idx & 7) * 8;
            *(uint4*)&skl[r][c] = *(const uint4*)&klb[(size_t)(lc * 64 + r) * 64 + c];
            *(uint4*)&swT[r][c] = *(const uint4*)&w3tb[(size_t)r * 256 + lc * 64 + c];
        }
        __syncthreads();
        float sf[8][4];
#pragma unroll
        for (int i = 0; i < 8; i++)
#pragma unroll
            for (int c = 0; c < 4; c++) sf[i][c] = 0.f;
#pragma unroll
        for (int ks = 0; ks < 4; ks++) {
#pragma unroll
            for (int nf4 = 0; nf4 < 4; nf4++) {
                unsigned bbf[4];
                ldm4(bbf, smem_u32(&skl[nf4 * 16 + lr][ks * 16 + lh * 8]));
                mmaf16(sf[nf4 * 2], qa[ks], bbf[0], bbf[2]);
                mmaf16(sf[nf4 * 2 + 1], qa[ks], bbf[1], bbf[3]);
            }
        }
#pragma unroll
        for (int nf = 0; nf < 8; nf++) {
            sf[nf][0] = fexp(sf[nf][0]); sf[nf][1] = fexp(sf[nf][1]);
            sf[nf][2] = fexp(sf[nf][2]); sf[nf][3] = fexp(sf[nf][3]);
            rsA += sf[nf][0] + sf[nf][1];
            rsB += sf[nf][2] + sf[nf][3];
        }
#pragma unroll
        for (int kk = 0; kk < 4; kk++) {
            unsigned pa[4];
            pa[0] = packh2(sf[2 * kk][0], sf[2 * kk][1]);
            pa[1] = packh2(sf[2 * kk][2], sf[2 * kk][3]);
            pa[2] = packh2(sf[2 * kk + 1][0], sf[2 * kk + 1][1]);
            pa[3] = packh2(sf[2 * kk + 1][2], sf[2 * kk + 1][3]);
#pragma unroll
            for (int nf4 = 0; nf4 < 4; nf4++) {
                unsigned bbf[4];
                ldm4(bbf, smem_u32(&swT[nf4 * 16 + lr][kk * 16 + lh * 8]));
                mmaf16(outacc[nf4 * 2], pa, bbf[0], bbf[2]);
                mmaf16(outacc[nf4 * 2 + 1], pa, bbf[1], bbf[3]);
            }
        }
    }
    rsA += __shfl_xor_sync(0xffffffffu, rsA, 1);
    rsA += __shfl_xor_sync(0xffffffffu, rsA, 2);
    rsB += __shfl_xor_sync(0xffffffffu, rsB, 1);
    rsB += __shfl_xor_sync(0xffffffffu, rsB, 2);
    float invA = 1.f / rsA, invB = 1.f / rsB;

    int lrA = w * 16 + (lane >> 2);
#pragma unroll
    for (int nf = 0; nf < 8; nf++) {
        int d = nf * 8 + (lane & 3) * 2;
        float a0 = 0.f, a1 = 0.f, b0 = 0.f, b1 = 0.f;
#pragma unroll
        for (int t = 0; t < KSZ; t++) {
            float wv = cw[t];
            float2 fA = __half22float2(*(__half2*)&sv[lrA + t][d]);
            float2 fB = __half22float2(*(__half2*)&sv[lrA + 8 + t][d]);
            a0 = fmaf(wv, fA.x, a0); a1 = fmaf(wv, fA.y, a1);
            b0 = fmaf(wv, fB.x, b0); b1 = fmaf(wv, fB.y, b1);
        }
        outacc[nf][0] = outacc[nf][0] * invA + a0;
        outacc[nf][1] = outacc[nf][1] * invA + a1;
        outacc[nf][2] = outacc[nf][2] * invB + b0;
        outacc[nf][3] = outacc[nf][3] * invB + b1;
    }

    int nA = n0 + lrA, nB = nA + 8;
    __half* oA = g_A16 + (size_t)(bb2 * NSEQ + nA) * 512 + h * 64;
    __half* oB = g_A16 + (size_t)(bb2 * NSEQ + nB) * 512 + h * 64;
#pragma unroll
    for (int nf = 0; nf < 8; nf++) {
        int d = nf * 8 + (lane & 3) * 2;
        *(__half2*)&oA[d] = __floats2half2_rn(outacc[nf][0], outacc[nf][1]);
        *(__half2*)&oB[d] = __floats2half2_rn(outacc[nf][2], outacc[nf][3]);
    }
}

// ================= host launcher =================
extern "C" void kernel_launch(void* const* d_in, const int* in_sizes, int n_in,
                              void* d_out, int out_size) {
    const float* x     = (const float*)d_in[0];
    const float* ln_g  = (const float*)d_in[1];
    const float* ln_b  = (const float*)d_in[2];
    const float* W_qkv = (const float*)d_in[3];
    const float* W_out = (const float*)d_in[4];
    const float* b_out = (const float*)d_in[5];
    const float* convw = (const float*)d_in[6];
    float* out = (float*)d_out;

    cudaFuncSetAttribute(attn1_mma, cudaFuncAttributeMaxDynamicSharedMemorySize, 60416);
    cudaFuncSetAttribute(gemm_lm_kernel, cudaFuncAttributeMaxDynamicSharedMemorySize, 81920);
    cudaFuncSetAttribute(gemm16_kernel, cudaFuncAttributeMaxDynamicSharedMemorySize, 73728);

    __nv_bfloat16 *bqh, *bql;
    cudaGetSymbolAddress((void**)&bqh, g_Bqh);
    cudaGetSymbolAddress((void**)&bql, g_Bql);
    __half *b16q, *b16o;
    cudaGetSymbolAddress((void**)&b16q, g_B16q);
    cudaGetSymbolAddress((void**)&b16o, g_B16o);
    float *xnlmp;
    cudaGetSymbolAddress((void**)&xnlmp, g_xnlm);

    reset_kernel<<<1, 1>>>();
    ln_kernel<<<Bb * NSEQ, 128>>>(x, ln_g, ln_b);  // writes g_xn (fp32) + g_A16 (fp16)

    convW16_kernel<<<dim3(48, 16), 1024>>>(W_qkv, 1536, b16q);
    convW16_kernel<<<dim3(16, 16), 1024>>>(W_out, 512, b16o);

    // qkv GEMM: single-pass fp16
    gemm16_kernel<<<dim3(12, 128), 256, 73728>>>(b16q, 0, nullptr, nullptr);

    // landmark path: accurate small GEMM
    xnlm_kernel<<<1024, 256>>>();
    convA_kernel<<<256, 256>>>(xnlmp);
    convW_kernel<<<dim3(48, 16), 1024>>>(W_qkv, 1536, bqh, bql);
    gemm_lm_kernel<<<dim3(8, 4), 256, 81920>>>(bqh, bql);

    attn2_kernel<<<16, 256>>>();
    colmax_kernel<<<16, 256>>>();
    z0_kernel<<<4096, 256>>>();

    int zc = 4, zn = 5;  // Za, Zb
    for (int it = 0; it < 6; it++) {
        int np = (it == 5) ? 3 : 1;
        gemm_pinv_mma<<<dim3(4, 4, 16), 128>>>(1, 0, zc, 0.f, 1.f, 1.f, np);
        gemm_pinv_mma<<<dim3(4, 4, 16), 128>>>(2, 1, 1, 7.f, -1.f, 1.f, np);
        gemm_pinv_mma<<<dim3(4, 4, 16), 128>>>(3, 1, 2, 15.f, -1.f, 1.f, np);
        gemm_pinv_mma<<<dim3(4, 4, 16), 128>>>(zn, zc, 3, 13.f, -1.f, 0.25f, np);
        int t = zc; zc = zn; zn = t;
    }

    flash_w2_mma<<<dim3(4, 2, 16), 256>>>();
    combine_w2_kernel<<<1024, 256>>>();
    gemm_bh_kernel<<<dim3(1, 4, 16), 256>>>(7, zc, 6, 64, 0.f, 1.f, 1.f);  // W3 = Z @ W2
    w3t_kernel<<<1024, 256>>>();
    attn1_mma<<<dim3(64, 16), 256, 60416>>>(convw);  // writes fp16 into g_A16

    // out GEMM: single-pass fp16
    gemm16_kernel<<<dim3(4, 128), 256, 73728>>>(b16o, 1, b_out, out);
}

// round 11
// speedup vs baseline: 1.1517x; 1.1517x over previous
#include <cuda_runtime.h>
#include <cuda_bf16.h>
#include <cuda_fp16.h>

#define Bb    2
#define NSEQ  8192
#define DIMV  512
#define NH    8
#define BHn   16
#define DHd   64
#define MLM   256
#define LGRP  32
#define KSZ   33
#define PADc  16
#define SCALE 0.125f

// ================= static device scratch =================
__device__ float g_xn[(size_t)Bb * NSEQ * DIMV];
__device__ float g_xnlm[512 * 512];
__device__ float g_ql[BHn * MLM * DHd];
__device__ float g_kl[BHn * MLM * DHd];
__device__ float g_attn2[BHn * MLM * MLM];
__device__ float g_Y[BHn * MLM * MLM];
__device__ float g_P[BHn * MLM * MLM];
__device__ float g_Qm[BHn * MLM * MLM];
__device__ float g_Za[BHn * MLM * MLM];
__device__ float g_Zb[BHn * MLM * MLM];
__device__ float g_W2[BHn * MLM * DHd];
__device__ float g_W3[BHn * MLM * DHd];
__device__ float g_Wpart[(size_t)BHn * 4 * MLM * DHd];
__device__ float g_Spart[BHn * 4 * MLM];
__device__ int   g_maxc_bits;

// bf16 hi/lo buffers (landmark GEMM)
__device__ __nv_bfloat16 g_Ahi[512 * 512];
__device__ __nv_bfloat16 g_Alo[512 * 512];
__device__ __nv_bfloat16 g_Bqh[1536 * 512];
__device__ __nv_bfloat16 g_Bql[1536 * 512];

// fp16 buffers
__device__ __half g_A16[(size_t)Bb * NSEQ * DIMV];
__device__ __half g_B16q[1536 * 512];
__device__ __half g_B16o[512 * 512];
__device__ __half g_qh[(size_t)BHn * NSEQ * DHd];
__device__ __half g_kh[(size_t)BHn * NSEQ * DHd];
__device__ __half g_vh[(size_t)BHn * NSEQ * DHd];
__device__ __half g_qlh[BHn * MLM * DHd];
__device__ __half g_klh[BHn * MLM * DHd];
__device__ __half g_W3T[BHn * DHd * MLM];

__global__ void reset_kernel() { g_maxc_bits = 0; }

// ================= mma.sync helpers =================
__device__ __forceinline__ unsigned smem_u32(const void* p) {
    unsigned a;
    asm("{ .reg .u64 t; cvta.to.shared.u64 t, %1; cvt.u32.u64 %0, t; }" : "=r"(a) : "l"(p));
    return a;
}
__device__ __forceinline__ void ldm4(unsigned* r, unsigned addr) {
    asm volatile("ldmatrix.sync.aligned.m8n8.x4.shared.b16 {%0,%1,%2,%3}, [%4];"
        : "=r"(r[0]), "=r"(r[1]), "=r"(r[2]), "=r"(r[3]) : "r"(addr));
}
__device__ __forceinline__ void mma16816(float* c, const unsigned* a, unsigned b0, unsigned b1) {
    asm volatile("mma.sync.aligned.m16n8k16.row.col.f32.bf16.bf16.f32 "
        "{%0,%1,%2,%3}, {%4,%5,%6,%7}, {%8,%9}, {%0,%1,%2,%3};"
        : "+f"(c[0]), "+f"(c[1]), "+f"(c[2]), "+f"(c[3])
        : "r"(a[0]), "r"(a[1]), "r"(a[2]), "r"(a[3]), "r"(b0), "r"(b1));
}
__device__ __forceinline__ void mmaf16(float* c, const unsigned* a, unsigned b0, unsigned b1) {
    asm volatile("mma.sync.aligned.m16n8k16.row.col.f32.f16.f16.f32 "
        "{%0,%1,%2,%3}, {%4,%5,%6,%7}, {%8,%9}, {%0,%1,%2,%3};"
        : "+f"(c[0]), "+f"(c[1]), "+f"(c[2]), "+f"(c[3])
        : "r"(a[0]), "r"(a[1]), "r"(a[2]), "r"(a[3]), "r"(b0), "r"(b1));
}
__device__ __forceinline__ void cpasync16(unsigned dst, const void* src) {
    asm volatile("cp.async.cg.shared.global [%0], [%1], 16;" :: "r"(dst), "l"(src));
}
#define CP_COMMIT() asm volatile("cp.async.commit_group;" ::: "memory")
__device__ __forceinline__ unsigned packh2(float a, float b) {
    __half2 h = __floats2half2_rn(a, b);
    return *(unsigned*)&h;
}
__device__ __forceinline__ float fexp(float x) {
    float t = x * 1.44269504f;
    float r = rintf(t);
    float f = t - r;
    float p = 1.33336e-3f;
    p = fmaf(p, f, 9.61813e-3f);
    p = fmaf(p, f, 5.55041e-2f);
    p = fmaf(p, f, 2.40226507e-1f);
    p = fmaf(p, f, 6.93147181e-1f);
    p = fmaf(p, f, 1.0f);
    int e = (int)r;
    return p * __int_as_float((e + 127) << 23);
}

// ================= layernorm (writes fp32 + fp16) =================
__global__ __launch_bounds__(128) void ln_kernel(const float* __restrict__ x,
                                                 const float* __restrict__ gam,
                                                 const float* __restrict__ bet) {
    int row = blockIdx.x;
    int tid = threadIdx.x;
    float4 v = ((const float4*)x)[(size_t)row * 128 + tid];
    float s1 = v.x + v.y + v.z + v.w;
    float s2 = v.x * v.x + v.y * v.y + v.z * v.z + v.w * v.w;
#pragma unroll
    for (int o = 16; o; o >>= 1) {
        s1 += __shfl_xor_sync(0xffffffffu, s1, o);
        s2 += __shfl_xor_sync(0xffffffffu, s2, o);
    }
    __shared__ float r1[4], r2[4];
    int w = tid >> 5;
    if ((tid & 31) == 0) { r1[w] = s1; r2[w] = s2; }
    __syncthreads();
    s1 = r1[0] + r1[1] + r1[2] + r1[3];
    s2 = r2[0] + r2[1] + r2[2] + r2[3];
    float mean = s1 * (1.f / 512.f);
    float var  = s2 * (1.f / 512.f) - mean * mean;
    float rstd = rsqrtf(var + 1e-5f);
    float4 g4 = ((const float4*)gam)[tid];
    float4 b4 = ((const float4*)bet)[tid];
    float4 o;
    o.x = (v.x - mean) * rstd * g4.x + b4.x;
    o.y = (v.y - mean) * rstd * g4.y + b4.y;
    o.z = (v.z - mean) * rstd * g4.z + b4.z;
    o.w = (v.w - mean) * rstd * g4.w + b4.w;
    ((float4*)g_xn)[(size_t)row * 128 + tid] = o;
    __half2* ph = (__half2*)(g_A16 + (size_t)row * 512 + tid * 4);
    ph[0] = __floats2half2_rn(o.x, o.y);
    ph[1] = __floats2half2_rn(o.z, o.w);
}

// ================= group means of xn (landmark pre-image) =================
__global__ void xnlm_kernel() {
    int idx = blockIdx.x * 256 + threadIdx.x;
    int row = idx >> 9;
    int d = idx & 511;
    int b = row >> 8, m = row & 255;
    const float* p = g_xn + ((size_t)(b * NSEQ) + m * LGRP) * DIMV + d;
    float s = 0.f;
#pragma unroll
    for (int i = 0; i < LGRP; i++) s += p[(size_t)i * DIMV];
    g_xnlm[idx] = s * (1.f / LGRP);
}

// ================= converters =================
__global__ __launch_bounds__(256) void convA_kernel(const float* __restrict__ src) {
    size_t i4 = ((size_t)blockIdx.x * 256 + threadIdx.x) * 4;
    float4 v = *(const float4*)(src + i4);
    __nv_bfloat16 h0 = __float2bfloat16(v.x), h1 = __float2bfloat16(v.y);
    __nv_bfloat16 h2 = __float2bfloat16(v.z), h3 = __float2bfloat16(v.w);
    __nv_bfloat16 l0 = __float2bfloat16(v.x - __bfloat162float(h0));
    __nv_bfloat16 l1 = __float2bfloat16(v.y - __bfloat162float(h1));
    __nv_bfloat16 l2 = __float2bfloat16(v.z - __bfloat162float(h2));
    __nv_bfloat16 l3 = __float2bfloat16(v.w - __bfloat162float(h3));
    __nv_bfloat162* ph = (__nv_bfloat162*)(g_Ahi + i4);
    __nv_bfloat162* pl = (__nv_bfloat162*)(g_Alo + i4);
    ph[0] = __nv_bfloat162(h0, h1); ph[1] = __nv_bfloat162(h2, h3);
    pl[0] = __nv_bfloat162(l0, l1); pl[1] = __nv_bfloat162(l2, l3);
}

__global__ __launch_bounds__(1024) void convW_kernel(const float* __restrict__ W, int N,
                                                     __nv_bfloat16* __restrict__ BThi,
                                                     __nv_bfloat16* __restrict__ BTlo) {
    __shared__ float sh[32][33];
    int n0 = blockIdx.x * 32, k0 = blockIdx.y * 32;
    int tx = threadIdx.x & 31, ty = threadIdx.x >> 5;
    sh[ty][tx] = W[(size_t)(k0 + ty) * N + n0 + tx];
    __syncthreads();
    float x = sh[tx][ty];
    __nv_bfloat16 h = __float2bfloat16(x);
    __nv_bfloat16 l = __float2bfloat16(x - __bfloat162float(h));
    BThi[(size_t)(n0 + ty) * 512 + k0 + tx] = h;
    BTlo[(size_t)(n0 + ty) * 512 + k0 + tx] = l;
}

__global__ __launch_bounds__(1024) void convW16_kernel(const float* __restrict__ W, int N,
                                                       __half* __restrict__ BT) {
    __shared__ float sh[32][33];
    int n0 = blockIdx.x * 32, k0 = blockIdx.y * 32;
    int tx = threadIdx.x & 31, ty = threadIdx.x >> 5;
    sh[ty][tx] = W[(size_t)(k0 + ty) * N + n0 + tx];
    __syncthreads();
    BT[(size_t)(n0 + ty) * 512 + k0 + tx] = __float2half(sh[tx][ty]);
}

// W3 -> W3T fp16 [bh][d][m]
__global__ void w3t_kernel() {
    int idx = blockIdx.x * 256 + threadIdx.x;
    int bh = idx >> 14;
    int m = (idx >> 6) & 255;
    int d = idx & 63;
    float v = g_W3[(bh * 256 + m) * 64 + d];
    g_W3T[((size_t)bh * 64 + d) * 256 + m] = __float2half(v);
}

// ================= fp16 single-pass dense GEMM (cp.async double-buffered) =================
__global__ __launch_bounds__(256) void gemm16_kernel(
    const __half* __restrict__ gBbase, int mode,
    const float* __restrict__ bout, float* __restrict__ outp) {
    extern __shared__ char smdyn[];
    unsigned sbase = smem_u32(smdyn);
    int tid = threadIdx.x, lane = tid & 31, wid = tid >> 5;
    int wm = wid & 3, wn = wid >> 2;
    int mBase = blockIdx.y * 128, nBase = blockIdx.x * 128;
    int lr = lane & 15, lh = lane >> 4;

    const __half* gA = g_A16 + (size_t)mBase * 512;
    const __half* gB = gBbase + (size_t)nBase * 512;

    float acc[2][8][4];
#pragma unroll
    for (int i = 0; i < 2; i++)
#pragma unroll
        for (int j = 0; j < 8; j++)
#pragma unroll
            for (int c = 0; c < 4; c++) acc[i][j][c] = 0.f;

    int r_ld = tid >> 1;
    int q2 = (tid & 1) * 4;

    auto load_stage = [&](int ch, unsigned st) {
#pragma unroll
        for (int u = 0; u < 4; u++) {
            unsigned soff = (unsigned)r_ld * 144u + (q2 + u) * 16u;
            size_t goff = (size_t)r_ld * 512 + ch * 64 + (q2 + u) * 8;
            cpasync16(sbase + st + soff, gA + goff);
            cpasync16(sbase + st + 18432u + soff, gB + goff);
        }
        CP_COMMIT();
    };

    load_stage(0, 0u);

    for (int ch = 0; ch < 8; ch++) {
        unsigned st = (unsigned)(ch & 1) * 36864u;
        if (ch + 1 < 8) {
            load_stage(ch + 1, (unsigned)((ch + 1) & 1) * 36864u);
            asm volatile("cp.async.wait_group 1;" ::: "memory");
        } else {
            asm volatile("cp.async.wait_group 0;" ::: "memory");
        }
        __syncthreads();

        unsigned aA = sbase + st;
        unsigned aB = aA + 18432u;
#pragma unroll
        for (int ks = 0; ks < 4; ks++) {
            unsigned kc2 = (unsigned)(ks * 16 + lh * 8) * 2u;
            unsigned ah[2][4];
#pragma unroll
            for (int mi = 0; mi < 2; mi++) {
                unsigned rowA = (unsigned)(wm * 32 + mi * 16 + lr) * 144u;
                ldm4(ah[mi], aA + rowA + kc2);
            }
#pragma unroll
            for (int nt = 0; nt < 4; nt++) {
                unsigned rowB = (unsigned)(wn * 64 + nt * 16 + lr) * 144u;
                unsigned bf[4];
                ldm4(bf, aB + rowB + kc2);
#pragma unroll
                for (int mi = 0; mi < 2; mi++) {
#pragma unroll
                    for (int ns = 0; ns < 2; ns++)
                        mmaf16(acc[mi][nt * 2 + ns], ah[mi], bf[ns], bf[ns + 2]);
                }
            }
        }
        __syncthreads();
    }

    int r0 = mBase + wm * 32 + (lane >> 2);
    if (mode == 0) {
        int sec = nBase >> 9;
        float sc = (sec == 0) ? SCALE : 1.f;
        __half* hdst = (sec == 0) ? g_qh : ((sec == 1) ? g_kh : g_vh);
        int h = ((nBase + wn * 64) >> 6) & 7;
#pragma unroll
        for (int mi = 0; mi < 2; mi++) {
#pragma unroll
            for (int jn = 0; jn < 8; jn++) {
                int d = jn * 8 + (lane & 3) * 2;
#pragma unroll
                for (int half = 0; half < 2; half++) {
                    int gr = r0 + mi * 16 + half * 8;
                    int bb = gr >> 13, n = gr & 8191;
                    size_t off = ((size_t)(bb * 8 + h) * NSEQ + n) * 64 + d;
                    *(__half2*)&hdst[off] = __floats2half2_rn(acc[mi][jn][half * 2] * sc,
                                                              acc[mi][jn][half * 2 + 1] * sc);
                }
            }
        }
    } else {
#pragma unroll
        for (int mi = 0; mi < 2; mi++) {
#pragma unroll
            for (int jn = 0; jn < 8; jn++) {
                int gc = nBase + wn * 64 + jn * 8 + (lane & 3) * 2;
#pragma unroll
                for (int half = 0; half < 2; half++) {
                    int gr = r0 + mi * 16 + half * 8;
                    float2 bo = *(const float2*)&bout[gc];
                    float2 xv = *(const float2*)&g_xn[(size_t)gr * 512 + gc];
                    float2 o = make_float2(acc[mi][jn][half * 2] + bo.x + xv.x,
                                           acc[mi][jn][half * 2 + 1] + bo.y + xv.y);
                    *(float2*)&outp[(size_t)gr * 512 + gc] = o;
                }
            }
        }
    }
}

// ================= bf16 split landmark GEMM (M=512, N=1024) =================
__global__ __launch_bounds__(256) void gemm_lm_kernel(
    const __nv_bfloat16* __restrict__ BThi, const __nv_bfloat16* __restrict__ BTlo) {
    extern __shared__ char smdyn[];
    unsigned sbase = smem_u32(smdyn);
    int tid = threadIdx.x, lane = tid & 31, wid = tid >> 5;
    int wm = wid & 3, wn = wid >> 2;
    int mBase = blockIdx.y * 128, nBase = blockIdx.x * 128;
    int lr = lane & 15, lh = lane >> 4;

    const __nv_bfloat16* gsrc[4];
    gsrc[0] = g_Ahi + (size_t)mBase * 512;
    gsrc[1] = g_Alo + (size_t)mBase * 512;
    gsrc[2] = BThi + (size_t)nBase * 512;
    gsrc[3] = BTlo + (size_t)nBase * 512;

    float acc[2][8][4];
#pragma unroll
    for (int i = 0; i < 2; i++)
#pragma unroll
        for (int j = 0; j < 8; j++)
#pragma unroll
            for (int c = 0; c < 4; c++) acc[i][j][c] = 0.f;

    int r_ld0 = tid >> 2, q_ld = tid & 3;
    unsigned so0 = (unsigned)r_ld0 * 80u + q_ld * 16u;
    unsigned so1 = (unsigned)(r_ld0 + 64) * 80u + q_ld * 16u;

    {
        size_t go0 = (size_t)r_ld0 * 512 + q_ld * 8;
        size_t go1 = (size_t)(r_ld0 + 64) * 512 + q_ld * 8;
#pragma unroll
        for (int a = 0; a < 4; a++) {
            cpasync16(sbase + a * 10240u + so0, gsrc[a] + go0);
            cpasync16(sbase + a * 10240u + so1, gsrc[a] + go1);
        }
        CP_COMMIT();
    }

    for (int ch = 0; ch < 16; ch++) {
        unsigned st = (unsigned)(ch & 1) * 40960u;
        if (ch + 1 < 16) {
            unsigned stn = (unsigned)((ch + 1) & 1) * 40960u;
            size_t go0 = (size_t)r_ld0 * 512 + (ch + 1) * 32 + q_ld * 8;
            size_t go1 = (size_t)(r_ld0 + 64) * 512 + (ch + 1) * 32 + q_ld * 8;
#pragma unroll
            for (int a = 0; a < 4; a++) {
                cpasync16(sbase + stn + a * 10240u + so0, gsrc[a] + go0);
                cpasync16(sbase + stn + a * 10240u + so1, gsrc[a] + go1);
            }
            CP_COMMIT();
            asm volatile("cp.async.wait_group 1;" ::: "memory");
        } else {
            asm volatile("cp.async.wait_group 0;" ::: "memory");
        }
        __syncthreads();

        unsigned aAh = sbase + st;
        unsigned aAl = aAh + 10240u;
        unsigned aBh = aAh + 20480u;
        unsigned aBl = aAh + 30720u;
#pragma unroll
        for (int ks = 0; ks < 2; ks++) {
            unsigned kc2 = (unsigned)(ks * 16 + lh * 8) * 2u;
            unsigned ah[2][4], al[2][4];
#pragma unroll
            for (int mi = 0; mi < 2; mi++) {
                unsigned rowA = (unsigned)(wm * 32 + mi * 16 + lr) * 80u;
                ldm4(ah[mi], aAh + rowA + kc2);
                ldm4(al[mi], aAl + rowA + kc2);
            }
#pragma unroll
            for (int nt = 0; nt < 4; nt++) {
                unsigned rowB = (unsigned)(wn * 64 + nt * 16 + lr) * 80u;
                unsigned bh[4], bl[4];
                ldm4(bh, aBh + rowB + kc2);
                ldm4(bl, aBl + rowB + kc2);
#pragma unroll
                for (int mi = 0; mi < 2; mi++) {
#pragma unroll
                    for (int ns = 0; ns < 2; ns++) {
                        float* cc = acc[mi][nt * 2 + ns];
                        mma16816(cc, ah[mi], bh[ns], bh[ns + 2]);
                        mma16816(cc, ah[mi], bl[ns], bl[ns + 2]);
                        mma16816(cc, al[mi], bh[ns], bh[ns + 2]);
                    }
                }
            }
        }
        __syncthreads();
    }

    int r0 = mBase + wm * 32 + (lane >> 2);
    int sec = nBase >> 9;
    float sc = (sec == 0) ? SCALE : 1.f;
    float* dst = (sec == 0) ? g_ql : g_kl;
    __half* hdst = (sec == 0) ? g_qlh : g_klh;
    int h = ((nBase + wn * 64) >> 6) & 7;
#pragma unroll
    for (int mi = 0; mi < 2; mi++) {
#pragma unroll
        for (int jn = 0; jn < 8; jn++) {
            int d = jn * 8 + (lane & 3) * 2;
#pragma unroll
            for (int half = 0; half < 2; half++) {
                int gr = r0 + mi * 16 + half * 8;
                int bb = gr >> 8, m = gr & 255;
                float2 o = make_float2(acc[mi][jn][half * 2] * sc,
                                       acc[mi][jn][half * 2 + 1] * sc);
                size_t off = ((size_t)(bb * 8 + h) * MLM + m) * 64 + d;
                *(float2*)&dst[off] = o;
                *(__half2*)&hdst[off] = __floats2half2_rn(o.x, o.y);
            }
        }
    }
}

// ================= attn2 = softmax(q_l k_l^T) =================
__global__ __launch_bounds__(256) void attn2_kernel() {
    int bh = blockIdx.x;
    int m = threadIdx.x;
    __shared__ float4 kls[1024];
    float4 q[16];
    const float4* qp = (const float4*)g_ql + (size_t)(bh * MLM + m) * 16;
#pragma unroll
    for (int i = 0; i < 16; i++) q[i] = qp[i];
    float sum = 0.f;
    float* arow = g_attn2 + (size_t)bh * 65536 + (size_t)m * 256;
    for (int tile = 0; tile < 4; tile++) {
        __syncthreads();
        const float4* src = (const float4*)g_kl + (size_t)(bh * MLM + tile * 64) * 16;
#pragma unroll
        for (int i = 0; i < 4; i++) kls[threadIdx.x + i * 256] = src[threadIdx.x + i * 256];
        __syncthreads();
        for (int j = 0; j < 64; j++) {
            const float4* kr = &kls[j * 16];
            float s = 0.f;
#pragma unroll
            for (int d = 0; d < 16; d++) {
                float4 a = q[d], b = kr[d];
                s += a.x * b.x + a.y * b.y + a.z * b.z + a.w * b.w;
            }
            float p = __expf(s);
            sum += p;
            arow[tile * 64 + j] = p;
        }
    }
    float inv = 1.f / sum;
    for (int j = 0; j < 256; j++) arow[j] *= inv;
}

// ================= max column-sum of attn2 =================
__global__ __launch_bounds__(256) void colmax_kernel() {
    int bh = blockIdx.x;
    int j = threadIdx.x;
    const float* a = g_attn2 + (size_t)bh * 65536;
    float s = 0.f;
    for (int m2 = 0; m2 < 256; m2++) s += a[m2 * 256 + j];
    __shared__ float red[256];
    red[j] = s;
    __syncthreads();
    for (int o = 128; o; o >>= 1) {
        if (j < o) red[j] = fmaxf(red[j], red[j + o]);
        __syncthreads();
    }
    if (j == 0) atomicMax(&g_maxc_bits, __float_as_int(red[0]));
}

__global__ void z0_kernel() {
    int idx = blockIdx.x * 256 + threadIdx.x;
    int bh = idx >> 16;
    int i = (idx >> 8) & 255;
    int j = idx & 255;
    float scale = 1.f / __int_as_float(g_maxc_bits);
    g_Za[idx] = g_attn2[(bh << 16) + (j << 8) + i] * scale;
}

// ================= buffer selector =================
__device__ __forceinline__ float* pickBuf(int id) {
    switch (id) {
        case 0: return g_attn2;
        case 1: return g_Y;
        case 2: return g_P;
        case 3: return g_Qm;
        case 4: return g_Za;
        case 5: return g_Zb;
        case 6: return g_W2;
        default: return g_W3;
    }
}

// ================= pinv batched GEMM (R9 version: 128x64 tiles, 256 thr, 1/3 pass) ===========
__global__ __launch_bounds__(256) void gemm_pinv_mma(int cId, int aId, int bId,
                                                     float beta, float sgn, float alpha,
                                                     int passes) {
    __shared__ __align__(16) __nv_bfloat16 sAh[128][40];
    __shared__ __align__(16) __nv_bfloat16 sAl[128][40];
    __shared__ __align__(16) __nv_bfloat16 sBh[64][40];
    __shared__ __align__(16) __nv_bfloat16 sBl[64][40];

    int bh = blockIdx.z;
    int mBase = blockIdx.y * 128, nBase = blockIdx.x * 64;
    const float* A = pickBuf(aId) + (size_t)bh * 65536;
    const float* B = pickBuf(bId) + (size_t)bh * 65536;
    float*       C = pickBuf(cId) + (size_t)bh * 65536;

    int tid = threadIdx.x, lane = tid & 31, w = tid >> 5;
    int wm = w & 3, wn = w >> 2;
    int lr = lane & 15, lh = lane >> 4;
    bool full = (passes == 3);

    float acc[2][4][4];
#pragma unroll
    for (int i = 0; i < 2; i++)
#pragma unroll
        for (int j = 0; j < 4; j++)
#pragma unroll
            for (int c = 0; c < 4; c++) acc[i][j][c] = 0.f;

    for (int ch = 0; ch < 8; ch++) {
        if (ch) __syncthreads();
#pragma unroll
        for (int i = 0; i < 4; i++) {
            int idx = tid + i * 256;
            int r = idx >> 3, c4 = (idx & 7) * 4;
            float4 v = *(const float4*)&A[(size_t)(mBase + r) * 256 + ch * 32 + c4];
            __nv_bfloat16 h0 = __float2bfloat16(v.x), h1 = __float2bfloat16(v.y);
            __nv_bfloat16 h2 = __float2bfloat16(v.z), h3 = __float2bfloat16(v.w);
            sAh[r][c4 + 0] = h0; sAh[r][c4 + 1] = h1;
            sAh[r][c4 + 2] = h2; sAh[r][c4 + 3] = h3;
            if (full) {
                sAl[r][c4 + 0] = __float2bfloat16(v.x - __bfloat162float(h0));
                sAl[r][c4 + 1] = __float2bfloat16(v.y - __bfloat162float(h1));
                sAl[r][c4 + 2] = __float2bfloat16(v.z - __bfloat162float(h2));
                sAl[r][c4 + 3] = __float2bfloat16(v.w - __bfloat162float(h3));
            }
        }
#pragma unroll
        for (int kl = 0; kl < 4; kl++) {
            int gk = ch * 32 + w * 4 + kl;
#pragma unroll
            for (int nh = 0; nh < 2; nh++) {
                int n = nh * 32 + lane;
                float v = B[(size_t)gk * 256 + nBase + n];
                v = sgn * v + ((gk == nBase + n) ? beta : 0.f);
                __nv_bfloat16 h = __float2bfloat16(v);
                sBh[n][w * 4 + kl] = h;
                if (full) sBl[n][w * 4 + kl] = __float2bfloat16(v - __bfloat162float(h));
            }
        }
        __syncthreads();
#pragma unroll
        for (int ks = 0; ks < 2; ks++) {
            int kc = ks * 16 + lh * 8;
            unsigned ah[2][4], al[2][4];
#pragma unroll
            for (int mi = 0; mi < 2; mi++) {
                int rowA = wm * 32 + mi * 16 + lr;
                ldm4(ah[mi], smem_u32(&sAh[rowA][kc]));
                if (full) ldm4(al[mi], smem_u32(&sAl[rowA][kc]));
            }
#pragma unroll
            for (int nt = 0; nt < 2; nt++) {
                int rowB = wn * 32 + nt * 16 + lr;
                unsigned bhf[4], blf[4];
                ldm4(bhf, smem_u32(&sBh[rowB][kc]));
                if (full) ldm4(blf, smem_u32(&sBl[rowB][kc]));
#pragma unroll
                for (int mi = 0; mi < 2; mi++) {
#pragma unroll
                    for (int ns = 0; ns < 2; ns++) {
                        float* cc = acc[mi][nt * 2 + ns];
                        mma16816(cc, ah[mi], bhf[ns], bhf[ns + 2]);
                        if (full) {
                            mma16816(cc, ah[mi], blf[ns], blf[ns + 2]);
                            mma16816(cc, al[mi], bhf[ns], bhf[ns + 2]);
                        }
                    }
                }
            }
        }
    }
#pragma unroll
    for (int mi = 0; mi < 2; mi++) {
#pragma unroll
        for (int jn = 0; jn < 4; jn++) {
            int gc = nBase + wn * 32 + jn * 8 + (lane & 3) * 2;
#pragma unroll
            for (int half = 0; half < 2; half++) {
                int gr = mBase + wm * 32 + mi * 16 + (lane >> 2) + half * 8;
                float2 o = make_float2(acc[mi][jn][half * 2] * alpha,
                                       acc[mi][jn][half * 2 + 1] * alpha);
                *(float2*)&C[(size_t)gr * 256 + gc] = o;
            }
        }
    }
}

// ================= batched per-bh GEMM (scalar, kept for W3) =================
__global__ __launch_bounds__(256) void gemm_bh_kernel(int cId, int aId, int bId, int Nn,
                                                      float beta, float sgn, float alpha) {
    int bh = blockIdx.z, mt = blockIdx.y, nt = blockIdx.x;
    const float* A  = pickBuf(aId) + (size_t)bh * 65536;
    const float* Bp = pickBuf(bId) + (size_t)bh * 256 * Nn;
    float*       C  = pickBuf(cId) + (size_t)bh * 256 * Nn;
    __shared__ float As[16][64];
    __shared__ float Bs[16][64];
    int tid = threadIdx.x;
    int ar = tid >> 2, ac = (tid & 3) * 4;
    int br = tid >> 4, bc = (tid & 15) * 4;
    int ty = tid >> 4, tx = tid & 15;
    float acc[4][4];
#pragma unroll
    for (int i = 0; i < 4; i++)
#pragma unroll
        for (int j = 0; j < 4; j++) acc[i][j] = 0.f;

    for (int k0 = 0; k0 < 256; k0 += 16) {
        float4 av = *(const float4*)&A[(size_t)(mt * 64 + ar) * 256 + k0 + ac];
        As[ac + 0][ar] = av.x; As[ac + 1][ar] = av.y;
        As[ac + 2][ar] = av.z; As[ac + 3][ar] = av.w;
        int gk = k0 + br;
        int gc = nt * 64 + bc;
        float4 bv = *(const float4*)&Bp[(size_t)gk * Nn + gc];
        bv.x = sgn * bv.x + (gk == gc + 0 ? beta : 0.f);
        bv.y = sgn * bv.y + (gk == gc + 1 ? beta : 0.f);
        bv.z = sgn * bv.z + (gk == gc + 2 ? beta : 0.f);
        bv.w = sgn * bv.w + (gk == gc + 3 ? beta : 0.f);
        *(float4*)&Bs[br][bc] = bv;
        __syncthreads();
#pragma unroll
        for (int kk = 0; kk < 16; kk++) {
            float4 a4 = *(const float4*)&As[kk][ty * 4];
            float4 b4 = *(const float4*)&Bs[kk][tx * 4];
            acc[0][0] += a4.x * b4.x; acc[0][1] += a4.x * b4.y; acc[0][2] += a4.x * b4.z; acc[0][3] += a4.x * b4.w;
            acc[1][0] += a4.y * b4.x; acc[1][1] += a4.y * b4.y; acc[1][2] += a4.y * b4.z; acc[1][3] += a4.y * b4.w;
            acc[2][0] += a4.z * b4.x; acc[2][1] += a4.z * b4.y; acc[2][2] += a4.z * b4.z; acc[2][3] += a4.z * b4.w;
            acc[3][0] += a4.w * b4.x; acc[3][1] += a4.w * b4.y; acc[3][2] += a4.w * b4.z; acc[3][3] += a4.w * b4.w;
        }
        __syncthreads();
    }
#pragma unroll
    for (int i = 0; i < 4; i++) {
        float4 o = make_float4(acc[i][0] * alpha, acc[i][1] * alpha,
                               acc[i][2] * alpha, acc[i][3] * alpha);
        *(float4*)&C[(size_t)(mt * 64 + ty * 4 + i) * Nn + nt * 64 + tx * 4] = o;
    }
}

// ================= flash W2 on tensor cores =================
__global__ __launch_bounds__(256) void flash_w2_mma() {
    __shared__ __align__(16) __half sql[128][72];
    __shared__ __align__(16) __half sk[64][72];
    __shared__ __align__(16) __half svT[64][72];

    int tid = threadIdx.x, lane = tid & 31, w = tid >> 5;
    int chunk = blockIdx.x, mblk = blockIdx.y, bh = blockIdx.z;
    int lr = lane & 15, lh = lane >> 4;

    const __half* qlh = g_qlh + (size_t)(bh * MLM + mblk * 128) * 64;
#pragma unroll
    for (int i = 0; i < 4; i++) {
        int idx = tid + i * 256;
        int r = idx >> 3, c = (idx & 7) * 8;
        *(uint4*)&sql[r][c] = *(const uint4*)&qlh[(size_t)r * 64 + c];
    }
    __syncthreads();
    unsigned qa[4][4];
#pragma unroll
    for (int ks = 0; ks < 4; ks++)
        ldm4(qa[ks], smem_u32(&sql[w * 16 + lr][ks * 16 + lh * 8]));

    float outacc[8][4];
#pragma unroll
    for (int i = 0; i < 8; i++)
#pragma unroll
        for (int c = 0; c < 4; c++) outacc[i][c] = 0.f;
    float rsA = 0.f, rsB = 0.f;

    const __half* kb = g_kh + (size_t)bh * NSEQ * 64;
    const __half* vb = g_vh + (size_t)bh * NSEQ * 64;

    for (int it = 0; it < 32; it++) {
        int s0 = chunk * 2048 + it * 64;
        __syncthreads();
#pragma unroll
        for (int i = 0; i < 2; i++) {
            int idx = tid + i * 256;
            int r = idx >> 3, c = (idx & 7) * 8;
            *(uint4*)&sk[r][c] = *(const uint4*)&kb[(size_t)(s0 + r) * 64 + c];
            uint4 vv = *(const uint4*)&vb[(size_t)(s0 + r) * 64 + c];
            __half vh[8];
            *(uint4*)vh = vv;
#pragma unroll
            for (int j = 0; j < 8; j++) svT[c + j][r] = vh[j];
        }
        __syncthreads();
        float sf[8][4];
#pragma unroll
        for (int i = 0; i < 8; i++)
#pragma unroll
            for (int c = 0; c < 4; c++) sf[i][c] = 0.f;
#pragma unroll
        for (int ks = 0; ks < 4; ks++) {
#pragma unroll
            for (int nf4 = 0; nf4 < 4; nf4++) {
                unsigned bbf[4];
                ldm4(bbf, smem_u32(&sk[nf4 * 16 + lr][ks * 16 + lh * 8]));
                mmaf16(sf[nf4 * 2], qa[ks], bbf[0], bbf[2]);
                mmaf16(sf[nf4 * 2 + 1], qa[ks], bbf[1], bbf[3]);
            }
        }
#pragma unroll
        for (int nf = 0; nf < 8; nf++) {
            sf[nf][0] = fexp(sf[nf][0]); sf[nf][1] = fexp(sf[nf][1]);
            sf[nf][2] = fexp(sf[nf][2]); sf[nf][3] = fexp(sf[nf][3]);
            rsA += sf[nf][0] + sf[nf][1];
            rsB += sf[nf][2] + sf[nf][3];
        }
#pragma unroll
        for (int kk = 0; kk < 4; kk++) {
            unsigned pa[4];
            pa[0] = packh2(sf[2 * kk][0], sf[2 * kk][1]);
            pa[1] = packh2(sf[2 * kk][2], sf[2 * kk][3]);
            pa[2] = packh2(sf[2 * kk + 1][0], sf[2 * kk + 1][1]);
            pa[3] = packh2(sf[2 * kk + 1][2], sf[2 * kk + 1][3]);
#pragma unroll
            for (int nf4 = 0; nf4 < 4; nf4++) {
                unsigned bbf[4];
                ldm4(bbf, smem_u32(&svT[nf4 * 16 + lr][kk * 16 + lh * 8]));
                mmaf16(outacc[nf4 * 2], pa, bbf[0], bbf[2]);
                mmaf16(outacc[nf4 * 2 + 1], pa, bbf[1], bbf[3]);
            }
        }
    }
    rsA += __shfl_xor_sync(0xffffffffu, rsA, 1);
    rsA += __shfl_xor_sync(0xffffffffu, rsA, 2);
    rsB += __shfl_xor_sync(0xffffffffu, rsB, 1);
    rsB += __shfl_xor_sync(0xffffffffu, rsB, 2);

    int rA = mblk * 128 + w * 16 + (lane >> 2);
    int rB = rA + 8;
    float* wpA = g_Wpart + (size_t)((bh * 4 + chunk) * MLM + rA) * 64;
    float* wpB = g_Wpart + (size_t)((bh * 4 + chunk) * MLM + rB) * 64;
#pragma unroll
    for (int nf = 0; nf < 8; nf++) {
        int d = nf * 8 + (lane & 3) * 2;
        *(float2*)&wpA[d] = make_float2(outacc[nf][0], outacc[nf][1]);
        *(float2*)&wpB[d] = make_float2(outacc[nf][2], outacc[nf][3]);
    }
    if ((lane & 3) == 0) {
        g_Spart[(bh * 4 + chunk) * MLM + rA] = rsA;
        g_Spart[(bh * 4 + chunk) * MLM + rB] = rsB;
    }
}

__global__ void combine_w2_kernel() {
    int idx = blockIdx.x * 256 + threadIdx.x;
    int bh = idx >> 14;
    int m = (idx >> 6) & 255;
    int d = idx & 63;
    float num = 0.f, den = 0.f;
#pragma unroll
    for (int c = 0; c < 4; c++) {
        num += g_Wpart[(size_t)((bh * 4 + c) * MLM + m) * 64 + d];
        den += g_Spart[(bh * 4 + c) * MLM + m];
    }
    g_W2[(bh * MLM + m) * 64 + d] = num / den;
}

// ================= attn1 + conv on tensor cores (writes fp16 to g_A16) =================
__global__ __launch_bounds__(256) void attn1_mma(const float* __restrict__ convw) {
    extern __shared__ char smx[];
    __half (*sq)[72]  = (__half(*)[72])(smx);
    __half (*skl)[72] = (__half(*)[72])(smx + 18432);
    __half (*swT)[72] = (__half(*)[72])(smx + 27648);
    __half (*sv)[72]  = (__half(*)[72])(smx + 36864);
    float* cw = (float*)(smx + 59904);

    int tid = threadIdx.x, lane = tid & 31, w = tid >> 5;
    int ntile = blockIdx.x, bh = blockIdx.y;
    int h = bh & 7, bb2 = bh >> 3;
    int n0 = ntile * 128;
    int lr = lane & 15, lh = lane >> 4;

    if (tid < KSZ) cw[tid] = convw[h * KSZ + tid];

    const __half* qb = g_qh + ((size_t)bh * NSEQ + n0) * 64;
#pragma unroll
    for (int i = 0; i < 4; i++) {
        int idx = tid + i * 256;
        int r = idx >> 3, c = (idx & 7) * 8;
        *(uint4*)&sq[r][c] = *(const uint4*)&qb[(size_t)r * 64 + c];
    }
    const __half* vb2 = g_vh + (size_t)bh * NSEQ * 64;
#pragma unroll
    for (int i = 0; i < 5; i++) {
        int idx = tid + i * 256;
        int r = idx >> 3, c = (idx & 7) * 8;
        int gr = n0 - 16 + r;
        uint4 z = make_uint4(0u, 0u, 0u, 0u);
        if (gr >= 0 && gr < NSEQ) z = *(const uint4*)&vb2[(size_t)gr * 64 + c];
        *(uint4*)&sv[r][c] = z;
    }
    __syncthreads();

    unsigned qa[4][4];
#pragma unroll
    for (int ks = 0; ks < 4; ks++)
        ldm4(qa[ks], smem_u32(&sq[w * 16 + lr][ks * 16 + lh * 8]));

    float outacc[8][4];
#pragma unroll
    for (int i = 0; i < 8; i++)
#pragma unroll
        for (int c = 0; c < 4; c++) outacc[i][c] = 0.f;
    float rsA = 0.f, rsB = 0.f;

    const __half* klb = g_klh + (size_t)bh * MLM * 64;
    const __half* w3tb = g_W3T + (size_t)bh * 64 * 256;

    for (int lc = 0; lc < 4; lc++) {
        __syncthreads();
#pragma unroll
        for (int i = 0; i < 2; i++) {
            int idx = tid + i * 256;
            int r = idx >> 3, c = (idx & 7) * 8;
            *(uint4*)&skl[r][c] = *(const uint4*)&klb[(size_t)(lc * 64 + r) * 64 + c];
            *(uint4*)&swT[r][c] = *(const uint4*)&w3tb[(size_t)r * 256 + lc * 64 + c];
        }
        __syncthreads();
        float sf[8][4];
#pragma unroll
        for (int i = 0; i < 8; i++)
#pragma unroll
            for (int c = 0; c < 4; c++) sf[i][c] = 0.f;
#pragma unroll
        for (int ks = 0; ks < 4; ks++) {
#pragma unroll
            for (int nf4 = 0; nf4 < 4; nf4++) {
                unsigned bbf[4];
                ldm4(bbf, smem_u32(&skl[nf4 * 16 + lr][ks * 16 + lh * 8]));
                mmaf16(sf[nf4 * 2], qa[ks], bbf[0], bbf[2]);
                mmaf16(sf[nf4 * 2 + 1], qa[ks], bbf[1], bbf[3]);
            }
        }
#pragma unroll
        for (int nf = 0; nf < 8; nf++) {
            sf[nf][0] = fexp(sf[nf][0]); sf[nf][1] = fexp(sf[nf][1]);
            sf[nf][2] = fexp(sf[nf][2]); sf[nf][3] = fexp(sf[nf][3]);
            rsA += sf[nf][0] + sf[nf][1];
            rsB += sf[nf][2] + sf[nf][3];
        }
#pragma unroll
        for (int kk = 0; kk < 4; kk++) {
            unsigned pa[4];
            pa[0] = packh2(sf[2 * kk][0], sf[2 * kk][1]);
            pa[1] = packh2(sf[2 * kk][2], sf[2 * kk][3]);
            pa[2] = packh2(sf[2 * kk + 1][0], sf[2 * kk + 1][1]);
            pa[3] = packh2(sf[2 * kk + 1][2], sf[2 * kk + 1][3]);
#pragma unroll
            for (int nf4 = 0; nf4 < 4; nf4++) {
                unsigned bbf[4];
                ldm4(bbf, smem_u32(&swT[nf4 * 16 + lr][kk * 16 + lh * 8]));
                mmaf16(outacc[nf4 * 2], pa, bbf[0], bbf[2]);
                mmaf16(outacc[nf4 * 2 + 1], pa, bbf[1], bbf[3]);
            }
        }
    }
    rsA += __shfl_xor_sync(0xffffffffu, rsA, 1);
    rsA += __shfl_xor_sync(0xffffffffu, rsA, 2);
    rsB += __shfl_xor_sync(0xffffffffu, rsB, 1);
    rsB += __shfl_xor_sync(0xffffffffu, rsB, 2);
    float invA = 1.f / rsA, invB = 1.f / rsB;

    int lrA = w * 16 + (lane >> 2);
#pragma unroll
    for (int nf = 0; nf < 8; nf++) {
        int d = nf * 8 + (lane & 3) * 2;
        float a0 = 0.f, a1 = 0.f, b0 = 0.f, b1 = 0.f;
#pragma unroll
        for (int t = 0; t < KSZ; t++) {
            float wv = cw[t];
            float2 fA = __half22float2(*(__half2*)&sv[lrA + t][d]);
            float2 fB = __half22float2(*(__half2*)&sv[lrA + 8 + t][d]);
            a0 = fmaf(wv, fA.x, a0); a1 = fmaf(wv, fA.y, a1);
            b0 = fmaf(wv, fB.x, b0); b1 = fmaf(wv, fB.y, b1);
        }
        outacc[nf][0] = outacc[nf][0] * invA + a0;
        outacc[nf][1] = outacc[nf][1] * invA + a1;
        outacc[nf][2] = outacc[nf][2] * invB + b0;
        outacc[nf][3] = outacc[nf][3] * invB + b1;
    }

    int nA = n0 + lrA, nB = nA + 8;
    __half* oA = g_A16 + (size_t)(bb2 * NSEQ + nA) * 512 + h * 64;
    __half* oB = g_A16 + (size_t)(bb2 * NSEQ + nB) * 512 + h * 64;
#pragma unroll
    for (int nf = 0; nf < 8; nf++) {
        int d = nf * 8 + (lane & 3) * 2;
        *(__half2*)&oA[d] = __floats2half2_rn(outacc[nf][0], outacc[nf][1]);
        *(__half2*)&oB[d] = __floats2half2_rn(outacc[nf][2], outacc[nf][3]);
    }
}

// ================= host launcher =================
extern "C" void kernel_launch(void* const* d_in, const int* in_sizes, int n_in,
                              void* d_out, int out_size) {
    const float* x     = (const float*)d_in[0];
    const float* ln_g  = (const float*)d_in[1];
    const float* ln_b  = (const float*)d_in[2];
    const float* W_qkv = (const float*)d_in[3];
    const float* W_out = (const float*)d_in[4];
    const float* b_out = (const float*)d_in[5];
    const float* convw = (const float*)d_in[6];
    float* out = (float*)d_out;

    cudaFuncSetAttribute(attn1_mma, cudaFuncAttributeMaxDynamicSharedMemorySize, 60416);
    cudaFuncSetAttribute(gemm_lm_kernel, cudaFuncAttributeMaxDynamicSharedMemorySize, 81920);
    cudaFuncSetAttribute(gemm16_kernel, cudaFuncAttributeMaxDynamicSharedMemorySize, 73728);

    __nv_bfloat16 *bqh, *bql;
    cudaGetSymbolAddress((void**)&bqh, g_Bqh);
    cudaGetSymbolAddress((void**)&bql, g_Bql);
    __half *b16q, *b16o;
    cudaGetSymbolAddress((void**)&b16q, g_B16q);
    cudaGetSymbolAddress((void**)&b16o, g_B16o);
    float *xnlmp;
    cudaGetSymbolAddress((void**)&xnlmp, g_xnlm);

    reset_kernel<<<1, 1>>>();
    ln_kernel<<<Bb * NSEQ, 128>>>(x, ln_g, ln_b);  // writes g_xn (fp32) + g_A16 (fp16)

    convW16_kernel<<<dim3(48, 16), 1024>>>(W_qkv, 1536, b16q);
    convW16_kernel<<<dim3(16, 16), 1024>>>(W_out, 512, b16o);

    // qkv GEMM: single-pass fp16
    gemm16_kernel<<<dim3(12, 128), 256, 73728>>>(b16q, 0, nullptr, nullptr);

    // landmark path: accurate small GEMM
    xnlm_kernel<<<1024, 256>>>();
    convA_kernel<<<256, 256>>>(xnlmp);
    convW_kernel<<<dim3(48, 16), 1024>>>(W_qkv, 1536, bqh, bql);
    gemm_lm_kernel<<<dim3(8, 4), 256, 81920>>>(bqh, bql);

    attn2_kernel<<<16, 256>>>();
    colmax_kernel<<<16, 256>>>();
    z0_kernel<<<4096, 256>>>();

    int zc = 4, zn = 5;  // Za, Zb
    for (int it = 0; it < 6; it++) {
        int np = (it == 5) ? 3 : 1;
        gemm_pinv_mma<<<dim3(4, 2, 16), 256>>>(1, 0, zc, 0.f, 1.f, 1.f, np);
        gemm_pinv_mma<<<dim3(4, 2, 16), 256>>>(2, 1, 1, 7.f, -1.f, 1.f, np);
        gemm_pinv_mma<<<dim3(4, 2, 16), 256>>>(3, 1, 2, 15.f, -1.f, 1.f, np);
        gemm_pinv_mma<<<dim3(4, 2, 16), 256>>>(zn, zc, 3, 13.f, -1.f, 0.25f, np);
        int t = zc; zc = zn; zn = t;
    }

    flash_w2_mma<<<dim3(4, 2, 16), 256>>>();
    combine_w2_kernel<<<1024, 256>>>();
    gemm_bh_kernel<<<dim3(1, 4, 16), 256>>>(7, zc, 6, 64, 0.f, 1.f, 1.f);  // W3 = Z @ W2
    w3t_kernel<<<1024, 256>>>();
    attn1_mma<<<dim3(64, 16), 256, 60416>>>(convw);  // writes fp16 into g_A16

    // out GEMM: single-pass fp16
    gemm16_kernel<<<dim3(4, 128), 256, 73728>>>(b16o, 1, b_out, out);
}

// round 12
// speedup vs baseline: 1.2608x; 1.0947x over previous
#include <cuda_runtime.h>
#include <cuda_bf16.h>
#include <cuda_fp16.h>

#define Bb    2
#define NSEQ  8192
#define DIMV  512
#define NH    8
#define BHn   16
#define DHd   64
#define MLM   256
#define LGRP  32
#define KSZ   33
#define PADc  16
#define SCALE 0.125f

// ================= static device scratch =================
__device__ float g_xn[(size_t)Bb * NSEQ * DIMV];
__device__ float g_xnlm[512 * 512];
__device__ float g_ql[BHn * MLM * DHd];
__device__ float g_kl[BHn * MLM * DHd];
__device__ float g_attn2[BHn * MLM * MLM];
__device__ float g_Y[BHn * MLM * MLM];
__device__ float g_P[BHn * MLM * MLM];
__device__ float g_Qm[BHn * MLM * MLM];
__device__ float g_Za[BHn * MLM * MLM];
__device__ float g_Zb[BHn * MLM * MLM];
__device__ float g_W2[BHn * MLM * DHd];
__device__ float g_W3[BHn * MLM * DHd];
__device__ float g_Wpart[(size_t)BHn * 4 * MLM * DHd];
__device__ float g_Spart[BHn * 4 * MLM];
__device__ int   g_maxc_bits;
__device__ unsigned g_bar;

// bf16 hi/lo buffers (landmark GEMM)
__device__ __nv_bfloat16 g_Ahi[512 * 512];
__device__ __nv_bfloat16 g_Alo[512 * 512];
__device__ __nv_bfloat16 g_Bqh[1536 * 512];
__device__ __nv_bfloat16 g_Bql[1536 * 512];

// fp16 buffers
__device__ __half g_A16[(size_t)Bb * NSEQ * DIMV];
__device__ __half g_B16q[1536 * 512];
__device__ __half g_B16o[512 * 512];
__device__ __half g_qh[(size_t)BHn * NSEQ * DHd];
__device__ __half g_kh[(size_t)BHn * NSEQ * DHd];
__device__ __half g_vh[(size_t)BHn * NSEQ * DHd];
__device__ __half g_qlh[BHn * MLM * DHd];
__device__ __half g_klh[BHn * MLM * DHd];
__device__ __half g_W3T[BHn * DHd * MLM];

__global__ void reset_kernel() { g_maxc_bits = 0; g_bar = 0u; }

// ================= mma.sync helpers =================
__device__ __forceinline__ unsigned smem_u32(const void* p) {
    unsigned a;
    asm("{ .reg .u64 t; cvta.to.shared.u64 t, %1; cvt.u32.u64 %0, t; }" : "=r"(a) : "l"(p));
    return a;
}
__device__ __forceinline__ void ldm4(unsigned* r, unsigned addr) {
    asm volatile("ldmatrix.sync.aligned.m8n8.x4.shared.b16 {%0,%1,%2,%3}, [%4];"
        : "=r"(r[0]), "=r"(r[1]), "=r"(r[2]), "=r"(r[3]) : "r"(addr));
}
__device__ __forceinline__ void mma16816(float* c, const unsigned* a, unsigned b0, unsigned b1) {
    asm volatile("mma.sync.aligned.m16n8k16.row.col.f32.bf16.bf16.f32 "
        "{%0,%1,%2,%3}, {%4,%5,%6,%7}, {%8,%9}, {%0,%1,%2,%3};"
        : "+f"(c[0]), "+f"(c[1]), "+f"(c[2]), "+f"(c[3])
        : "r"(a[0]), "r"(a[1]), "r"(a[2]), "r"(a[3]), "r"(b0), "r"(b1));
}
__device__ __forceinline__ void mmaf16(float* c, const unsigned* a, unsigned b0, unsigned b1) {
    asm volatile("mma.sync.aligned.m16n8k16.row.col.f32.f16.f16.f32 "
        "{%0,%1,%2,%3}, {%4,%5,%6,%7}, {%8,%9}, {%0,%1,%2,%3};"
        : "+f"(c[0]), "+f"(c[1]), "+f"(c[2]), "+f"(c[3])
        : "r"(a[0]), "r"(a[1]), "r"(a[2]), "r"(a[3]), "r"(b0), "r"(b1));
}
__device__ __forceinline__ void cpasync16(unsigned dst, const void* src) {
    asm volatile("cp.async.cg.shared.global [%0], [%1], 16;" :: "r"(dst), "l"(src));
}
#define CP_COMMIT() asm volatile("cp.async.commit_group;" ::: "memory")
__device__ __forceinline__ unsigned packh2(float a, float b) {
    __half2 h = __floats2half2_rn(a, b);
    return *(unsigned*)&h;
}
__device__ __forceinline__ float fexp(float x) {
    float t = x * 1.44269504f;
    float r = rintf(t);
    float f = t - r;
    float p = 1.33336e-3f;
    p = fmaf(p, f, 9.61813e-3f);
    p = fmaf(p, f, 5.55041e-2f);
    p = fmaf(p, f, 2.40226507e-1f);
    p = fmaf(p, f, 6.93147181e-1f);
    p = fmaf(p, f, 1.0f);
    int e = (int)r;
    return p * __int_as_float((e + 127) << 23);
}

// ================= layernorm (writes fp32 + fp16) =================
__global__ __launch_bounds__(128) void ln_kernel(const float* __restrict__ x,
                                                 const float* __restrict__ gam,
                                                 const float* __restrict__ bet) {
    int row = blockIdx.x;
    int tid = threadIdx.x;
    float4 v = ((const float4*)x)[(size_t)row * 128 + tid];
    float s1 = v.x + v.y + v.z + v.w;
    float s2 = v.x * v.x + v.y * v.y + v.z * v.z + v.w * v.w;
#pragma unroll
    for (int o = 16; o; o >>= 1) {
        s1 += __shfl_xor_sync(0xffffffffu, s1, o);
        s2 += __shfl_xor_sync(0xffffffffu, s2, o);
    }
    __shared__ float r1[4], r2[4];
    int w = tid >> 5;
    if ((tid & 31) == 0) { r1[w] = s1; r2[w] = s2; }
    __syncthreads();
    s1 = r1[0] + r1[1] + r1[2] + r1[3];
    s2 = r2[0] + r2[1] + r2[2] + r2[3];
    float mean = s1 * (1.f / 512.f);
    float var  = s2 * (1.f / 512.f) - mean * mean;
    float rstd = rsqrtf(var + 1e-5f);
    float4 g4 = ((const float4*)gam)[tid];
    float4 b4 = ((const float4*)bet)[tid];
    float4 o;
    o.x = (v.x - mean) * rstd * g4.x + b4.x;
    o.y = (v.y - mean) * rstd * g4.y + b4.y;
    o.z = (v.z - mean) * rstd * g4.z + b4.z;
    o.w = (v.w - mean) * rstd * g4.w + b4.w;
    ((float4*)g_xn)[(size_t)row * 128 + tid] = o;
    __half2* ph = (__half2*)(g_A16 + (size_t)row * 512 + tid * 4);
    ph[0] = __floats2half2_rn(o.x, o.y);
    ph[1] = __floats2half2_rn(o.z, o.w);
}

// ================= group means of xn (landmark pre-image) =================
__global__ void xnlm_kernel() {
    int idx = blockIdx.x * 256 + threadIdx.x;
    int row = idx >> 9;
    int d = idx & 511;
    int b = row >> 8, m = row & 255;
    const float* p = g_xn + ((size_t)(b * NSEQ) + m * LGRP) * DIMV + d;
    float s = 0.f;
#pragma unroll
    for (int i = 0; i < LGRP; i++) s += p[(size_t)i * DIMV];
    g_xnlm[idx] = s * (1.f / LGRP);
}

// ================= converters =================
__global__ __launch_bounds__(256) void convA_kernel(const float* __restrict__ src) {
    size_t i4 = ((size_t)blockIdx.x * 256 + threadIdx.x) * 4;
    float4 v = *(const float4*)(src + i4);
    __nv_bfloat16 h0 = __float2bfloat16(v.x), h1 = __float2bfloat16(v.y);
    __nv_bfloat16 h2 = __float2bfloat16(v.z), h3 = __float2bfloat16(v.w);
    __nv_bfloat16 l0 = __float2bfloat16(v.x - __bfloat162float(h0));
    __nv_bfloat16 l1 = __float2bfloat16(v.y - __bfloat162float(h1));
    __nv_bfloat16 l2 = __float2bfloat16(v.z - __bfloat162float(h2));
    __nv_bfloat16 l3 = __float2bfloat16(v.w - __bfloat162float(h3));
    __nv_bfloat162* ph = (__nv_bfloat162*)(g_Ahi + i4);
    __nv_bfloat162* pl = (__nv_bfloat162*)(g_Alo + i4);
    ph[0] = __nv_bfloat162(h0, h1); ph[1] = __nv_bfloat162(h2, h3);
    pl[0] = __nv_bfloat162(l0, l1); pl[1] = __nv_bfloat162(l2, l3);
}

__global__ __launch_bounds__(1024) void convW_kernel(const float* __restrict__ W, int N,
                                                     __nv_bfloat16* __restrict__ BThi,
                                                     __nv_bfloat16* __restrict__ BTlo) {
    __shared__ float sh[32][33];
    int n0 = blockIdx.x * 32, k0 = blockIdx.y * 32;
    int tx = threadIdx.x & 31, ty = threadIdx.x >> 5;
    sh[ty][tx] = W[(size_t)(k0 + ty) * N + n0 + tx];
    __syncthreads();
    float x = sh[tx][ty];
    __nv_bfloat16 h = __float2bfloat16(x);
    __nv_bfloat16 l = __float2bfloat16(x - __bfloat162float(h));
    BThi[(size_t)(n0 + ty) * 512 + k0 + tx] = h;
    BTlo[(size_t)(n0 + ty) * 512 + k0 + tx] = l;
}

__global__ __launch_bounds__(1024) void convW16_kernel(const float* __restrict__ W, int N,
                                                       __half* __restrict__ BT) {
    __shared__ float sh[32][33];
    int n0 = blockIdx.x * 32, k0 = blockIdx.y * 32;
    int tx = threadIdx.x & 31, ty = threadIdx.x >> 5;
    sh[ty][tx] = W[(size_t)(k0 + ty) * N + n0 + tx];
    __syncthreads();
    BT[(size_t)(n0 + ty) * 512 + k0 + tx] = __float2half(sh[tx][ty]);
}

// W3 -> W3T fp16 [bh][d][m]
__global__ void w3t_kernel() {
    int idx = blockIdx.x * 256 + threadIdx.x;
    int bh = idx >> 14;
    int m = (idx >> 6) & 255;
    int d = idx & 63;
    float v = g_W3[(bh * 256 + m) * 64 + d];
    g_W3T[((size_t)bh * 64 + d) * 256 + m] = __float2half(v);
}

// ================= fp16 single-pass dense GEMM (cp.async double-buffered) =================
__global__ __launch_bounds__(256) void gemm16_kernel(
    const __half* __restrict__ gBbase, int mode,
    const float* __restrict__ bout, float* __restrict__ outp) {
    extern __shared__ char smdyn[];
    unsigned sbase = smem_u32(smdyn);
    int tid = threadIdx.x, lane = tid & 31, wid = tid >> 5;
    int wm = wid & 3, wn = wid >> 2;
    int mBase = blockIdx.y * 128, nBase = blockIdx.x * 128;
    int lr = lane & 15, lh = lane >> 4;

    const __half* gA = g_A16 + (size_t)mBase * 512;
    const __half* gB = gBbase + (size_t)nBase * 512;

    float acc[2][8][4];
#pragma unroll
    for (int i = 0; i < 2; i++)
#pragma unroll
        for (int j = 0; j < 8; j++)
#pragma unroll
            for (int c = 0; c < 4; c++) acc[i][j][c] = 0.f;

    int r_ld = tid >> 1;
    int q2 = (tid & 1) * 4;

    auto load_stage = [&](int ch, unsigned st) {
#pragma unroll
        for (int u = 0; u < 4; u++) {
            unsigned soff = (unsigned)r_ld * 144u + (q2 + u) * 16u;
            size_t goff = (size_t)r_ld * 512 + ch * 64 + (q2 + u) * 8;
            cpasync16(sbase + st + soff, gA + goff);
            cpasync16(sbase + st + 18432u + soff, gB + goff);
        }
        CP_COMMIT();
    };

    load_stage(0, 0u);

    for (int ch = 0; ch < 8; ch++) {
        unsigned st = (unsigned)(ch & 1) * 36864u;
        if (ch + 1 < 8) {
            load_stage(ch + 1, (unsigned)((ch + 1) & 1) * 36864u);
            asm volatile("cp.async.wait_group 1;" ::: "memory");
        } else {
            asm volatile("cp.async.wait_group 0;" ::: "memory");
        }
        __syncthreads();

        unsigned aA = sbase + st;
        unsigned aB = aA + 18432u;
#pragma unroll
        for (int ks = 0; ks < 4; ks++) {
            unsigned kc2 = (unsigned)(ks * 16 + lh * 8) * 2u;
            unsigned ah[2][4];
#pragma unroll
            for (int mi = 0; mi < 2; mi++) {
                unsigned rowA = (unsigned)(wm * 32 + mi * 16 + lr) * 144u;
                ldm4(ah[mi], aA + rowA + kc2);
            }
#pragma unroll
            for (int nt = 0; nt < 4; nt++) {
                unsigned rowB = (unsigned)(wn * 64 + nt * 16 + lr) * 144u;
                unsigned bf[4];
                ldm4(bf, aB + rowB + kc2);
#pragma unroll
                for (int mi = 0; mi < 2; mi++) {
#pragma unroll
                    for (int ns = 0; ns < 2; ns++)
                        mmaf16(acc[mi][nt * 2 + ns], ah[mi], bf[ns], bf[ns + 2]);
                }
            }
        }
        __syncthreads();
    }

    int r0 = mBase + wm * 32 + (lane >> 2);
    if (mode == 0) {
        int sec = nBase >> 9;
        float sc = (sec == 0) ? SCALE : 1.f;
        __half* hdst = (sec == 0) ? g_qh : ((sec == 1) ? g_kh : g_vh);
        int h = ((nBase + wn * 64) >> 6) & 7;
#pragma unroll
        for (int mi = 0; mi < 2; mi++) {
#pragma unroll
            for (int jn = 0; jn < 8; jn++) {
                int d = jn * 8 + (lane & 3) * 2;
#pragma unroll
                for (int half = 0; half < 2; half++) {
                    int gr = r0 + mi * 16 + half * 8;
                    int bb = gr >> 13, n = gr & 8191;
                    size_t off = ((size_t)(bb * 8 + h) * NSEQ + n) * 64 + d;
                    *(__half2*)&hdst[off] = __floats2half2_rn(acc[mi][jn][half * 2] * sc,
                                                              acc[mi][jn][half * 2 + 1] * sc);
                }
            }
        }
    } else {
#pragma unroll
        for (int mi = 0; mi < 2; mi++) {
#pragma unroll
            for (int jn = 0; jn < 8; jn++) {
                int gc = nBase + wn * 64 + jn * 8 + (lane & 3) * 2;
#pragma unroll
                for (int half = 0; half < 2; half++) {
                    int gr = r0 + mi * 16 + half * 8;
                    float2 bo = *(const float2*)&bout[gc];
                    float2 xv = *(const float2*)&g_xn[(size_t)gr * 512 + gc];
                    float2 o = make_float2(acc[mi][jn][half * 2] + bo.x + xv.x,
                                           acc[mi][jn][half * 2 + 1] + bo.y + xv.y);
                    *(float2*)&outp[(size_t)gr * 512 + gc] = o;
                }
            }
        }
    }
}

// ================= bf16 split landmark GEMM (M=512, N=1024) =================
__global__ __launch_bounds__(256) void gemm_lm_kernel(
    const __nv_bfloat16* __restrict__ BThi, const __nv_bfloat16* __restrict__ BTlo) {
    extern __shared__ char smdyn[];
    unsigned sbase = smem_u32(smdyn);
    int tid = threadIdx.x, lane = tid & 31, wid = tid >> 5;
    int wm = wid & 3, wn = wid >> 2;
    int mBase = blockIdx.y * 128, nBase = blockIdx.x * 128;
    int lr = lane & 15, lh = lane >> 4;

    const __nv_bfloat16* gsrc[4];
    gsrc[0] = g_Ahi + (size_t)mBase * 512;
    gsrc[1] = g_Alo + (size_t)mBase * 512;
    gsrc[2] = BThi + (size_t)nBase * 512;
    gsrc[3] = BTlo + (size_t)nBase * 512;

    float acc[2][8][4];
#pragma unroll
    for (int i = 0; i < 2; i++)
#pragma unroll
        for (int j = 0; j < 8; j++)
#pragma unroll
            for (int c = 0; c < 4; c++) acc[i][j][c] = 0.f;

    int r_ld0 = tid >> 2, q_ld = tid & 3;
    unsigned so0 = (unsigned)r_ld0 * 80u + q_ld * 16u;
    unsigned so1 = (unsigned)(r_ld0 + 64) * 80u + q_ld * 16u;

    {
        size_t go0 = (size_t)r_ld0 * 512 + q_ld * 8;
        size_t go1 = (size_t)(r_ld0 + 64) * 512 + q_ld * 8;
#pragma unroll
        for (int a = 0; a < 4; a++) {
            cpasync16(sbase + a * 10240u + so0, gsrc[a] + go0);
            cpasync16(sbase + a * 10240u + so1, gsrc[a] + go1);
        }
        CP_COMMIT();
    }

    for (int ch = 0; ch < 16; ch++) {
        unsigned st = (unsigned)(ch & 1) * 40960u;
        if (ch + 1 < 16) {
            unsigned stn = (unsigned)((ch + 1) & 1) * 40960u;
            size_t go0 = (size_t)r_ld0 * 512 + (ch + 1) * 32 + q_ld * 8;
            size_t go1 = (size_t)(r_ld0 + 64) * 512 + (ch + 1) * 32 + q_ld * 8;
#pragma unroll
            for (int a = 0; a < 4; a++) {
                cpasync16(sbase + stn + a * 10240u + so0, gsrc[a] + go0);
                cpasync16(sbase + stn + a * 10240u + so1, gsrc[a] + go1);
            }
            CP_COMMIT();
            asm volatile("cp.async.wait_group 1;" ::: "memory");
        } else {
            asm volatile("cp.async.wait_group 0;" ::: "memory");
        }
        __syncthreads();

        unsigned aAh = sbase + st;
        unsigned aAl = aAh + 10240u;
        unsigned aBh = aAh + 20480u;
        unsigned aBl = aAh + 30720u;
#pragma unroll
        for (int ks = 0; ks < 2; ks++) {
            unsigned kc2 = (unsigned)(ks * 16 + lh * 8) * 2u;
            unsigned ah[2][4], al[2][4];
#pragma unroll
            for (int mi = 0; mi < 2; mi++) {
                unsigned rowA = (unsigned)(wm * 32 + mi * 16 + lr) * 80u;
                ldm4(ah[mi], aAh + rowA + kc2);
                ldm4(al[mi], aAl + rowA + kc2);
            }
#pragma unroll
            for (int nt = 0; nt < 4; nt++) {
                unsigned rowB = (unsigned)(wn * 64 + nt * 16 + lr) * 80u;
                unsigned bh[4], bl[4];
                ldm4(bh, aBh + rowB + kc2);
                ldm4(bl, aBl + rowB + kc2);
#pragma unroll
                for (int mi = 0; mi < 2; mi++) {
#pragma unroll
                    for (int ns = 0; ns < 2; ns++) {
                        float* cc = acc[mi][nt * 2 + ns];
                        mma16816(cc, ah[mi], bh[ns], bh[ns + 2]);
                        mma16816(cc, ah[mi], bl[ns], bl[ns + 2]);
                        mma16816(cc, al[mi], bh[ns], bh[ns + 2]);
                    }
                }
            }
        }
        __syncthreads();
    }

    int r0 = mBase + wm * 32 + (lane >> 2);
    int sec = nBase >> 9;
    float sc = (sec == 0) ? SCALE : 1.f;
    float* dst = (sec == 0) ? g_ql : g_kl;
    __half* hdst = (sec == 0) ? g_qlh : g_klh;
    int h = ((nBase + wn * 64) >> 6) & 7;
#pragma unroll
    for (int mi = 0; mi < 2; mi++) {
#pragma unroll
        for (int jn = 0; jn < 8; jn++) {
            int d = jn * 8 + (lane & 3) * 2;
#pragma unroll
            for (int half = 0; half < 2; half++) {
                int gr = r0 + mi * 16 + half * 8;
                int bb = gr >> 8, m = gr & 255;
                float2 o = make_float2(acc[mi][jn][half * 2] * sc,
                                       acc[mi][jn][half * 2 + 1] * sc);
                size_t off = ((size_t)(bb * 8 + h) * MLM + m) * 64 + d;
                *(float2*)&dst[off] = o;
                *(__half2*)&hdst[off] = __floats2half2_rn(o.x, o.y);
            }
        }
    }
}

// ================= attn2 = softmax(q_l k_l^T), 64 CTAs =================
// grid (4 row-tiles, 16 bh); thread = (row within 64, col-quarter)
__global__ __launch_bounds__(256) void attn2_kernel() {
    extern __shared__ float sklf[];  // 256*64 floats = 64 KB
    int rt = blockIdx.x, bh = blockIdx.y;
    int tid = threadIdx.x;
    int row = rt * 64 + (tid >> 2);
    int cg = tid & 3;

    const float4* klsrc = (const float4*)(g_kl + (size_t)bh * MLM * 64);
    float4* kld = (float4*)sklf;
#pragma unroll
    for (int i = 0; i < 16; i++) kld[tid + i * 256] = klsrc[tid + i * 256];

    float4 q[16];
    const float4* qp = (const float4*)(g_ql + (size_t)(bh * MLM + row) * 64);
#pragma unroll
    for (int i = 0; i < 16; i++) q[i] = qp[i];
    __syncthreads();

    float p[64];
    float sum = 0.f;
    const float4* klb = (const float4*)sklf + cg * 64 * 16;
    for (int j = 0; j < 64; j++) {
        const float4* kr = klb + j * 16;
        float s = 0.f;
#pragma unroll
        for (int d = 0; d < 16; d++) {
            float4 a = q[d], b = kr[d];
            s += a.x * b.x + a.y * b.y + a.z * b.z + a.w * b.w;
        }
        p[j] = __expf(s);
        sum += p[j];
    }
    sum += __shfl_xor_sync(0xffffffffu, sum, 1);
    sum += __shfl_xor_sync(0xffffffffu, sum, 2);
    float inv = 1.f / sum;
    float* arow = g_attn2 + (size_t)bh * 65536 + (size_t)row * 256 + cg * 64;
#pragma unroll
    for (int j = 0; j < 64; j += 4)
        *(float4*)&arow[j] = make_float4(p[j] * inv, p[j + 1] * inv,
                                         p[j + 2] * inv, p[j + 3] * inv);
}

// ================= max column-sum of attn2 =================
__global__ __launch_bounds__(256) void colmax_kernel() {
    int bh = blockIdx.x;
    int j = threadIdx.x;
    const float* a = g_attn2 + (size_t)bh * 65536;
    float s = 0.f;
    for (int m2 = 0; m2 < 256; m2++) s += a[m2 * 256 + j];
    __shared__ float red[256];
    red[j] = s;
    __syncthreads();
    for (int o = 128; o; o >>= 1) {
        if (j < o) red[j] = fmaxf(red[j], red[j + o]);
        __syncthreads();
    }
    if (j == 0) atomicMax(&g_maxc_bits, __float_as_int(red[0]));
}

__global__ void z0_kernel() {
    int idx = blockIdx.x * 256 + threadIdx.x;
    int bh = idx >> 16;
    int i = (idx >> 8) & 255;
    int j = idx & 255;
    float scale = 1.f / __int_as_float(g_maxc_bits);
    g_Za[idx] = g_attn2[(bh << 16) + (j << 8) + i] * scale;
}

// ================= buffer selector =================
__device__ __forceinline__ float* pickBuf(int id) {
    switch (id) {
        case 0: return g_attn2;
        case 1: return g_Y;
        case 2: return g_P;
        case 3: return g_Qm;
        case 4: return g_Za;
        case 5: return g_Zb;
        case 6: return g_W2;
        default: return g_W3;
    }
}

// ================= persistent pinv: all 24 GEMM steps in one kernel =================
// grid (4 nt, 2 mt, 16 bh) = 128 CTAs <= 148 SMs -> all co-resident, software barrier safe.
// A/B loads via __ldcg (L2-coherent) to avoid stale L1 across steps.
struct PinvSmem {
    __nv_bfloat16 Ah[128][40];
    __nv_bfloat16 Al[128][40];
    __nv_bfloat16 Bh[64][40];
    __nv_bfloat16 Bl[64][40];
};

__device__ __forceinline__ void gbarrier(int step) {
    __syncthreads();
    if (threadIdx.x == 0) {
        __threadfence();
        atomicAdd(&g_bar, 1u);
        unsigned target = 128u * (unsigned)step;
        while (*(volatile unsigned*)&g_bar < target) { }
    }
    __syncthreads();
}

__device__ void pinv_gemm(PinvSmem& S, int cId, int aId, int bId,
                          float beta, float sgn, float alpha, bool full,
                          int mBase, int nBase, int bh) {
    const float* A = pickBuf(aId) + (size_t)bh * 65536;
    const float* B = pickBuf(bId) + (size_t)bh * 65536;
    float*       C = pickBuf(cId) + (size_t)bh * 65536;

    int tid = threadIdx.x, lane = tid & 31, w = tid >> 5;
    int wm = w & 3, wn = w >> 2;
    int lr = lane & 15, lh = lane >> 4;

    float acc[2][4][4];
#pragma unroll
    for (int i = 0; i < 2; i++)
#pragma unroll
        for (int j = 0; j < 4; j++)
#pragma unroll
            for (int c = 0; c < 4; c++) acc[i][j][c] = 0.f;

    for (int ch = 0; ch < 8; ch++) {
        if (ch) __syncthreads();
#pragma unroll
        for (int i = 0; i < 4; i++) {
            int idx = tid + i * 256;
            int r = idx >> 3, c4 = (idx & 7) * 4;
            float4 v = __ldcg((const float4*)&A[(size_t)(mBase + r) * 256 + ch * 32 + c4]);
            __nv_bfloat16 h0 = __float2bfloat16(v.x), h1 = __float2bfloat16(v.y);
            __nv_bfloat16 h2 = __float2bfloat16(v.z), h3 = __float2bfloat16(v.w);
            S.Ah[r][c4 + 0] = h0; S.Ah[r][c4 + 1] = h1;
            S.Ah[r][c4 + 2] = h2; S.Ah[r][c4 + 3] = h3;
            if (full) {
                S.Al[r][c4 + 0] = __float2bfloat16(v.x - __bfloat162float(h0));
                S.Al[r][c4 + 1] = __float2bfloat16(v.y - __bfloat162float(h1));
                S.Al[r][c4 + 2] = __float2bfloat16(v.z - __bfloat162float(h2));
                S.Al[r][c4 + 3] = __float2bfloat16(v.w - __bfloat162float(h3));
            }
        }
#pragma unroll
        for (int kl = 0; kl < 4; kl++) {
            int gk = ch * 32 + w * 4 + kl;
#pragma unroll
            for (int nh = 0; nh < 2; nh++) {
                int n = nh * 32 + lane;
                float v = __ldcg(&B[(size_t)gk * 256 + nBase + n]);
                v = sgn * v + ((gk == nBase + n) ? beta : 0.f);
                __nv_bfloat16 h = __float2bfloat16(v);
                S.Bh[n][w * 4 + kl] = h;
                if (full) S.Bl[n][w * 4 + kl] = __float2bfloat16(v - __bfloat162float(h));
            }
        }
        __syncthreads();
#pragma unroll
        for (int ks = 0; ks < 2; ks++) {
            int kc = ks * 16 + lh * 8;
            unsigned ah[2][4], al[2][4];
#pragma unroll
            for (int mi = 0; mi < 2; mi++) {
                int rowA = wm * 32 + mi * 16 + lr;
                ldm4(ah[mi], smem_u32(&S.Ah[rowA][kc]));
                if (full) ldm4(al[mi], smem_u32(&S.Al[rowA][kc]));
            }
#pragma unroll
            for (int nt = 0; nt < 2; nt++) {
                int rowB = wn * 32 + nt * 16 + lr;
                unsigned bhf[4], blf[4];
                ldm4(bhf, smem_u32(&S.Bh[rowB][kc]));
                if (full) ldm4(blf, smem_u32(&S.Bl[rowB][kc]));
#pragma unroll
                for (int mi = 0; mi < 2; mi++) {
#pragma unroll
                    for (int ns = 0; ns < 2; ns++) {
                        float* cc = acc[mi][nt * 2 + ns];
                        mma16816(cc, ah[mi], bhf[ns], bhf[ns + 2]);
                        if (full) {
                            mma16816(cc, ah[mi], blf[ns], blf[ns + 2]);
                            mma16816(cc, al[mi], bhf[ns], bhf[ns + 2]);
                        }
                    }
                }
            }
        }
    }
#pragma unroll
    for (int mi = 0; mi < 2; mi++) {
#pragma unroll
        for (int jn = 0; jn < 4; jn++) {
            int gc = nBase + wn * 32 + jn * 8 + (lane & 3) * 2;
#pragma unroll
            for (int half = 0; half < 2; half++) {
                int gr = mBase + wm * 32 + mi * 16 + (lane >> 2) + half * 8;
                float2 o = make_float2(acc[mi][jn][half * 2] * alpha,
                                       acc[mi][jn][half * 2 + 1] * alpha);
                *(float2*)&C[(size_t)gr * 256 + gc] = o;
            }
        }
    }
}

__global__ __launch_bounds__(256) void pinv_persist() {
    __shared__ PinvSmem S;
    int bh = blockIdx.z;
    int mBase = blockIdx.y * 128, nBase = blockIdx.x * 64;
    int step = 0;
    for (int it = 0; it < 6; it++) {
        bool full = (it == 5);
        int zc = 4 + (it & 1), zn = 5 - (it & 1);
        pinv_gemm(S, 1, 0, zc, 0.f, 1.f, 1.f, full, mBase, nBase, bh);
        gbarrier(++step);
        pinv_gemm(S, 2, 1, 1, 7.f, -1.f, 1.f, full, mBase, nBase, bh);
        gbarrier(++step);
        pinv_gemm(S, 3, 1, 2, 15.f, -1.f, 1.f, full, mBase, nBase, bh);
        gbarrier(++step);
        pinv_gemm(S, zn, zc, 3, 13.f, -1.f, 0.25f, full, mBase, nBase, bh);
        gbarrier(++step);
    }
}

// ================= batched per-bh GEMM (scalar, kept for W3) =================
__global__ __launch_bounds__(256) void gemm_bh_kernel(int cId, int aId, int bId, int Nn,
                                                      float beta, float sgn, float alpha) {
    int bh = blockIdx.z, mt = blockIdx.y, nt = blockIdx.x;
    const float* A  = pickBuf(aId) + (size_t)bh * 65536;
    const float* Bp = pickBuf(bId) + (size_t)bh * 256 * Nn;
    float*       C  = pickBuf(cId) + (size_t)bh * 256 * Nn;
    __shared__ float As[16][64];
    __shared__ float Bs[16][64];
    int tid = threadIdx.x;
    int ar = tid >> 2, ac = (tid & 3) * 4;
    int br = tid >> 4, bc = (tid & 15) * 4;
    int ty = tid >> 4, tx = tid & 15;
    float acc[4][4];
#pragma unroll
    for (int i = 0; i < 4; i++)
#pragma unroll
        for (int j = 0; j < 4; j++) acc[i][j] = 0.f;

    for (int k0 = 0; k0 < 256; k0 += 16) {
        float4 av = *(const float4*)&A[(size_t)(mt * 64 + ar) * 256 + k0 + ac];
        As[ac + 0][ar] = av.x; As[ac + 1][ar] = av.y;
        As[ac + 2][ar] = av.z; As[ac + 3][ar] = av.w;
        int gk = k0 + br;
        int gc = nt * 64 + bc;
        float4 bv = *(const float4*)&Bp[(size_t)gk * Nn + gc];
        bv.x = sgn * bv.x + (gk == gc + 0 ? beta : 0.f);
        bv.y = sgn * bv.y + (gk == gc + 1 ? beta : 0.f);
        bv.z = sgn * bv.z + (gk == gc + 2 ? beta : 0.f);
        bv.w = sgn * bv.w + (gk == gc + 3 ? beta : 0.f);
        *(float4*)&Bs[br][bc] = bv;
        __syncthreads();
#pragma unroll
        for (int kk = 0; kk < 16; kk++) {
            float4 a4 = *(const float4*)&As[kk][ty * 4];
            float4 b4 = *(const float4*)&Bs[kk][tx * 4];
            acc[0][0] += a4.x * b4.x; acc[0][1] += a4.x * b4.y; acc[0][2] += a4.x * b4.z; acc[0][3] += a4.x * b4.w;
            acc[1][0] += a4.y * b4.x; acc[1][1] += a4.y * b4.y; acc[1][2] += a4.y * b4.z; acc[1][3] += a4.y * b4.w;
            acc[2][0] += a4.z * b4.x; acc[2][1] += a4.z * b4.y; acc[2][2] += a4.z * b4.z; acc[2][3] += a4.z * b4.w;
            acc[3][0] += a4.w * b4.x; acc[3][1] += a4.w * b4.y; acc[3][2] += a4.w * b4.z; acc[3][3] += a4.w * b4.w;
        }
        __syncthreads();
    }
#pragma unroll
    for (int i = 0; i < 4; i++) {
        float4 o = make_float4(acc[i][0] * alpha, acc[i][1] * alpha,
                               acc[i][2] * alpha, acc[i][3] * alpha);
        *(float4*)&C[(size_t)(mt * 64 + ty * 4 + i) * Nn + nt * 64 + tx * 4] = o;
    }
}

// ================= flash W2 on tensor cores =================
__global__ __launch_bounds__(256) void flash_w2_mma() {
    __shared__ __align__(16) __half sql[128][72];
    __shared__ __align__(16) __half sk[64][72];
    __shared__ __align__(16) __half svT[64][72];

    int tid = threadIdx.x, lane = tid & 31, w = tid >> 5;
    int chunk = blockIdx.x, mblk = blockIdx.y, bh = blockIdx.z;
    int lr = lane & 15, lh = lane >> 4;

    const __half* qlh = g_qlh + (size_t)(bh * MLM + mblk * 128) * 64;
#pragma unroll
    for (int i = 0; i < 4; i++) {
        int idx = tid + i * 256;
        int r = idx >> 3, c = (idx & 7) * 8;
        *(uint4*)&sql[r][c] = *(const uint4*)&qlh[(size_t)r * 64 + c];
    }
    __syncthreads();
    unsigned qa[4][4];
#pragma unroll
    for (int ks = 0; ks < 4; ks++)
        ldm4(qa[ks], smem_u32(&sql[w * 16 + lr][ks * 16 + lh * 8]));

    float outacc[8][4];
#pragma unroll
    for (int i = 0; i < 8; i++)
#pragma unroll
        for (int c = 0; c < 4; c++) outacc[i][c] = 0.f;
    float rsA = 0.f, rsB = 0.f;

    const __half* kb = g_kh + (size_t)bh * NSEQ * 64;
    const __half* vb = g_vh + (size_t)bh * NSEQ * 64;

    for (int it = 0; it < 32; it++) {
        int s0 = chunk * 2048 + it * 64;
        __syncthreads();
#pragma unroll
        for (int i = 0; i < 2; i++) {
            int idx = tid + i * 256;
            int r = idx >> 3, c = (idx & 7) * 8;
            *(uint4*)&sk[r][c] = *(const uint4*)&kb[(size_t)(s0 + r) * 64 + c];
            uint4 vv = *(const uint4*)&vb[(size_t)(s0 + r) * 64 + c];
            __half vh[8];
            *(uint4*)vh = vv;
#pragma unroll
            for (int j = 0; j < 8; j++) svT[c + j][r] = vh[j];
        }
        __syncthreads();
        float sf[8][4];
#pragma unroll
        for (int i = 0; i < 8; i++)
#pragma unroll
            for (int c = 0; c < 4; c++) sf[i][c] = 0.f;
#pragma unroll
        for (int ks = 0; ks < 4; ks++) {
#pragma unroll
            for (int nf4 = 0; nf4 < 4; nf4++) {
                unsigned bbf[4];
                ldm4(bbf, smem_u32(&sk[nf4 * 16 + lr][ks * 16 + lh * 8]));
                mmaf16(sf[nf4 * 2], qa[ks], bbf[0], bbf[2]);
                mmaf16(sf[nf4 * 2 + 1], qa[ks], bbf[1], bbf[3]);
            }
        }
#pragma unroll
        for (int nf = 0; nf < 8; nf++) {
            sf[nf][0] = fexp(sf[nf][0]); sf[nf][1] = fexp(sf[nf][1]);
            sf[nf][2] = fexp(sf[nf][2]); sf[nf][3] = fexp(sf[nf][3]);
            rsA += sf[nf][0] + sf[nf][1];
            rsB += sf[nf][2] + sf[nf][3];
        }
#pragma unroll
        for (int kk = 0; kk < 4; kk++) {
            unsigned pa[4];
            pa[0] = packh2(sf[2 * kk][0], sf[2 * kk][1]);
            pa[1] = packh2(sf[2 * kk][2], sf[2 * kk][3]);
            pa[2] = packh2(sf[2 * kk + 1][0], sf[2 * kk + 1][1]);
            pa[3] = packh2(sf[2 * kk + 1][2], sf[2 * kk + 1][3]);
#pragma unroll
            for (int nf4 = 0; nf4 < 4; nf4++) {
                unsigned bbf[4];
                ldm4(bbf, smem_u32(&svT[nf4 * 16 + lr][kk * 16 + lh * 8]));
                mmaf16(outacc[nf4 * 2], pa, bbf[0], bbf[2]);
                mmaf16(outacc[nf4 * 2 + 1], pa, bbf[1], bbf[3]);
            }
        }
    }
    rsA += __shfl_xor_sync(0xffffffffu, rsA, 1);
    rsA += __shfl_xor_sync(0xffffffffu, rsA, 2);
    rsB += __shfl_xor_sync(0xffffffffu, rsB, 1);
    rsB += __shfl_xor_sync(0xffffffffu, rsB, 2);

    int rA = mblk * 128 + w * 16 + (lane >> 2);
    int rB = rA + 8;
    float* wpA = g_Wpart + (size_t)((bh * 4 + chunk) * MLM + rA) * 64;
    float* wpB = g_Wpart + (size_t)((bh * 4 + chunk) * MLM + rB) * 64;
#pragma unroll
    for (int nf = 0; nf < 8; nf++) {
        int d = nf * 8 + (lane & 3) * 2;
        *(float2*)&wpA[d] = make_float2(outacc[nf][0], outacc[nf][1]);
        *(float2*)&wpB[d] = make_float2(outacc[nf][2], outacc[nf][3]);
    }
    if ((lane & 3) == 0) {
        g_Spart[(bh * 4 + chunk) * MLM + rA] = rsA;
        g_Spart[(bh * 4 + chunk) * MLM + rB] = rsB;
    }
}

__global__ void combine_w2_kernel() {
    int idx = blockIdx.x * 256 + threadIdx.x;
    int bh = idx >> 14;
    int m = (idx >> 6) & 255;
    int d = idx & 63;
    float num = 0.f, den = 0.f;
#pragma unroll
    for (int c = 0; c < 4; c++) {
        num += g_Wpart[(size_t)((bh * 4 + c) * MLM + m) * 64 + d];
        den += g_Spart[(bh * 4 + c) * MLM + m];
    }
    g_W2[(bh * MLM + m) * 64 + d] = num / den;
}

// ================= attn1 + conv on tensor cores (writes fp16 to g_A16) =================
__global__ __launch_bounds__(256) void attn1_mma(const float* __restrict__ convw) {
    extern __shared__ char smx[];
    __half (*sq)[72]  = (__half(*)[72])(smx);
    __half (*skl)[72] = (__half(*)[72])(smx + 18432);
    __half (*swT)[72] = (__half(*)[72])(smx + 27648);
    __half (*sv)[72]  = (__half(*)[72])(smx + 36864);
    float* cw = (float*)(smx + 59904);

    int tid = threadIdx.x, lane = tid & 31, w = tid >> 5;
    int ntile = blockIdx.x, bh = blockIdx.y;
    int h = bh & 7, bb2 = bh >> 3;
    int n0 = ntile * 128;
    int lr = lane & 15, lh = lane >> 4;

    if (tid < KSZ) cw[tid] = convw[h * KSZ + tid];

    const __half* qb = g_qh + ((size_t)bh * NSEQ + n0) * 64;
#pragma unroll
    for (int i = 0; i < 4; i++) {
        int idx = tid + i * 256;
        int r = idx >> 3, c = (idx & 7) * 8;
        *(uint4*)&sq[r][c] = *(const uint4*)&qb[(size_t)r * 64 + c];
    }
    const __half* vb2 = g_vh + (size_t)bh * NSEQ * 64;
#pragma unroll
    for (int i = 0; i < 5; i++) {
        int idx = tid + i * 256;
        int r = idx >> 3, c = (idx & 7) * 8;
        int gr = n0 - 16 + r;
        uint4 z = make_uint4(0u, 0u, 0u, 0u);
        if (gr >= 0 && gr < NSEQ) z = *(const uint4*)&vb2[(size_t)gr * 64 + c];
        *(uint4*)&sv[r][c] = z;
    }
    __syncthreads();

    unsigned qa[4][4];
#pragma unroll
    for (int ks = 0; ks < 4; ks++)
        ldm4(qa[ks], smem_u32(&sq[w * 16 + lr][ks * 16 + lh * 8]));

    float outacc[8][4];
#pragma unroll
    for (int i = 0; i < 8; i++)
#pragma unroll
        for (int c = 0; c < 4; c++) outacc[i][c] = 0.f;
    float rsA = 0.f, rsB = 0.f;

    const __half* klb = g_klh + (size_t)bh * MLM * 64;
    const __half* w3tb = g_W3T + (size_t)bh * 64 * 256;

    for (int lc = 0; lc < 4; lc++) {
        __syncthreads();
#pragma unroll
        for (int i = 0; i < 2; i++) {
            int idx = tid + i * 256;
            int r = idx >> 3, c = (idx & 7) * 8;
            *(uint4*)&skl[r][c] = *(const uint4*)&klb[(size_t)(lc * 64 + r) * 64 + c];
            *(uint4*)&swT[r][c] = *(const uint4*)&w3tb[(size_t)r * 256 + lc * 64 + c];
        }
        __syncthreads();
        float sf[8][4];
#pragma unroll
        for (int i = 0; i < 8; i++)
#pragma unroll
            for (int c = 0; c < 4; c++) sf[i][c] = 0.f;
#pragma unroll
        for (int ks = 0; ks < 4; ks++) {
#pragma unroll
            for (int nf4 = 0; nf4 < 4; nf4++) {
                unsigned bbf[4];
                ldm4(bbf, smem_u32(&skl[nf4 * 16 + lr][ks * 16 + lh * 8]));
                mmaf16(sf[nf4 * 2], qa[ks], bbf[0], bbf[2]);
                mmaf16(sf[nf4 * 2 + 1], qa[ks], bbf[1], bbf[3]);
            }
        }
#pragma unroll
        for (int nf = 0; nf < 8; nf++) {
            sf[nf][0] = fexp(sf[nf][0]); sf[nf][1] = fexp(sf[nf][1]);
            sf[nf][2] = fexp(sf[nf][2]); sf[nf][3] = fexp(sf[nf][3]);
            rsA += sf[nf][0] + sf[nf][1];
            rsB += sf[nf][2] + sf[nf][3];
        }
#pragma unroll
        for (int kk = 0; kk < 4; kk++) {
            unsigned pa[4];
            pa[0] = packh2(sf[2 * kk][0], sf[2 * kk][1]);
            pa[1] = packh2(sf[2 * kk][2], sf[2 * kk][3]);
            pa[2] = packh2(sf[2 * kk + 1][0], sf[2 * kk + 1][1]);
            pa[3] = packh2(sf[2 * kk + 1][2], sf[2 * kk + 1][3]);
#pragma unroll
            for (int nf4 = 0; nf4 < 4; nf4++) {
                unsigned bbf[4];
                ldm4(bbf, smem_u32(&swT[nf4 * 16 + lr][kk * 16 + lh * 8]));
                mmaf16(outacc[nf4 * 2], pa, bbf[0], bbf[2]);
                mmaf16(outacc[nf4 * 2 + 1], pa, bbf[1], bbf[3]);
            }
        }
    }
    rsA += __shfl_xor_sync(0xffffffffu, rsA, 1);
    rsA += __shfl_xor_sync(0xffffffffu, rsA, 2);
    rsB += __shfl_xor_sync(0xffffffffu, rsB, 1);
    rsB += __shfl_xor_sync(0xffffffffu, rsB, 2);
    float invA = 1.f / rsA, invB = 1.f / rsB;

    int lrA = w * 16 + (lane >> 2);
#pragma unroll
    for (int nf = 0; nf < 8; nf++) {
        int d = nf * 8 + (lane & 3) * 2;
        float a0 = 0.f, a1 = 0.f, b0 = 0.f, b1 = 0.f;
#pragma unroll
        for (int t = 0; t < KSZ; t++) {
            float wv = cw[t];
            float2 fA = __half22float2(*(__half2*)&sv[lrA + t][d]);
            float2 fB = __half22float2(*(__half2*)&sv[lrA + 8 + t][d]);
            a0 = fmaf(wv, fA.x, a0); a1 = fmaf(wv, fA.y, a1);
            b0 = fmaf(wv, fB.x, b0); b1 = fmaf(wv, fB.y, b1);
        }
        outacc[nf][0] = outacc[nf][0] * invA + a0;
        outacc[nf][1] = outacc[nf][1] * invA + a1;
        outacc[nf][2] = outacc[nf][2] * invB + b0;
        outacc[nf][3] = outacc[nf][3] * invB + b1;
    }

    int nA = n0 + lrA, nB = nA + 8;
    __half* oA = g_A16 + (size_t)(bb2 * NSEQ + nA) * 512 + h * 64;
    __half* oB = g_A16 + (size_t)(bb2 * NSEQ + nB) * 512 + h * 64;
#pragma unroll
    for (int nf = 0; nf < 8; nf++) {
        int d = nf * 8 + (lane & 3) * 2;
        *(__half2*)&oA[d] = __floats2half2_rn(outacc[nf][0], outacc[nf][1]);
        *(__half2*)&oB[d] = __floats2half2_rn(outacc[nf][2], outacc[nf][3]);
    }
}

// ================= host launcher =================
extern "C" void kernel_launch(void* const* d_in, const int* in_sizes, int n_in,
                              void* d_out, int out_size) {
    const float* x     = (const float*)d_in[0];
    const float* ln_g  = (const float*)d_in[1];
    const float* ln_b  = (const float*)d_in[2];
    const float* W_qkv = (const float*)d_in[3];
    const float* W_out = (const float*)d_in[4];
    const float* b_out = (const float*)d_in[5];
    const float* convw = (const float*)d_in[6];
    float* out = (float*)d_out;

    cudaFuncSetAttribute(attn1_mma, cudaFuncAttributeMaxDynamicSharedMemorySize, 60416);
    cudaFuncSetAttribute(gemm_lm_kernel, cudaFuncAttributeMaxDynamicSharedMemorySize, 81920);
    cudaFuncSetAttribute(gemm16_kernel, cudaFuncAttributeMaxDynamicSharedMemorySize, 73728);
    cudaFuncSetAttribute(attn2_kernel, cudaFuncAttributeMaxDynamicSharedMemorySize, 65536);

    __nv_bfloat16 *bqh, *bql;
    cudaGetSymbolAddress((void**)&bqh, g_Bqh);
    cudaGetSymbolAddress((void**)&bql, g_Bql);
    __half *b16q, *b16o;
    cudaGetSymbolAddress((void**)&b16q, g_B16q);
    cudaGetSymbolAddress((void**)&b16o, g_B16o);
    float *xnlmp;
    cudaGetSymbolAddress((void**)&xnlmp, g_xnlm);

    reset_kernel<<<1, 1>>>();
    ln_kernel<<<Bb * NSEQ, 128>>>(x, ln_g, ln_b);  // writes g_xn (fp32) + g_A16 (fp16)

    convW16_kernel<<<dim3(48, 16), 1024>>>(W_qkv, 1536, b16q);
    convW16_kernel<<<dim3(16, 16), 1024>>>(W_out, 512, b16o);

    // qkv GEMM: single-pass fp16
    gemm16_kernel<<<dim3(12, 128), 256, 73728>>>(b16q, 0, nullptr, nullptr);

    // landmark path: accurate small GEMM
    xnlm_kernel<<<1024, 256>>>();
    convA_kernel<<<256, 256>>>(xnlmp);
    convW_kernel<<<dim3(48, 16), 1024>>>(W_qkv, 1536, bqh, bql);
    gemm_lm_kernel<<<dim3(8, 4), 256, 81920>>>(bqh, bql);

    attn2_kernel<<<dim3(4, 16), 256, 65536>>>();
    colmax_kernel<<<16, 256>>>();
    z0_kernel<<<4096, 256>>>();

    // all 24 Newton-Schulz GEMM steps in one persistent kernel
    pinv_persist<<<dim3(4, 2, 16), 256>>>();

    flash_w2_mma<<<dim3(4, 2, 16), 256>>>();
    combine_w2_kernel<<<1024, 256>>>();
    gemm_bh_kernel<<<dim3(1, 4, 16), 256>>>(7, 4, 6, 64, 0.f, 1.f, 1.f);  // W3 = Za @ W2
    w3t_kernel<<<1024, 256>>>();
    attn1_mma<<<dim3(64, 16), 256, 60416>>>(convw);  // writes fp16 into g_A16

    // out GEMM: single-pass fp16
    gemm16_kernel<<<dim3(4, 128), 256, 73728>>>(b16o, 1, b_out, out);
}

// round 13
// speedup vs baseline: 1.3367x; 1.0602x over previous
#include <cuda_runtime.h>
#include <cuda_bf16.h>
#include <cuda_fp16.h>

#define Bb    2
#define NSEQ  8192
#define DIMV  512
#define NH    8
#define BHn   16
#define DHd   64
#define MLM   256
#define LGRP  32
#define KSZ   33
#define PADc  16
#define SCALE 0.125f

// ================= static device scratch =================
__device__ float g_xn[(size_t)Bb * NSEQ * DIMV];
__device__ float g_xnlm[512 * 512];
__device__ float g_ql[BHn * MLM * DHd];
__device__ float g_kl[BHn * MLM * DHd];
__device__ float g_attn2[BHn * MLM * MLM];
__device__ float g_Y[BHn * MLM * MLM];
__device__ float g_P[BHn * MLM * MLM];
__device__ float g_Qm[BHn * MLM * MLM];
__device__ float g_Za[BHn * MLM * MLM];
__device__ float g_Zb[BHn * MLM * MLM];
__device__ float g_W2[BHn * MLM * DHd];
__device__ float g_W3[BHn * MLM * DHd];
__device__ float g_Wpart[(size_t)BHn * 4 * MLM * DHd];
__device__ float g_Spart[BHn * 4 * MLM];
__device__ int   g_maxc_bits;
__device__ unsigned g_bar;

// bf16 hi/lo buffers (landmark GEMM)
__device__ __nv_bfloat16 g_Ahi[512 * 512];
__device__ __nv_bfloat16 g_Alo[512 * 512];
__device__ __nv_bfloat16 g_Bqh[1536 * 512];
__device__ __nv_bfloat16 g_Bql[1536 * 512];

// fp16 buffers
__device__ __half g_A16[(size_t)Bb * NSEQ * DIMV];
__device__ __half g_B16q[1536 * 512];
__device__ __half g_B16o[512 * 512];
__device__ __half g_qh[(size_t)BHn * NSEQ * DHd];
__device__ __half g_kh[(size_t)BHn * NSEQ * DHd];
__device__ __half g_vh[(size_t)BHn * NSEQ * DHd];
__device__ __half g_qlh[BHn * MLM * DHd];
__device__ __half g_klh[BHn * MLM * DHd];
__device__ __half g_W3T[BHn * DHd * MLM];

__global__ void reset_kernel() { g_maxc_bits = 0; g_bar = 0u; }

// ================= mma.sync helpers =================
__device__ __forceinline__ unsigned smem_u32(const void* p) {
    unsigned a;
    asm("{ .reg .u64 t; cvta.to.shared.u64 t, %1; cvt.u32.u64 %0, t; }" : "=r"(a) : "l"(p));
    return a;
}
__device__ __forceinline__ void ldm4(unsigned* r, unsigned addr) {
    asm volatile("ldmatrix.sync.aligned.m8n8.x4.shared.b16 {%0,%1,%2,%3}, [%4];"
        : "=r"(r[0]), "=r"(r[1]), "=r"(r[2]), "=r"(r[3]) : "r"(addr));
}
__device__ __forceinline__ void mma16816(float* c, const unsigned* a, unsigned b0, unsigned b1) {
    asm volatile("mma.sync.aligned.m16n8k16.row.col.f32.bf16.bf16.f32 "
        "{%0,%1,%2,%3}, {%4,%5,%6,%7}, {%8,%9}, {%0,%1,%2,%3};"
        : "+f"(c[0]), "+f"(c[1]), "+f"(c[2]), "+f"(c[3])
        : "r"(a[0]), "r"(a[1]), "r"(a[2]), "r"(a[3]), "r"(b0), "r"(b1));
}
__device__ __forceinline__ void mmaf16(float* c, const unsigned* a, unsigned b0, unsigned b1) {
    asm volatile("mma.sync.aligned.m16n8k16.row.col.f32.f16.f16.f32 "
        "{%0,%1,%2,%3}, {%4,%5,%6,%7}, {%8,%9}, {%0,%1,%2,%3};"
        : "+f"(c[0]), "+f"(c[1]), "+f"(c[2]), "+f"(c[3])
        : "r"(a[0]), "r"(a[1]), "r"(a[2]), "r"(a[3]), "r"(b0), "r"(b1));
}
__device__ __forceinline__ void cpasync16(unsigned dst, const void* src) {
    asm volatile("cp.async.cg.shared.global [%0], [%1], 16;" :: "r"(dst), "l"(src));
}
#define CP_COMMIT() asm volatile("cp.async.commit_group;" ::: "memory")
__device__ __forceinline__ unsigned packh2(float a, float b) {
    __half2 h = __floats2half2_rn(a, b);
    return *(unsigned*)&h;
}
__device__ __forceinline__ float fexp(float x) {
    float t = x * 1.44269504f;
    float r = rintf(t);
    float f = t - r;
    float p = 1.33336e-3f;
    p = fmaf(p, f, 9.61813e-3f);
    p = fmaf(p, f, 5.55041e-2f);
    p = fmaf(p, f, 2.40226507e-1f);
    p = fmaf(p, f, 6.93147181e-1f);
    p = fmaf(p, f, 1.0f);
    int e = (int)r;
    return p * __int_as_float((e + 127) << 23);
}

// ================= layernorm (writes fp32 + fp16) =================
__global__ __launch_bounds__(128) void ln_kernel(const float* __restrict__ x,
                                                 const float* __restrict__ gam,
                                                 const float* __restrict__ bet) {
    int row = blockIdx.x;
    int tid = threadIdx.x;
    float4 v = ((const float4*)x)[(size_t)row * 128 + tid];
    float s1 = v.x + v.y + v.z + v.w;
    float s2 = v.x * v.x + v.y * v.y + v.z * v.z + v.w * v.w;
#pragma unroll
    for (int o = 16; o; o >>= 1) {
        s1 += __shfl_xor_sync(0xffffffffu, s1, o);
        s2 += __shfl_xor_sync(0xffffffffu, s2, o);
    }
    __shared__ float r1[4], r2[4];
    int w = tid >> 5;
    if ((tid & 31) == 0) { r1[w] = s1; r2[w] = s2; }
    __syncthreads();
    s1 = r1[0] + r1[1] + r1[2] + r1[3];
    s2 = r2[0] + r2[1] + r2[2] + r2[3];
    float mean = s1 * (1.f / 512.f);
    float var  = s2 * (1.f / 512.f) - mean * mean;
    float rstd = rsqrtf(var + 1e-5f);
    float4 g4 = ((const float4*)gam)[tid];
    float4 b4 = ((const float4*)bet)[tid];
    float4 o;
    o.x = (v.x - mean) * rstd * g4.x + b4.x;
    o.y = (v.y - mean) * rstd * g4.y + b4.y;
    o.z = (v.z - mean) * rstd * g4.z + b4.z;
    o.w = (v.w - mean) * rstd * g4.w + b4.w;
    ((float4*)g_xn)[(size_t)row * 128 + tid] = o;
    __half2* ph = (__half2*)(g_A16 + (size_t)row * 512 + tid * 4);
    ph[0] = __floats2half2_rn(o.x, o.y);
    ph[1] = __floats2half2_rn(o.z, o.w);
}

// ================= group means of xn (landmark pre-image) =================
__global__ void xnlm_kernel() {
    int idx = blockIdx.x * 256 + threadIdx.x;
    int row = idx >> 9;
    int d = idx & 511;
    int b = row >> 8, m = row & 255;
    const float* p = g_xn + ((size_t)(b * NSEQ) + m * LGRP) * DIMV + d;
    float s = 0.f;
#pragma unroll
    for (int i = 0; i < LGRP; i++) s += p[(size_t)i * DIMV];
    g_xnlm[idx] = s * (1.f / LGRP);
}

// ================= converters =================
__global__ __launch_bounds__(256) void convA_kernel(const float* __restrict__ src) {
    size_t i4 = ((size_t)blockIdx.x * 256 + threadIdx.x) * 4;
    float4 v = *(const float4*)(src + i4);
    __nv_bfloat16 h0 = __float2bfloat16(v.x), h1 = __float2bfloat16(v.y);
    __nv_bfloat16 h2 = __float2bfloat16(v.z), h3 = __float2bfloat16(v.w);
    __nv_bfloat16 l0 = __float2bfloat16(v.x - __bfloat162float(h0));
    __nv_bfloat16 l1 = __float2bfloat16(v.y - __bfloat162float(h1));
    __nv_bfloat16 l2 = __float2bfloat16(v.z - __bfloat162float(h2));
    __nv_bfloat16 l3 = __float2bfloat16(v.w - __bfloat162float(h3));
    __nv_bfloat162* ph = (__nv_bfloat162*)(g_Ahi + i4);
    __nv_bfloat162* pl = (__nv_bfloat162*)(g_Alo + i4);
    ph[0] = __nv_bfloat162(h0, h1); ph[1] = __nv_bfloat162(h2, h3);
    pl[0] = __nv_bfloat162(l0, l1); pl[1] = __nv_bfloat162(l2, l3);
}

__global__ __launch_bounds__(1024) void convW_kernel(const float* __restrict__ W, int N,
                                                     __nv_bfloat16* __restrict__ BThi,
                                                     __nv_bfloat16* __restrict__ BTlo) {
    __shared__ float sh[32][33];
    int n0 = blockIdx.x * 32, k0 = blockIdx.y * 32;
    int tx = threadIdx.x & 31, ty = threadIdx.x >> 5;
    sh[ty][tx] = W[(size_t)(k0 + ty) * N + n0 + tx];
    __syncthreads();
    float x = sh[tx][ty];
    __nv_bfloat16 h = __float2bfloat16(x);
    __nv_bfloat16 l = __float2bfloat16(x - __bfloat162float(h));
    BThi[(size_t)(n0 + ty) * 512 + k0 + tx] = h;
    BTlo[(size_t)(n0 + ty) * 512 + k0 + tx] = l;
}

__global__ __launch_bounds__(1024) void convW16_kernel(const float* __restrict__ W, int N,
                                                       __half* __restrict__ BT) {
    __shared__ float sh[32][33];
    int n0 = blockIdx.x * 32, k0 = blockIdx.y * 32;
    int tx = threadIdx.x & 31, ty = threadIdx.x >> 5;
    sh[ty][tx] = W[(size_t)(k0 + ty) * N + n0 + tx];
    __syncthreads();
    BT[(size_t)(n0 + ty) * 512 + k0 + tx] = __float2half(sh[tx][ty]);
}

// W3 -> W3T fp16 [bh][d][m]
__global__ void w3t_kernel() {
    int idx = blockIdx.x * 256 + threadIdx.x;
    int bh = idx >> 14;
    int m = (idx >> 6) & 255;
    int d = idx & 63;
    float v = g_W3[(bh * 256 + m) * 64 + d];
    g_W3T[((size_t)bh * 64 + d) * 256 + m] = __float2half(v);
}

// ================= fp16 single-pass dense GEMM (cp.async double-buffered) =================
__global__ __launch_bounds__(256) void gemm16_kernel(
    const __half* __restrict__ gBbase, int mode,
    const float* __restrict__ bout, float* __restrict__ outp) {
    extern __shared__ char smdyn[];
    unsigned sbase = smem_u32(smdyn);
    int tid = threadIdx.x, lane = tid & 31, wid = tid >> 5;
    int wm = wid & 3, wn = wid >> 2;
    int mBase = blockIdx.y * 128, nBase = blockIdx.x * 128;
    int lr = lane & 15, lh = lane >> 4;

    const __half* gA = g_A16 + (size_t)mBase * 512;
    const __half* gB = gBbase + (size_t)nBase * 512;

    float acc[2][8][4];
#pragma unroll
    for (int i = 0; i < 2; i++)
#pragma unroll
        for (int j = 0; j < 8; j++)
#pragma unroll
            for (int c = 0; c < 4; c++) acc[i][j][c] = 0.f;

    int r_ld = tid >> 1;
    int q2 = (tid & 1) * 4;

    auto load_stage = [&](int ch, unsigned st) {
#pragma unroll
        for (int u = 0; u < 4; u++) {
            unsigned soff = (unsigned)r_ld * 144u + (q2 + u) * 16u;
            size_t goff = (size_t)r_ld * 512 + ch * 64 + (q2 + u) * 8;
            cpasync16(sbase + st + soff, gA + goff);
            cpasync16(sbase + st + 18432u + soff, gB + goff);
        }
        CP_COMMIT();
    };

    load_stage(0, 0u);

    for (int ch = 0; ch < 8; ch++) {
        unsigned st = (unsigned)(ch & 1) * 36864u;
        if (ch + 1 < 8) {
            load_stage(ch + 1, (unsigned)((ch + 1) & 1) * 36864u);
            asm volatile("cp.async.wait_group 1;" ::: "memory");
        } else {
            asm volatile("cp.async.wait_group 0;" ::: "memory");
        }
        __syncthreads();

        unsigned aA = sbase + st;
        unsigned aB = aA + 18432u;
#pragma unroll
        for (int ks = 0; ks < 4; ks++) {
            unsigned kc2 = (unsigned)(ks * 16 + lh * 8) * 2u;
            unsigned ah[2][4];
#pragma unroll
            for (int mi = 0; mi < 2; mi++) {
                unsigned rowA = (unsigned)(wm * 32 + mi * 16 + lr) * 144u;
                ldm4(ah[mi], aA + rowA + kc2);
            }
#pragma unroll
            for (int nt = 0; nt < 4; nt++) {
                unsigned rowB = (unsigned)(wn * 64 + nt * 16 + lr) * 144u;
                unsigned bf[4];
                ldm4(bf, aB + rowB + kc2);
#pragma unroll
                for (int mi = 0; mi < 2; mi++) {
#pragma unroll
                    for (int ns = 0; ns < 2; ns++)
                        mmaf16(acc[mi][nt * 2 + ns], ah[mi], bf[ns], bf[ns + 2]);
                }
            }
        }
        __syncthreads();
    }

    int r0 = mBase + wm * 32 + (lane >> 2);
    if (mode == 0) {
        int sec = nBase >> 9;
        float sc = (sec == 0) ? SCALE : 1.f;
        __half* hdst = (sec == 0) ? g_qh : ((sec == 1) ? g_kh : g_vh);
        int h = ((nBase + wn * 64) >> 6) & 7;
#pragma unroll
        for (int mi = 0; mi < 2; mi++) {
#pragma unroll
            for (int jn = 0; jn < 8; jn++) {
                int d = jn * 8 + (lane & 3) * 2;
#pragma unroll
                for (int half = 0; half < 2; half++) {
                    int gr = r0 + mi * 16 + half * 8;
                    int bb = gr >> 13, n = gr & 8191;
                    size_t off = ((size_t)(bb * 8 + h) * NSEQ + n) * 64 + d;
                    *(__half2*)&hdst[off] = __floats2half2_rn(acc[mi][jn][half * 2] * sc,
                                                              acc[mi][jn][half * 2 + 1] * sc);
                }
            }
        }
    } else {
#pragma unroll
        for (int mi = 0; mi < 2; mi++) {
#pragma unroll
            for (int jn = 0; jn < 8; jn++) {
                int gc = nBase + wn * 64 + jn * 8 + (lane & 3) * 2;
#pragma unroll
                for (int half = 0; half < 2; half++) {
                    int gr = r0 + mi * 16 + half * 8;
                    float2 bo = *(const float2*)&bout[gc];
                    float2 xv = *(const float2*)&g_xn[(size_t)gr * 512 + gc];
                    float2 o = make_float2(acc[mi][jn][half * 2] + bo.x + xv.x,
                                           acc[mi][jn][half * 2 + 1] + bo.y + xv.y);
                    *(float2*)&outp[(size_t)gr * 512 + gc] = o;
                }
            }
        }
    }
}

// ================= bf16 split landmark GEMM (M=512, N=1024) =================
__global__ __launch_bounds__(256) void gemm_lm_kernel(
    const __nv_bfloat16* __restrict__ BThi, const __nv_bfloat16* __restrict__ BTlo) {
    extern __shared__ char smdyn[];
    unsigned sbase = smem_u32(smdyn);
    int tid = threadIdx.x, lane = tid & 31, wid = tid >> 5;
    int wm = wid & 3, wn = wid >> 2;
    int mBase = blockIdx.y * 128, nBase = blockIdx.x * 128;
    int lr = lane & 15, lh = lane >> 4;

    const __nv_bfloat16* gsrc[4];
    gsrc[0] = g_Ahi + (size_t)mBase * 512;
    gsrc[1] = g_Alo + (size_t)mBase * 512;
    gsrc[2] = BThi + (size_t)nBase * 512;
    gsrc[3] = BTlo + (size_t)nBase * 512;

    float acc[2][8][4];
#pragma unroll
    for (int i = 0; i < 2; i++)
#pragma unroll
        for (int j = 0; j < 8; j++)
#pragma unroll
            for (int c = 0; c < 4; c++) acc[i][j][c] = 0.f;

    int r_ld0 = tid >> 2, q_ld = tid & 3;
    unsigned so0 = (unsigned)r_ld0 * 80u + q_ld * 16u;
    unsigned so1 = (unsigned)(r_ld0 + 64) * 80u + q_ld * 16u;

    {
        size_t go0 = (size_t)r_ld0 * 512 + q_ld * 8;
        size_t go1 = (size_t)(r_ld0 + 64) * 512 + q_ld * 8;
#pragma unroll
        for (int a = 0; a < 4; a++) {
            cpasync16(sbase + a * 10240u + so0, gsrc[a] + go0);
            cpasync16(sbase + a * 10240u + so1, gsrc[a] + go1);
        }
        CP_COMMIT();
    }

    for (int ch = 0; ch < 16; ch++) {
        unsigned st = (unsigned)(ch & 1) * 40960u;
        if (ch + 1 < 16) {
            unsigned stn = (unsigned)((ch + 1) & 1) * 40960u;
            size_t go0 = (size_t)r_ld0 * 512 + (ch + 1) * 32 + q_ld * 8;
            size_t go1 = (size_t)(r_ld0 + 64) * 512 + (ch + 1) * 32 + q_ld * 8;
#pragma unroll
            for (int a = 0; a < 4; a++) {
                cpasync16(sbase + stn + a * 10240u + so0, gsrc[a] + go0);
                cpasync16(sbase + stn + a * 10240u + so1, gsrc[a] + go1);
            }
            CP_COMMIT();
            asm volatile("cp.async.wait_group 1;" ::: "memory");
        } else {
            asm volatile("cp.async.wait_group 0;" ::: "memory");
        }
        __syncthreads();

        unsigned aAh = sbase + st;
        unsigned aAl = aAh + 10240u;
        unsigned aBh = aAh + 20480u;
        unsigned aBl = aAh + 30720u;
#pragma unroll
        for (int ks = 0; ks < 2; ks++) {
            unsigned kc2 = (unsigned)(ks * 16 + lh * 8) * 2u;
            unsigned ah[2][4], al[2][4];
#pragma unroll
            for (int mi = 0; mi < 2; mi++) {
                unsigned rowA = (unsigned)(wm * 32 + mi * 16 + lr) * 80u;
                ldm4(ah[mi], aAh + rowA + kc2);
                ldm4(al[mi], aAl + rowA + kc2);
            }
#pragma unroll
            for (int nt = 0; nt < 4; nt++) {
                unsigned rowB = (unsigned)(wn * 64 + nt * 16 + lr) * 80u;
                unsigned bh[4], bl[4];
                ldm4(bh, aBh + rowB + kc2);
                ldm4(bl, aBl + rowB + kc2);
#pragma unroll
                for (int mi = 0; mi < 2; mi++) {
#pragma unroll
                    for (int ns = 0; ns < 2; ns++) {
                        float* cc = acc[mi][nt * 2 + ns];
                        mma16816(cc, ah[mi], bh[ns], bh[ns + 2]);
                        mma16816(cc, ah[mi], bl[ns], bl[ns + 2]);
                        mma16816(cc, al[mi], bh[ns], bh[ns + 2]);
                    }
                }
            }
        }
        __syncthreads();
    }

    int r0 = mBase + wm * 32 + (lane >> 2);
    int sec = nBase >> 9;
    float sc = (sec == 0) ? SCALE : 1.f;
    float* dst = (sec == 0) ? g_ql : g_kl;
    __half* hdst = (sec == 0) ? g_qlh : g_klh;
    int h = ((nBase + wn * 64) >> 6) & 7;
#pragma unroll
    for (int mi = 0; mi < 2; mi++) {
#pragma unroll
        for (int jn = 0; jn < 8; jn++) {
            int d = jn * 8 + (lane & 3) * 2;
#pragma unroll
            for (int half = 0; half < 2; half++) {
                int gr = r0 + mi * 16 + half * 8;
                int bb = gr >> 8, m = gr & 255;
                float2 o = make_float2(acc[mi][jn][half * 2] * sc,
                                       acc[mi][jn][half * 2 + 1] * sc);
                size_t off = ((size_t)(bb * 8 + h) * MLM + m) * 64 + d;
                *(float2*)&dst[off] = o;
                *(__half2*)&hdst[off] = __floats2half2_rn(o.x, o.y);
            }
        }
    }
}

// ================= attn2 = softmax(q_l k_l^T), 64 CTAs =================
__global__ __launch_bounds__(256) void attn2_kernel() {
    extern __shared__ float sklf[];
    int rt = blockIdx.x, bh = blockIdx.y;
    int tid = threadIdx.x;
    int row = rt * 64 + (tid >> 2);
    int cg = tid & 3;

    const float4* klsrc = (const float4*)(g_kl + (size_t)bh * MLM * 64);
    float4* kld = (float4*)sklf;
#pragma unroll
    for (int i = 0; i < 16; i++) kld[tid + i * 256] = klsrc[tid + i * 256];

    float4 q[16];
    const float4* qp = (const float4*)(g_ql + (size_t)(bh * MLM + row) * 64);
#pragma unroll
    for (int i = 0; i < 16; i++) q[i] = qp[i];
    __syncthreads();

    float p[64];
    float sum = 0.f;
    const float4* klb = (const float4*)sklf + cg * 64 * 16;
    for (int j = 0; j < 64; j++) {
        const float4* kr = klb + j * 16;
        float s = 0.f;
#pragma unroll
        for (int d = 0; d < 16; d++) {
            float4 a = q[d], b = kr[d];
            s += a.x * b.x + a.y * b.y + a.z * b.z + a.w * b.w;
        }
        p[j] = __expf(s);
        sum += p[j];
    }
    sum += __shfl_xor_sync(0xffffffffu, sum, 1);
    sum += __shfl_xor_sync(0xffffffffu, sum, 2);
    float inv = 1.f / sum;
    float* arow = g_attn2 + (size_t)bh * 65536 + (size_t)row * 256 + cg * 64;
#pragma unroll
    for (int j = 0; j < 64; j += 4)
        *(float4*)&arow[j] = make_float4(p[j] * inv, p[j + 1] * inv,
                                         p[j + 2] * inv, p[j + 3] * inv);
}

// ================= max column-sum of attn2 =================
__global__ __launch_bounds__(256) void colmax_kernel() {
    int bh = blockIdx.x;
    int j = threadIdx.x;
    const float* a = g_attn2 + (size_t)bh * 65536;
    float s = 0.f;
    for (int m2 = 0; m2 < 256; m2++) s += a[m2 * 256 + j];
    __shared__ float red[256];
    red[j] = s;
    __syncthreads();
    for (int o = 128; o; o >>= 1) {
        if (j < o) red[j] = fmaxf(red[j], red[j + o]);
        __syncthreads();
    }
    if (j == 0) atomicMax(&g_maxc_bits, __float_as_int(red[0]));
}

__global__ void z0_kernel() {
    int idx = blockIdx.x * 256 + threadIdx.x;
    int bh = idx >> 16;
    int i = (idx >> 8) & 255;
    int j = idx & 255;
    float scale = 1.f / __int_as_float(g_maxc_bits);
    g_Za[idx] = g_attn2[(bh << 16) + (j << 8) + i] * scale;
}

// ================= buffer selector =================
__device__ __forceinline__ float* pickBuf(int id) {
    switch (id) {
        case 0: return g_attn2;
        case 1: return g_Y;
        case 2: return g_P;
        case 3: return g_Qm;
        case 4: return g_Za;
        case 5: return g_Zb;
        case 6: return g_W2;
        default: return g_W3;
    }
}

// ================= persistent pinv: all 24 GEMM steps in one kernel =================
struct PinvSmem {
    __nv_bfloat16 Ah[128][40];
    __nv_bfloat16 Al[128][40];
    __nv_bfloat16 Bh[64][40];
    __nv_bfloat16 Bl[64][40];
};

__device__ __forceinline__ void gbarrier(int step) {
    __syncthreads();
    if (threadIdx.x == 0) {
        __threadfence();
        atomicAdd(&g_bar, 1u);
        unsigned target = 128u * (unsigned)step;
        while (*(volatile unsigned*)&g_bar < target) { }
    }
    __syncthreads();
}

__device__ void pinv_gemm(PinvSmem& S, int cId, int aId, int bId,
                          float beta, float sgn, float alpha, bool full,
                          int mBase, int nBase, int bh) {
    const float* A = pickBuf(aId) + (size_t)bh * 65536;
    const float* B = pickBuf(bId) + (size_t)bh * 65536;
    float*       C = pickBuf(cId) + (size_t)bh * 65536;

    int tid = threadIdx.x, lane = tid & 31, w = tid >> 5;
    int wm = w & 3, wn = w >> 2;
    int lr = lane & 15, lh = lane >> 4;

    float acc[2][4][4];
#pragma unroll
    for (int i = 0; i < 2; i++)
#pragma unroll
        for (int j = 0; j < 4; j++)
#pragma unroll
            for (int c = 0; c < 4; c++) acc[i][j][c] = 0.f;

    for (int ch = 0; ch < 8; ch++) {
        if (ch) __syncthreads();
#pragma unroll
        for (int i = 0; i < 4; i++) {
            int idx = tid + i * 256;
            int r = idx >> 3, c4 = (idx & 7) * 4;
            float4 v = __ldcg((const float4*)&A[(size_t)(mBase + r) * 256 + ch * 32 + c4]);
            __nv_bfloat16 h0 = __float2bfloat16(v.x), h1 = __float2bfloat16(v.y);
            __nv_bfloat16 h2 = __float2bfloat16(v.z), h3 = __float2bfloat16(v.w);
            S.Ah[r][c4 + 0] = h0; S.Ah[r][c4 + 1] = h1;
            S.Ah[r][c4 + 2] = h2; S.Ah[r][c4 + 3] = h3;
            if (full) {
                S.Al[r][c4 + 0] = __float2bfloat16(v.x - __bfloat162float(h0));
                S.Al[r][c4 + 1] = __float2bfloat16(v.y - __bfloat162float(h1));
                S.Al[r][c4 + 2] = __float2bfloat16(v.z - __bfloat162float(h2));
                S.Al[r][c4 + 3] = __float2bfloat16(v.w - __bfloat162float(h3));
            }
        }
#pragma unroll
        for (int kl = 0; kl < 4; kl++) {
            int gk = ch * 32 + w * 4 + kl;
#pragma unroll
            for (int nh = 0; nh < 2; nh++) {
                int n = nh * 32 + lane;
                float v = __ldcg(&B[(size_t)gk * 256 + nBase + n]);
                v = sgn * v + ((gk == nBase + n) ? beta : 0.f);
                __nv_bfloat16 h = __float2bfloat16(v);
                S.Bh[n][w * 4 + kl] = h;
                if (full) S.Bl[n][w * 4 + kl] = __float2bfloat16(v - __bfloat162float(h));
            }
        }
        __syncthreads();
#pragma unroll
        for (int ks = 0; ks < 2; ks++) {
            int kc = ks * 16 + lh * 8;
            unsigned ah[2][4], al[2][4];
#pragma unroll
            for (int mi = 0; mi < 2; mi++) {
                int rowA = wm * 32 + mi * 16 + lr;
                ldm4(ah[mi], smem_u32(&S.Ah[rowA][kc]));
                if (full) ldm4(al[mi], smem_u32(&S.Al[rowA][kc]));
            }
#pragma unroll
            for (int nt = 0; nt < 2; nt++) {
                int rowB = wn * 32 + nt * 16 + lr;
                unsigned bhf[4], blf[4];
                ldm4(bhf, smem_u32(&S.Bh[rowB][kc]));
                if (full) ldm4(blf, smem_u32(&S.Bl[rowB][kc]));
#pragma unroll
                for (int mi = 0; mi < 2; mi++) {
#pragma unroll
                    for (int ns = 0; ns < 2; ns++) {
                        float* cc = acc[mi][nt * 2 + ns];
                        mma16816(cc, ah[mi], bhf[ns], bhf[ns + 2]);
                        if (full) {
                            mma16816(cc, ah[mi], blf[ns], blf[ns + 2]);
                            mma16816(cc, al[mi], bhf[ns], bhf[ns + 2]);
                        }
                    }
                }
            }
        }
    }
#pragma unroll
    for (int mi = 0; mi < 2; mi++) {
#pragma unroll
        for (int jn = 0; jn < 4; jn++) {
            int gc = nBase + wn * 32 + jn * 8 + (lane & 3) * 2;
#pragma unroll
            for (int half = 0; half < 2; half++) {
                int gr = mBase + wm * 32 + mi * 16 + (lane >> 2) + half * 8;
                float2 o = make_float2(acc[mi][jn][half * 2] * alpha,
                                       acc[mi][jn][half * 2 + 1] * alpha);
                *(float2*)&C[(size_t)gr * 256 + gc] = o;
            }
        }
    }
}

__global__ __launch_bounds__(256) void pinv_persist() {
    __shared__ PinvSmem S;
    int bh = blockIdx.z;
    int mBase = blockIdx.y * 128, nBase = blockIdx.x * 64;
    int step = 0;
    for (int it = 0; it < 6; it++) {
        bool full = (it == 5);
        int zc = 4 + (it & 1), zn = 5 - (it & 1);
        pinv_gemm(S, 1, 0, zc, 0.f, 1.f, 1.f, full, mBase, nBase, bh);
        gbarrier(++step);
        pinv_gemm(S, 2, 1, 1, 7.f, -1.f, 1.f, full, mBase, nBase, bh);
        gbarrier(++step);
        pinv_gemm(S, 3, 1, 2, 15.f, -1.f, 1.f, full, mBase, nBase, bh);
        gbarrier(++step);
        pinv_gemm(S, zn, zc, 3, 13.f, -1.f, 0.25f, full, mBase, nBase, bh);
        gbarrier(++step);
    }
}

// ================= batched per-bh GEMM (scalar, kept for W3) =================
__global__ __launch_bounds__(256) void gemm_bh_kernel(int cId, int aId, int bId, int Nn,
                                                      float beta, float sgn, float alpha) {
    int bh = blockIdx.z, mt = blockIdx.y, nt = blockIdx.x;
    const float* A  = pickBuf(aId) + (size_t)bh * 65536;
    const float* Bp = pickBuf(bId) + (size_t)bh * 256 * Nn;
    float*       C  = pickBuf(cId) + (size_t)bh * 256 * Nn;
    __shared__ float As[16][64];
    __shared__ float Bs[16][64];
    int tid = threadIdx.x;
    int ar = tid >> 2, ac = (tid & 3) * 4;
    int br = tid >> 4, bc = (tid & 15) * 4;
    int ty = tid >> 4, tx = tid & 15;
    float acc[4][4];
#pragma unroll
    for (int i = 0; i < 4; i++)
#pragma unroll
        for (int j = 0; j < 4; j++) acc[i][j] = 0.f;

    for (int k0 = 0; k0 < 256; k0 += 16) {
        float4 av = *(const float4*)&A[(size_t)(mt * 64 + ar) * 256 + k0 + ac];
        As[ac + 0][ar] = av.x; As[ac + 1][ar] = av.y;
        As[ac + 2][ar] = av.z; As[ac + 3][ar] = av.w;
        int gk = k0 + br;
        int gc = nt * 64 + bc;
        float4 bv = *(const float4*)&Bp[(size_t)gk * Nn + gc];
        bv.x = sgn * bv.x + (gk == gc + 0 ? beta : 0.f);
        bv.y = sgn * bv.y + (gk == gc + 1 ? beta : 0.f);
        bv.z = sgn * bv.z + (gk == gc + 2 ? beta : 0.f);
        bv.w = sgn * bv.w + (gk == gc + 3 ? beta : 0.f);
        *(float4*)&Bs[br][bc] = bv;
        __syncthreads();
#pragma unroll
        for (int kk = 0; kk < 16; kk++) {
            float4 a4 = *(const float4*)&As[kk][ty * 4];
            float4 b4 = *(const float4*)&Bs[kk][tx * 4];
            acc[0][0] += a4.x * b4.x; acc[0][1] += a4.x * b4.y; acc[0][2] += a4.x * b4.z; acc[0][3] += a4.x * b4.w;
            acc[1][0] += a4.y * b4.x; acc[1][1] += a4.y * b4.y; acc[1][2] += a4.y * b4.z; acc[1][3] += a4.y * b4.w;
            acc[2][0] += a4.z * b4.x; acc[2][1] += a4.z * b4.y; acc[2][2] += a4.z * b4.z; acc[2][3] += a4.z * b4.w;
            acc[3][0] += a4.w * b4.x; acc[3][1] += a4.w * b4.y; acc[3][2] += a4.w * b4.z; acc[3][3] += a4.w * b4.w;
        }
        __syncthreads();
    }
#pragma unroll
    for (int i = 0; i < 4; i++) {
        float4 o = make_float4(acc[i][0] * alpha, acc[i][1] * alpha,
                               acc[i][2] * alpha, acc[i][3] * alpha);
        *(float4*)&C[(size_t)(mt * 64 + ty * 4 + i) * Nn + nt * 64 + tx * 4] = o;
    }
}

// ================= flash W2 on tensor cores =================
__global__ __launch_bounds__(256) void flash_w2_mma() {
    __shared__ __align__(16) __half sql[128][72];
    __shared__ __align__(16) __half sk[64][72];
    __shared__ __align__(16) __half svT[64][72];

    int tid = threadIdx.x, lane = tid & 31, w = tid >> 5;
    int chunk = blockIdx.x, mblk = blockIdx.y, bh = blockIdx.z;
    int lr = lane & 15, lh = lane >> 4;

    const __half* qlh = g_qlh + (size_t)(bh * MLM + mblk * 128) * 64;
#pragma unroll
    for (int i = 0; i < 4; i++) {
        int idx = tid + i * 256;
        int r = idx >> 3, c = (idx & 7) * 8;
        *(uint4*)&sql[r][c] = *(const uint4*)&qlh[(size_t)r * 64 + c];
    }
    __syncthreads();
    unsigned qa[4][4];
#pragma unroll
    for (int ks = 0; ks < 4; ks++)
        ldm4(qa[ks], smem_u32(&sql[w * 16 + lr][ks * 16 + lh * 8]));

    float outacc[8][4];
#pragma unroll
    for (int i = 0; i < 8; i++)
#pragma unroll
        for (int c = 0; c < 4; c++) outacc[i][c] = 0.f;
    float rsA = 0.f, rsB = 0.f;

    const __half* kb = g_kh + (size_t)bh * NSEQ * 64;
    const __half* vb = g_vh + (size_t)bh * NSEQ * 64;

    for (int it = 0; it < 32; it++) {
        int s0 = chunk * 2048 + it * 64;
        __syncthreads();
#pragma unroll
        for (int i = 0; i < 2; i++) {
            int idx = tid + i * 256;
            int r = idx >> 3, c = (idx & 7) * 8;
            *(uint4*)&sk[r][c] = *(const uint4*)&kb[(size_t)(s0 + r) * 64 + c];
            uint4 vv = *(const uint4*)&vb[(size_t)(s0 + r) * 64 + c];
            __half vh[8];
            *(uint4*)vh = vv;
#pragma unroll
            for (int j = 0; j < 8; j++) svT[c + j][r] = vh[j];
        }
        __syncthreads();
        float sf[8][4];
#pragma unroll
        for (int i = 0; i < 8; i++)
#pragma unroll
            for (int c = 0; c < 4; c++) sf[i][c] = 0.f;
#pragma unroll
        for (int ks = 0; ks < 4; ks++) {
#pragma unroll
            for (int nf4 = 0; nf4 < 4; nf4++) {
                unsigned bbf[4];
                ldm4(bbf, smem_u32(&sk[nf4 * 16 + lr][ks * 16 + lh * 8]));
                mmaf16(sf[nf4 * 2], qa[ks], bbf[0], bbf[2]);
                mmaf16(sf[nf4 * 2 + 1], qa[ks], bbf[1], bbf[3]);
            }
        }
#pragma unroll
        for (int nf = 0; nf < 8; nf++) {
            sf[nf][0] = fexp(sf[nf][0]); sf[nf][1] = fexp(sf[nf][1]);
            sf[nf][2] = fexp(sf[nf][2]); sf[nf][3] = fexp(sf[nf][3]);
            rsA += sf[nf][0] + sf[nf][1];
            rsB += sf[nf][2] + sf[nf][3];
        }
#pragma unroll
        for (int kk = 0; kk < 4; kk++) {
            unsigned pa[4];
            pa[0] = packh2(sf[2 * kk][0], sf[2 * kk][1]);
            pa[1] = packh2(sf[2 * kk][2], sf[2 * kk][3]);
            pa[2] = packh2(sf[2 * kk + 1][0], sf[2 * kk + 1][1]);
            pa[3] = packh2(sf[2 * kk + 1][2], sf[2 * kk + 1][3]);
#pragma unroll
            for (int nf4 = 0; nf4 < 4; nf4++) {
                unsigned bbf[4];
                ldm4(bbf, smem_u32(&svT[nf4 * 16 + lr][kk * 16 + lh * 8]));
                mmaf16(outacc[nf4 * 2], pa, bbf[0], bbf[2]);
                mmaf16(outacc[nf4 * 2 + 1], pa, bbf[1], bbf[3]);
            }
        }
    }
    rsA += __shfl_xor_sync(0xffffffffu, rsA, 1);
    rsA += __shfl_xor_sync(0xffffffffu, rsA, 2);
    rsB += __shfl_xor_sync(0xffffffffu, rsB, 1);
    rsB += __shfl_xor_sync(0xffffffffu, rsB, 2);

    int rA = mblk * 128 + w * 16 + (lane >> 2);
    int rB = rA + 8;
    float* wpA = g_Wpart + (size_t)((bh * 4 + chunk) * MLM + rA) * 64;
    float* wpB = g_Wpart + (size_t)((bh * 4 + chunk) * MLM + rB) * 64;
#pragma unroll
    for (int nf = 0; nf < 8; nf++) {
        int d = nf * 8 + (lane & 3) * 2;
        *(float2*)&wpA[d] = make_float2(outacc[nf][0], outacc[nf][1]);
        *(float2*)&wpB[d] = make_float2(outacc[nf][2], outacc[nf][3]);
    }
    if ((lane & 3) == 0) {
        g_Spart[(bh * 4 + chunk) * MLM + rA] = rsA;
        g_Spart[(bh * 4 + chunk) * MLM + rB] = rsB;
    }
}

__global__ void combine_w2_kernel() {
    int idx = blockIdx.x * 256 + threadIdx.x;
    int bh = idx >> 14;
    int m = (idx >> 6) & 255;
    int d = idx & 63;
    float num = 0.f, den = 0.f;
#pragma unroll
    for (int c = 0; c < 4; c++) {
        num += g_Wpart[(size_t)((bh * 4 + c) * MLM + m) * 64 + d];
        den += g_Spart[(bh * 4 + c) * MLM + m];
    }
    g_W2[(bh * MLM + m) * 64 + d] = num / den;
}

// ================= attn1 + conv on tensor cores (writes fp16 to g_A16) =================
__global__ __launch_bounds__(256) void attn1_mma(const float* __restrict__ convw) {
    extern __shared__ char smx[];
    __half (*sq)[72]  = (__half(*)[72])(smx);
    __half (*skl)[72] = (__half(*)[72])(smx + 18432);
    __half (*swT)[72] = (__half(*)[72])(smx + 27648);
    __half (*sv)[72]  = (__half(*)[72])(smx + 36864);
    float* cw = (float*)(smx + 59904);

    int tid = threadIdx.x, lane = tid & 31, w = tid >> 5;
    int ntile = blockIdx.x, bh = blockIdx.y;
    int h = bh & 7, bb2 = bh >> 3;
    int n0 = ntile * 128;
    int lr = lane & 15, lh = lane >> 4;

    if (tid < KSZ) cw[tid] = convw[h * KSZ + tid];

    const __half* qb = g_qh + ((size_t)bh * NSEQ + n0) * 64;
#pragma unroll
    for (int i = 0; i < 4; i++) {
        int idx = tid + i * 256;
        int r = idx >> 3, c = (idx & 7) * 8;
        *(uint4*)&sq[r][c] = *(const uint4*)&qb[(size_t)r * 64 + c];
    }
    const __half* vb2 = g_vh + (size_t)bh * NSEQ * 64;
#pragma unroll
    for (int i = 0; i < 5; i++) {
        int idx = tid + i * 256;
        int r = idx >> 3, c = (idx & 7) * 8;
        int gr = n0 - 16 + r;
        uint4 z = make_uint4(0u, 0u, 0u, 0u);
        if (gr >= 0 && gr < NSEQ) z = *(const uint4*)&vb2[(size_t)gr * 64 + c];
        *(uint4*)&sv[r][c] = z;
    }
    __syncthreads();

    unsigned qa[4][4];
#pragma unroll
    for (int ks = 0; ks < 4; ks++)
        ldm4(qa[ks], smem_u32(&sq[w * 16 + lr][ks * 16 + lh * 8]));

    float outacc[8][4];
#pragma unroll
    for (int i = 0; i < 8; i++)
#pragma unroll
        for (int c = 0; c < 4; c++) outacc[i][c] = 0.f;
    float rsA = 0.f, rsB = 0.f;

    const __half* klb = g_klh + (size_t)bh * MLM * 64;
    const __half* w3tb = g_W3T + (size_t)bh * 64 * 256;

    for (int lc = 0; lc < 4; lc++) {
        __syncthreads();
#pragma unroll
        for (int i = 0; i < 2; i++) {
            int idx = tid + i * 256;
            int r = idx >> 3, c = (idx & 7) * 8;
            *(uint4*)&skl[r][c] = *(const uint4*)&klb[(size_t)(lc * 64 + r) * 64 + c];
            *(uint4*)&swT[r][c] = *(const uint4*)&w3tb[(size_t)r * 256 + lc * 64 + c];
        }
        __syncthreads();
        float sf[8][4];
#pragma unroll
        for (int i = 0; i < 8; i++)
#pragma unroll
            for (int c = 0; c < 4; c++) sf[i][c] = 0.f;
#pragma unroll
        for (int ks = 0; ks < 4; ks++) {
#pragma unroll
            for (int nf4 = 0; nf4 < 4; nf4++) {
                unsigned bbf[4];
                ldm4(bbf, smem_u32(&skl[nf4 * 16 + lr][ks * 16 + lh * 8]));
                mmaf16(sf[nf4 * 2], qa[ks], bbf[0], bbf[2]);
                mmaf16(sf[nf4 * 2 + 1], qa[ks], bbf[1], bbf[3]);
            }
        }
#pragma unroll
        for (int nf = 0; nf < 8; nf++) {
            sf[nf][0] = fexp(sf[nf][0]); sf[nf][1] = fexp(sf[nf][1]);
            sf[nf][2] = fexp(sf[nf][2]); sf[nf][3] = fexp(sf[nf][3]);
            rsA += sf[nf][0] + sf[nf][1];
            rsB += sf[nf][2] + sf[nf][3];
        }
#pragma unroll
        for (int kk = 0; kk < 4; kk++) {
            unsigned pa[4];
            pa[0] = packh2(sf[2 * kk][0], sf[2 * kk][1]);
            pa[1] = packh2(sf[2 * kk][2], sf[2 * kk][3]);
            pa[2] = packh2(sf[2 * kk + 1][0], sf[2 * kk + 1][1]);
            pa[3] = packh2(sf[2 * kk + 1][2], sf[2 * kk + 1][3]);
#pragma unroll
            for (int nf4 = 0; nf4 < 4; nf4++) {
                unsigned bbf[4];
                ldm4(bbf, smem_u32(&swT[nf4 * 16 + lr][kk * 16 + lh * 8]));
                mmaf16(outacc[nf4 * 2], pa, bbf[0], bbf[2]);
                mmaf16(outacc[nf4 * 2 + 1], pa, bbf[1], bbf[3]);
            }
        }
    }
    rsA += __shfl_xor_sync(0xffffffffu, rsA, 1);
    rsA += __shfl_xor_sync(0xffffffffu, rsA, 2);
    rsB += __shfl_xor_sync(0xffffffffu, rsB, 1);
    rsB += __shfl_xor_sync(0xffffffffu, rsB, 2);
    float invA = 1.f / rsA, invB = 1.f / rsB;

    int lrA = w * 16 + (lane >> 2);
#pragma unroll
    for (int nf = 0; nf < 8; nf++) {
        int d = nf * 8 + (lane & 3) * 2;
        float a0 = 0.f, a1 = 0.f, b0 = 0.f, b1 = 0.f;
#pragma unroll
        for (int t = 0; t < KSZ; t++) {
            float wv = cw[t];
            float2 fA = __half22float2(*(__half2*)&sv[lrA + t][d]);
            float2 fB = __half22float2(*(__half2*)&sv[lrA + 8 + t][d]);
            a0 = fmaf(wv, fA.x, a0); a1 = fmaf(wv, fA.y, a1);
            b0 = fmaf(wv, fB.x, b0); b1 = fmaf(wv, fB.y, b1);
        }
        outacc[nf][0] = outacc[nf][0] * invA + a0;
        outacc[nf][1] = outacc[nf][1] * invA + a1;
        outacc[nf][2] = outacc[nf][2] * invB + b0;
        outacc[nf][3] = outacc[nf][3] * invB + b1;
    }

    int nA = n0 + lrA, nB = nA + 8;
    __half* oA = g_A16 + (size_t)(bb2 * NSEQ + nA) * 512 + h * 64;
    __half* oB = g_A16 + (size_t)(bb2 * NSEQ + nB) * 512 + h * 64;
#pragma unroll
    for (int nf = 0; nf < 8; nf++) {
        int d = nf * 8 + (lane & 3) * 2;
        *(__half2*)&oA[d] = __floats2half2_rn(outacc[nf][0], outacc[nf][1]);
        *(__half2*)&oB[d] = __floats2half2_rn(outacc[nf][2], outacc[nf][3]);
    }
}

// ================= host launcher (two-stream overlap) =================
extern "C" void kernel_launch(void* const* d_in, const int* in_sizes, int n_in,
                              void* d_out, int out_size) {
    const float* x     = (const float*)d_in[0];
    const float* ln_g  = (const float*)d_in[1];
    const float* ln_b  = (const float*)d_in[2];
    const float* W_qkv = (const float*)d_in[3];
    const float* W_out = (const float*)d_in[4];
    const float* b_out = (const float*)d_in[5];
    const float* convw = (const float*)d_in[6];
    float* out = (float*)d_out;

    static cudaStream_t sB = nullptr;
    static cudaEvent_t eFork = nullptr, eLm = nullptr, eJoin = nullptr;
    if (!sB) {
        cudaStreamCreateWithFlags(&sB, cudaStreamNonBlocking);
        cudaEventCreateWithFlags(&eFork, cudaEventDisableTiming);
        cudaEventCreateWithFlags(&eLm, cudaEventDisableTiming);
        cudaEventCreateWithFlags(&eJoin, cudaEventDisableTiming);
        cudaFuncSetAttribute(attn1_mma, cudaFuncAttributeMaxDynamicSharedMemorySize, 60416);
        cudaFuncSetAttribute(gemm_lm_kernel, cudaFuncAttributeMaxDynamicSharedMemorySize, 81920);
        cudaFuncSetAttribute(gemm16_kernel, cudaFuncAttributeMaxDynamicSharedMemorySize, 73728);
        cudaFuncSetAttribute(attn2_kernel, cudaFuncAttributeMaxDynamicSharedMemorySize, 65536);
    }

    __nv_bfloat16 *bqh, *bql;
    cudaGetSymbolAddress((void**)&bqh, g_Bqh);
    cudaGetSymbolAddress((void**)&bql, g_Bql);
    __half *b16q, *b16o;
    cudaGetSymbolAddress((void**)&b16q, g_B16q);
    cudaGetSymbolAddress((void**)&b16o, g_B16o);
    float *xnlmp;
    cudaGetSymbolAddress((void**)&xnlmp, g_xnlm);

    reset_kernel<<<1, 1>>>();
    ln_kernel<<<Bb * NSEQ, 128>>>(x, ln_g, ln_b);  // g_xn + g_A16

    // ---- fork ----
    cudaEventRecord(eFork, 0);
    cudaStreamWaitEvent(sB, eFork, 0);

    // Chain B (stream sB): landmark path -> attn2 -> z0 -> persistent pinv
    xnlm_kernel<<<1024, 256, 0, sB>>>();
    convA_kernel<<<256, 256, 0, sB>>>(xnlmp);
    convW_kernel<<<dim3(48, 16), 1024, 0, sB>>>(W_qkv, 1536, bqh, bql);
    gemm_lm_kernel<<<dim3(8, 4), 256, 81920, sB>>>(bqh, bql);
    cudaEventRecord(eLm, sB);
    attn2_kernel<<<dim3(4, 16), 256, 65536, sB>>>();
    colmax_kernel<<<16, 256, 0, sB>>>();
    z0_kernel<<<4096, 256, 0, sB>>>();
    pinv_persist<<<dim3(4, 2, 16), 256, 0, sB>>>();
    cudaEventRecord(eJoin, sB);

    // Chain A (default stream): qkv GEMM -> flash_w2 -> combine
    convW16_kernel<<<dim3(48, 16), 1024>>>(W_qkv, 1536, b16q);
    convW16_kernel<<<dim3(16, 16), 1024>>>(W_out, 512, b16o);
    gemm16_kernel<<<dim3(12, 128), 256, 73728>>>(b16q, 0, nullptr, nullptr);
    cudaStreamWaitEvent(0, eLm, 0);   // flash_w2 needs g_qlh from gemm_lm
    flash_w2_mma<<<dim3(4, 2, 16), 256>>>();
    combine_w2_kernel<<<1024, 256>>>();

    // ---- join ----
    cudaStreamWaitEvent(0, eJoin, 0);  // W3 needs Za from pinv
    gemm_bh_kernel<<<dim3(1, 4, 16), 256>>>(7, 4, 6, 64, 0.f, 1.f, 1.f);  // W3 = Za @ W2
    w3t_kernel<<<1024, 256>>>();
    attn1_mma<<<dim3(64, 16), 256, 60416>>>(convw);

    gemm16_kernel<<<dim3(4, 128), 256, 73728>>>(b16o, 1, b_out, out);
}

// round 14
// speedup vs baseline: 1.4304x; 1.0701x over previous
#include <cuda_runtime.h>
#include <cuda_bf16.h>
#include <cuda_fp16.h>

#define Bb    2
#define NSEQ  8192
#define DIMV  512
#define NH    8
#define BHn   16
#define DHd   64
#define MLM   256
#define LGRP  32
#define KSZ   33
#define PADc  16
#define SCALE 0.125f

// ================= static device scratch =================
__device__ float g_xn[(size_t)Bb * NSEQ * DIMV];
__device__ float g_ql[BHn * MLM * DHd];
__device__ float g_kl[BHn * MLM * DHd];
__device__ float g_attn2[BHn * MLM * MLM];
__device__ float g_Y[BHn * MLM * MLM];
__device__ float g_P[BHn * MLM * MLM];
__device__ float g_Qm[BHn * MLM * MLM];
__device__ float g_Za[BHn * MLM * MLM];
__device__ float g_Zb[BHn * MLM * MLM];
__device__ float g_W2[BHn * MLM * DHd];
__device__ float g_Wpart[(size_t)BHn * 4 * MLM * DHd];
__device__ float g_Spart[BHn * 4 * MLM];
__device__ int   g_maxc_bits;
__device__ unsigned g_bar;

// bf16 hi/lo buffers (landmark GEMM)
__device__ __nv_bfloat16 g_Ahi[512 * 512];
__device__ __nv_bfloat16 g_Alo[512 * 512];
__device__ __nv_bfloat16 g_Bqh[1536 * 512];
__device__ __nv_bfloat16 g_Bql[1536 * 512];

// fp16 buffers
__device__ __half g_A16[(size_t)Bb * NSEQ * DIMV];
__device__ __half g_B16q[1536 * 512];
__device__ __half g_B16o[512 * 512];
__device__ __half g_qh[(size_t)BHn * NSEQ * DHd];
__device__ __half g_kh[(size_t)BHn * NSEQ * DHd];
__device__ __half g_vh[(size_t)BHn * NSEQ * DHd];
__device__ __half g_qlh[BHn * MLM * DHd];
__device__ __half g_klh[BHn * MLM * DHd];
__device__ __half g_W3T[BHn * DHd * MLM];

// ================= mma.sync helpers =================
__device__ __forceinline__ unsigned smem_u32(const void* p) {
    unsigned a;
    asm("{ .reg .u64 t; cvta.to.shared.u64 t, %1; cvt.u32.u64 %0, t; }" : "=r"(a) : "l"(p));
    return a;
}
__device__ __forceinline__ void ldm4(unsigned* r, unsigned addr) {
    asm volatile("ldmatrix.sync.aligned.m8n8.x4.shared.b16 {%0,%1,%2,%3}, [%4];"
        : "=r"(r[0]), "=r"(r[1]), "=r"(r[2]), "=r"(r[3]) : "r"(addr));
}
__device__ __forceinline__ void mma16816(float* c, const unsigned* a, unsigned b0, unsigned b1) {
    asm volatile("mma.sync.aligned.m16n8k16.row.col.f32.bf16.bf16.f32 "
        "{%0,%1,%2,%3}, {%4,%5,%6,%7}, {%8,%9}, {%0,%1,%2,%3};"
        : "+f"(c[0]), "+f"(c[1]), "+f"(c[2]), "+f"(c[3])
        : "r"(a[0]), "r"(a[1]), "r"(a[2]), "r"(a[3]), "r"(b0), "r"(b1));
}
__device__ __forceinline__ void mmaf16(float* c, const unsigned* a, unsigned b0, unsigned b1) {
    asm volatile("mma.sync.aligned.m16n8k16.row.col.f32.f16.f16.f32 "
        "{%0,%1,%2,%3}, {%4,%5,%6,%7}, {%8,%9}, {%0,%1,%2,%3};"
        : "+f"(c[0]), "+f"(c[1]), "+f"(c[2]), "+f"(c[3])
        : "r"(a[0]), "r"(a[1]), "r"(a[2]), "r"(a[3]), "r"(b0), "r"(b1));
}
__device__ __forceinline__ void cpasync16(unsigned dst, const void* src) {
    asm volatile("cp.async.cg.shared.global [%0], [%1], 16;" :: "r"(dst), "l"(src));
}
#define CP_COMMIT() asm volatile("cp.async.commit_group;" ::: "memory")
__device__ __forceinline__ unsigned packh2(float a, float b) {
    __half2 h = __floats2half2_rn(a, b);
    return *(unsigned*)&h;
}
__device__ __forceinline__ float fexp(float x) {
    float t = x * 1.44269504f;
    float r = rintf(t);
    float f = t - r;
    float p = 1.33336e-3f;
    p = fmaf(p, f, 9.61813e-3f);
    p = fmaf(p, f, 5.55041e-2f);
    p = fmaf(p, f, 2.40226507e-1f);
    p = fmaf(p, f, 6.93147181e-1f);
    p = fmaf(p, f, 1.0f);
    int e = (int)r;
    return p * __int_as_float((e + 127) << 23);
}

// ================= layernorm (writes fp32 + fp16; also resets globals) =================
__global__ __launch_bounds__(128) void ln_kernel(const float* __restrict__ x,
                                                 const float* __restrict__ gam,
                                                 const float* __restrict__ bet) {
    if (blockIdx.x == 0 && threadIdx.x == 0) { g_maxc_bits = 0; g_bar = 0u; }
    int row = blockIdx.x;
    int tid = threadIdx.x;
    float4 v = ((const float4*)x)[(size_t)row * 128 + tid];
    float s1 = v.x + v.y + v.z + v.w;
    float s2 = v.x * v.x + v.y * v.y + v.z * v.z + v.w * v.w;
#pragma unroll
    for (int o = 16; o; o >>= 1) {
        s1 += __shfl_xor_sync(0xffffffffu, s1, o);
        s2 += __shfl_xor_sync(0xffffffffu, s2, o);
    }
    __shared__ float r1[4], r2[4];
    int w = tid >> 5;
    if ((tid & 31) == 0) { r1[w] = s1; r2[w] = s2; }
    __syncthreads();
    s1 = r1[0] + r1[1] + r1[2] + r1[3];
    s2 = r2[0] + r2[1] + r2[2] + r2[3];
    float mean = s1 * (1.f / 512.f);
    float var  = s2 * (1.f / 512.f) - mean * mean;
    float rstd = rsqrtf(var + 1e-5f);
    float4 g4 = ((const float4*)gam)[tid];
    float4 b4 = ((const float4*)bet)[tid];
    float4 o;
    o.x = (v.x - mean) * rstd * g4.x + b4.x;
    o.y = (v.y - mean) * rstd * g4.y + b4.y;
    o.z = (v.z - mean) * rstd * g4.z + b4.z;
    o.w = (v.w - mean) * rstd * g4.w + b4.w;
    ((float4*)g_xn)[(size_t)row * 128 + tid] = o;
    __half2* ph = (__half2*)(g_A16 + (size_t)row * 512 + tid * 4);
    ph[0] = __floats2half2_rn(o.x, o.y);
    ph[1] = __floats2half2_rn(o.z, o.w);
}

// ================= fused: group means of xn -> bf16 hi/lo =================
__global__ void xnlm_conv_kernel() {
    int idx = blockIdx.x * 256 + threadIdx.x;  // 512*512
    int row = idx >> 9;
    int d = idx & 511;
    int b = row >> 8, m = row & 255;
    const float* p = g_xn + ((size_t)(b * NSEQ) + m * LGRP) * DIMV + d;
    float s = 0.f;
#pragma unroll
    for (int i = 0; i < LGRP; i++) s += p[(size_t)i * DIMV];
    float val = s * (1.f / LGRP);
    __nv_bfloat16 h = __float2bfloat16(val);
    g_Ahi[idx] = h;
    g_Alo[idx] = __float2bfloat16(val - __bfloat162float(h));
}

// ================= converters =================
__global__ __launch_bounds__(1024) void convW_kernel(const float* __restrict__ W, int N,
                                                     __nv_bfloat16* __restrict__ BThi,
                                                     __nv_bfloat16* __restrict__ BTlo) {
    __shared__ float sh[32][33];
    int n0 = blockIdx.x * 32, k0 = blockIdx.y * 32;
    int tx = threadIdx.x & 31, ty = threadIdx.x >> 5;
    sh[ty][tx] = W[(size_t)(k0 + ty) * N + n0 + tx];
    __syncthreads();
    float x = sh[tx][ty];
    __nv_bfloat16 h = __float2bfloat16(x);
    __nv_bfloat16 l = __float2bfloat16(x - __bfloat162float(h));
    BThi[(size_t)(n0 + ty) * 512 + k0 + tx] = h;
    BTlo[(size_t)(n0 + ty) * 512 + k0 + tx] = l;
}

__global__ __launch_bounds__(1024) void convW16_kernel(const float* __restrict__ W, int N,
                                                       __half* __restrict__ BT) {
    __shared__ float sh[32][33];
    int n0 = blockIdx.x * 32, k0 = blockIdx.y * 32;
    int tx = threadIdx.x & 31, ty = threadIdx.x >> 5;
    sh[ty][tx] = W[(size_t)(k0 + ty) * N + n0 + tx];
    __syncthreads();
    BT[(size_t)(n0 + ty) * 512 + k0 + tx] = __float2half(sh[tx][ty]);
}

// ================= fp16 single-pass dense GEMM (cp.async double-buffered) =================
__global__ __launch_bounds__(256) void gemm16_kernel(
    const __half* __restrict__ gBbase, int mode,
    const float* __restrict__ bout, float* __restrict__ outp) {
    extern __shared__ char smdyn[];
    unsigned sbase = smem_u32(smdyn);
    int tid = threadIdx.x, lane = tid & 31, wid = tid >> 5;
    int wm = wid & 3, wn = wid >> 2;
    int mBase = blockIdx.y * 128, nBase = blockIdx.x * 128;
    int lr = lane & 15, lh = lane >> 4;

    const __half* gA = g_A16 + (size_t)mBase * 512;
    const __half* gB = gBbase + (size_t)nBase * 512;

    float acc[2][8][4];
#pragma unroll
    for (int i = 0; i < 2; i++)
#pragma unroll
        for (int j = 0; j < 8; j++)
#pragma unroll
            for (int c = 0; c < 4; c++) acc[i][j][c] = 0.f;

    int r_ld = tid >> 1;
    int q2 = (tid & 1) * 4;

    auto load_stage = [&](int ch, unsigned st) {
#pragma unroll
        for (int u = 0; u < 4; u++) {
            unsigned soff = (unsigned)r_ld * 144u + (q2 + u) * 16u;
            size_t goff = (size_t)r_ld * 512 + ch * 64 + (q2 + u) * 8;
            cpasync16(sbase + st + soff, gA + goff);
            cpasync16(sbase + st + 18432u + soff, gB + goff);
        }
        CP_COMMIT();
    };

    load_stage(0, 0u);

    for (int ch = 0; ch < 8; ch++) {
        unsigned st = (unsigned)(ch & 1) * 36864u;
        if (ch + 1 < 8) {
            load_stage(ch + 1, (unsigned)((ch + 1) & 1) * 36864u);
            asm volatile("cp.async.wait_group 1;" ::: "memory");
        } else {
            asm volatile("cp.async.wait_group 0;" ::: "memory");
        }
        __syncthreads();

        unsigned aA = sbase + st;
        unsigned aB = aA + 18432u;
#pragma unroll
        for (int ks = 0; ks < 4; ks++) {
            unsigned kc2 = (unsigned)(ks * 16 + lh * 8) * 2u;
            unsigned ah[2][4];
#pragma unroll
            for (int mi = 0; mi < 2; mi++) {
                unsigned rowA = (unsigned)(wm * 32 + mi * 16 + lr) * 144u;
                ldm4(ah[mi], aA + rowA + kc2);
            }
#pragma unroll
            for (int nt = 0; nt < 4; nt++) {
                unsigned rowB = (unsigned)(wn * 64 + nt * 16 + lr) * 144u;
                unsigned bf[4];
                ldm4(bf, aB + rowB + kc2);
#pragma unroll
                for (int mi = 0; mi < 2; mi++) {
#pragma unroll
                    for (int ns = 0; ns < 2; ns++)
                        mmaf16(acc[mi][nt * 2 + ns], ah[mi], bf[ns], bf[ns + 2]);
                }
            }
        }
        __syncthreads();
    }

    int r0 = mBase + wm * 32 + (lane >> 2);
    if (mode == 0) {
        int sec = nBase >> 9;
        float sc = (sec == 0) ? SCALE : 1.f;
        __half* hdst = (sec == 0) ? g_qh : ((sec == 1) ? g_kh : g_vh);
        int h = ((nBase + wn * 64) >> 6) & 7;
#pragma unroll
        for (int mi = 0; mi < 2; mi++) {
#pragma unroll
            for (int jn = 0; jn < 8; jn++) {
                int d = jn * 8 + (lane & 3) * 2;
#pragma unroll
                for (int half = 0; half < 2; half++) {
                    int gr = r0 + mi * 16 + half * 8;
                    int bb = gr >> 13, n = gr & 8191;
                    size_t off = ((size_t)(bb * 8 + h) * NSEQ + n) * 64 + d;
                    *(__half2*)&hdst[off] = __floats2half2_rn(acc[mi][jn][half * 2] * sc,
                                                              acc[mi][jn][half * 2 + 1] * sc);
                }
            }
        }
    } else {
#pragma unroll
        for (int mi = 0; mi < 2; mi++) {
#pragma unroll
            for (int jn = 0; jn < 8; jn++) {
                int gc = nBase + wn * 64 + jn * 8 + (lane & 3) * 2;
#pragma unroll
                for (int half = 0; half < 2; half++) {
                    int gr = r0 + mi * 16 + half * 8;
                    float2 bo = *(const float2*)&bout[gc];
                    float2 xv = *(const float2*)&g_xn[(size_t)gr * 512 + gc];
                    float2 o = make_float2(acc[mi][jn][half * 2] + bo.x + xv.x,
                                           acc[mi][jn][half * 2 + 1] + bo.y + xv.y);
                    *(float2*)&outp[(size_t)gr * 512 + gc] = o;
                }
            }
        }
    }
}

// ================= bf16 split landmark GEMM (M=512, N=1024) =================
__global__ __launch_bounds__(256) void gemm_lm_kernel(
    const __nv_bfloat16* __restrict__ BThi, const __nv_bfloat16* __restrict__ BTlo) {
    extern __shared__ char smdyn[];
    unsigned sbase = smem_u32(smdyn);
    int tid = threadIdx.x, lane = tid & 31, wid = tid >> 5;
    int wm = wid & 3, wn = wid >> 2;
    int mBase = blockIdx.y * 128, nBase = blockIdx.x * 128;
    int lr = lane & 15, lh = lane >> 4;

    const __nv_bfloat16* gsrc[4];
    gsrc[0] = g_Ahi + (size_t)mBase * 512;
    gsrc[1] = g_Alo + (size_t)mBase * 512;
    gsrc[2] = BThi + (size_t)nBase * 512;
    gsrc[3] = BTlo + (size_t)nBase * 512;

    float acc[2][8][4];
#pragma unroll
    for (int i = 0; i < 2; i++)
#pragma unroll
        for (int j = 0; j < 8; j++)
#pragma unroll
            for (int c = 0; c < 4; c++) acc[i][j][c] = 0.f;

    int r_ld0 = tid >> 2, q_ld = tid & 3;
    unsigned so0 = (unsigned)r_ld0 * 80u + q_ld * 16u;
    unsigned so1 = (unsigned)(r_ld0 + 64) * 80u + q_ld * 16u;

    {
        size_t go0 = (size_t)r_ld0 * 512 + q_ld * 8;
        size_t go1 = (size_t)(r_ld0 + 64) * 512 + q_ld * 8;
#pragma unroll
        for (int a = 0; a < 4; a++) {
            cpasync16(sbase + a * 10240u + so0, gsrc[a] + go0);
            cpasync16(sbase + a * 10240u + so1, gsrc[a] + go1);
        }
        CP_COMMIT();
    }

    for (int ch = 0; ch < 16; ch++) {
        unsigned st = (unsigned)(ch & 1) * 40960u;
        if (ch + 1 < 16) {
            unsigned stn = (unsigned)((ch + 1) & 1) * 40960u;
            size_t go0 = (size_t)r_ld0 * 512 + (ch + 1) * 32 + q_ld * 8;
            size_t go1 = (size_t)(r_ld0 + 64) * 512 + (ch + 1) * 32 + q_ld * 8;
#pragma unroll
            for (int a = 0; a < 4; a++) {
                cpasync16(sbase + stn + a * 10240u + so0, gsrc[a] + go0);
                cpasync16(sbase + stn + a * 10240u + so1, gsrc[a] + go1);
            }
            CP_COMMIT();
            asm volatile("cp.async.wait_group 1;" ::: "memory");
        } else {
            asm volatile("cp.async.wait_group 0;" ::: "memory");
        }
        __syncthreads();

        unsigned aAh = sbase + st;
        unsigned aAl = aAh + 10240u;
        unsigned aBh = aAh + 20480u;
        unsigned aBl = aAh + 30720u;
#pragma unroll
        for (int ks = 0; ks < 2; ks++) {
            unsigned kc2 = (unsigned)(ks * 16 + lh * 8) * 2u;
            unsigned ah[2][4], al[2][4];
#pragma unroll
            for (int mi = 0; mi < 2; mi++) {
                unsigned rowA = (unsigned)(wm * 32 + mi * 16 + lr) * 80u;
                ldm4(ah[mi], aAh + rowA + kc2);
                ldm4(al[mi], aAl + rowA + kc2);
            }
#pragma unroll
            for (int nt = 0; nt < 4; nt++) {
                unsigned rowB = (unsigned)(wn * 64 + nt * 16 + lr) * 80u;
                unsigned bh[4], bl[4];
                ldm4(bh, aBh + rowB + kc2);
                ldm4(bl, aBl + rowB + kc2);
#pragma unroll
                for (int mi = 0; mi < 2; mi++) {
#pragma unroll
                    for (int ns = 0; ns < 2; ns++) {
                        float* cc = acc[mi][nt * 2 + ns];
                        mma16816(cc, ah[mi], bh[ns], bh[ns + 2]);
                        mma16816(cc, ah[mi], bl[ns], bl[ns + 2]);
                        mma16816(cc, al[mi], bh[ns], bh[ns + 2]);
                    }
                }
            }
        }
        __syncthreads();
    }

    int r0 = mBase + wm * 32 + (lane >> 2);
    int sec = nBase >> 9;
    float sc = (sec == 0) ? SCALE : 1.f;
    float* dst = (sec == 0) ? g_ql : g_kl;
    __half* hdst = (sec == 0) ? g_qlh : g_klh;
    int h = ((nBase + wn * 64) >> 6) & 7;
#pragma unroll
    for (int mi = 0; mi < 2; mi++) {
#pragma unroll
        for (int jn = 0; jn < 8; jn++) {
            int d = jn * 8 + (lane & 3) * 2;
#pragma unroll
            for (int half = 0; half < 2; half++) {
                int gr = r0 + mi * 16 + half * 8;
                int bb = gr >> 8, m = gr & 255;
                float2 o = make_float2(acc[mi][jn][half * 2] * sc,
                                       acc[mi][jn][half * 2 + 1] * sc);
                size_t off = ((size_t)(bb * 8 + h) * MLM + m) * 64 + d;
                *(float2*)&dst[off] = o;
                *(__half2*)&hdst[off] = __floats2half2_rn(o.x, o.y);
            }
        }
    }
}

// ================= attn2 = softmax(q_l k_l^T), 64 CTAs =================
__global__ __launch_bounds__(256) void attn2_kernel() {
    extern __shared__ float sklf[];
    int rt = blockIdx.x, bh = blockIdx.y;
    int tid = threadIdx.x;
    int row = rt * 64 + (tid >> 2);
    int cg = tid & 3;

    const float4* klsrc = (const float4*)(g_kl + (size_t)bh * MLM * 64);
    float4* kld = (float4*)sklf;
#pragma unroll
    for (int i = 0; i < 16; i++) kld[tid + i * 256] = klsrc[tid + i * 256];

    float4 q[16];
    const float4* qp = (const float4*)(g_ql + (size_t)(bh * MLM + row) * 64);
#pragma unroll
    for (int i = 0; i < 16; i++) q[i] = qp[i];
    __syncthreads();

    float p[64];
    float sum = 0.f;
    const float4* klb = (const float4*)sklf + cg * 64 * 16;
    for (int j = 0; j < 64; j++) {
        const float4* kr = klb + j * 16;
        float s = 0.f;
#pragma unroll
        for (int d = 0; d < 16; d++) {
            float4 a = q[d], b = kr[d];
            s += a.x * b.x + a.y * b.y + a.z * b.z + a.w * b.w;
        }
        p[j] = __expf(s);
        sum += p[j];
    }
    sum += __shfl_xor_sync(0xffffffffu, sum, 1);
    sum += __shfl_xor_sync(0xffffffffu, sum, 2);
    float inv = 1.f / sum;
    float* arow = g_attn2 + (size_t)bh * 65536 + (size_t)row * 256 + cg * 64;
#pragma unroll
    for (int j = 0; j < 64; j += 4)
        *(float4*)&arow[j] = make_float4(p[j] * inv, p[j + 1] * inv,
                                         p[j + 2] * inv, p[j + 3] * inv);
}

// ================= max column-sum of attn2 =================
__global__ __launch_bounds__(256) void colmax_kernel() {
    int bh = blockIdx.x;
    int j = threadIdx.x;
    const float* a = g_attn2 + (size_t)bh * 65536;
    float s = 0.f;
    for (int m2 = 0; m2 < 256; m2++) s += a[m2 * 256 + j];
    __shared__ float red[256];
    red[j] = s;
    __syncthreads();
    for (int o = 128; o; o >>= 1) {
        if (j < o) red[j] = fmaxf(red[j], red[j + o]);
        __syncthreads();
    }
    if (j == 0) atomicMax(&g_maxc_bits, __float_as_int(red[0]));
}

__global__ void z0_kernel() {
    int idx = blockIdx.x * 256 + threadIdx.x;
    int bh = idx >> 16;
    int i = (idx >> 8) & 255;
    int j = idx & 255;
    float scale = 1.f / __int_as_float(g_maxc_bits);
    g_Za[idx] = g_attn2[(bh << 16) + (j << 8) + i] * scale;
}

// ================= buffer selector =================
__device__ __forceinline__ float* pickBuf(int id) {
    switch (id) {
        case 0: return g_attn2;
        case 1: return g_Y;
        case 2: return g_P;
        case 3: return g_Qm;
        case 4: return g_Za;
        default: return g_Zb;
    }
}

// ================= persistent pinv with register-prefetch pipelining =================
struct PinvSmem {
    __nv_bfloat16 Ah[128][40];
    __nv_bfloat16 Al[128][40];
    __nv_bfloat16 Bh[64][40];
    __nv_bfloat16 Bl[64][40];
};

__device__ __forceinline__ void gbarrier(int step) {
    __syncthreads();
    if (threadIdx.x == 0) {
        __threadfence();
        atomicAdd(&g_bar, 1u);
        unsigned target = 128u * (unsigned)step;
        while (*(volatile unsigned*)&g_bar < target) { }
    }
    __syncthreads();
}

__device__ void pinv_gemm(PinvSmem& S, int cId, int aId, int bId,
                          float beta, float sgn, float alpha, bool full,
                          int mBase, int nBase, int bh) {
    const float* A = pickBuf(aId) + (size_t)bh * 65536;
    const float* B = pickBuf(bId) + (size_t)bh * 65536;
    float*       C = pickBuf(cId) + (size_t)bh * 65536;

    int tid = threadIdx.x, lane = tid & 31, w = tid >> 5;
    int wm = w & 3, wn = w >> 2;
    int lr = lane & 15, lh = lane >> 4;

    float acc[2][4][4];
#pragma unroll
    for (int i = 0; i < 2; i++)
#pragma unroll
        for (int j = 0; j < 4; j++)
#pragma unroll
            for (int c = 0; c < 4; c++) acc[i][j][c] = 0.f;

    // register-prefetch pipeline state
    float4 rA[4];
    float rB[8];
    auto loadA = [&](int ch, float4* ra) {
#pragma unroll
        for (int i = 0; i < 4; i++) {
            int idx = tid + i * 256;
            int r = idx >> 3, c4 = (idx & 7) * 4;
            ra[i] = __ldcg((const float4*)&A[(size_t)(mBase + r) * 256 + ch * 32 + c4]);
        }
    };
    auto loadB = [&](int ch, float* rb) {
#pragma unroll
        for (int kl = 0; kl < 4; kl++) {
            int gk = ch * 32 + w * 4 + kl;
#pragma unroll
            for (int nh = 0; nh < 2; nh++) {
                int n = nh * 32 + lane;
                rb[kl * 2 + nh] = __ldcg(&B[(size_t)gk * 256 + nBase + n]);
            }
        }
    };

    loadA(0, rA);
    loadB(0, rB);

    for (int ch = 0; ch < 8; ch++) {
        if (ch) __syncthreads();
        // store current regs -> smem (convert hi/lo)
#pragma unroll
        for (int i = 0; i < 4; i++) {
            int idx = tid + i * 256;
            int r = idx >> 3, c4 = (idx & 7) * 4;
            float4 v = rA[i];
            __nv_bfloat16 h0 = __float2bfloat16(v.x), h1 = __float2bfloat16(v.y);
            __nv_bfloat16 h2 = __float2bfloat16(v.z), h3 = __float2bfloat16(v.w);
            S.Ah[r][c4 + 0] = h0; S.Ah[r][c4 + 1] = h1;
            S.Ah[r][c4 + 2] = h2; S.Ah[r][c4 + 3] = h3;
            if (full) {
                S.Al[r][c4 + 0] = __float2bfloat16(v.x - __bfloat162float(h0));
                S.Al[r][c4 + 1] = __float2bfloat16(v.y - __bfloat162float(h1));
                S.Al[r][c4 + 2] = __float2bfloat16(v.z - __bfloat162float(h2));
                S.Al[r][c4 + 3] = __float2bfloat16(v.w - __bfloat162float(h3));
            }
        }
#pragma unroll
        for (int kl = 0; kl < 4; kl++) {
            int gk = ch * 32 + w * 4 + kl;
#pragma unroll
            for (int nh = 0; nh < 2; nh++) {
                int n = nh * 32 + lane;
                float v = rB[kl * 2 + nh];
                v = sgn * v + ((gk == nBase + n) ? beta : 0.f);
                __nv_bfloat16 h = __float2bfloat16(v);
                S.Bh[n][w * 4 + kl] = h;
                if (full) S.Bl[n][w * 4 + kl] = __float2bfloat16(v - __bfloat162float(h));
            }
        }
        // prefetch next chunk while MMA runs
        float4 rA2[4];
        float rB2[8];
        if (ch + 1 < 8) {
            loadA(ch + 1, rA2);
            loadB(ch + 1, rB2);
        }
        __syncthreads();
#pragma unroll
        for (int ks = 0; ks < 2; ks++) {
            int kc = ks * 16 + lh * 8;
            unsigned ah[2][4], al[2][4];
#pragma unroll
            for (int mi = 0; mi < 2; mi++) {
                int rowA = wm * 32 + mi * 16 + lr;
                ldm4(ah[mi], smem_u32(&S.Ah[rowA][kc]));
                if (full) ldm4(al[mi], smem_u32(&S.Al[rowA][kc]));
            }
#pragma unroll
            for (int nt = 0; nt < 2; nt++) {
                int rowB = wn * 32 + nt * 16 + lr;
                unsigned bhf[4], blf[4];
                ldm4(bhf, smem_u32(&S.Bh[rowB][kc]));
                if (full) ldm4(blf, smem_u32(&S.Bl[rowB][kc]));
#pragma unroll
                for (int mi = 0; mi < 2; mi++) {
#pragma unroll
                    for (int ns = 0; ns < 2; ns++) {
                        float* cc = acc[mi][nt * 2 + ns];
                        mma16816(cc, ah[mi], bhf[ns], bhf[ns + 2]);
                        if (full) {
                            mma16816(cc, ah[mi], blf[ns], blf[ns + 2]);
                            mma16816(cc, al[mi], bhf[ns], bhf[ns + 2]);
                        }
                    }
                }
            }
        }
        if (ch + 1 < 8) {
#pragma unroll
            for (int i = 0; i < 4; i++) rA[i] = rA2[i];
#pragma unroll
            for (int i = 0; i < 8; i++) rB[i] = rB2[i];
        }
    }
#pragma unroll
    for (int mi = 0; mi < 2; mi++) {
#pragma unroll
        for (int jn = 0; jn < 4; jn++) {
            int gc = nBase + wn * 32 + jn * 8 + (lane & 3) * 2;
#pragma unroll
            for (int half = 0; half < 2; half++) {
                int gr = mBase + wm * 32 + mi * 16 + (lane >> 2) + half * 8;
                float2 o = make_float2(acc[mi][jn][half * 2] * alpha,
                                       acc[mi][jn][half * 2 + 1] * alpha);
                *(float2*)&C[(size_t)gr * 256 + gc] = o;
            }
        }
    }
}

__global__ __launch_bounds__(256) void pinv_persist() {
    __shared__ PinvSmem S;
    int bh = blockIdx.z;
    int mBase = blockIdx.y * 128, nBase = blockIdx.x * 64;
    int step = 0;
    for (int it = 0; it < 6; it++) {
        bool full = (it == 5);
        int zc = 4 + (it & 1), zn = 5 - (it & 1);
        pinv_gemm(S, 1, 0, zc, 0.f, 1.f, 1.f, full, mBase, nBase, bh);
        gbarrier(++step);
        pinv_gemm(S, 2, 1, 1, 7.f, -1.f, 1.f, full, mBase, nBase, bh);
        gbarrier(++step);
        pinv_gemm(S, 3, 1, 2, 15.f, -1.f, 1.f, full, mBase, nBase, bh);
        gbarrier(++step);
        pinv_gemm(S, zn, zc, 3, 13.f, -1.f, 0.25f, full, mBase, nBase, bh);
        gbarrier(++step);
    }
}

// ================= W3 GEMM: W3T(fp16, transposed) = Za @ W2 =================
__global__ __launch_bounds__(256) void gemm_w3_kernel() {
    int bh = blockIdx.z, mt = blockIdx.y;
    const float* A  = g_Za + (size_t)bh * 65536;
    const float* Bp = g_W2 + (size_t)bh * 256 * 64;
    __half*      C  = g_W3T + (size_t)bh * 64 * 256;
    __shared__ float As[16][64];
    __shared__ float Bs[16][64];
    int tid = threadIdx.x;
    int ar = tid >> 2, ac = (tid & 3) * 4;
    int br = tid >> 4, bc = (tid & 15) * 4;
    int ty = tid >> 4, tx = tid & 15;
    float acc[4][4];
#pragma unroll
    for (int i = 0; i < 4; i++)
#pragma unroll
        for (int j = 0; j < 4; j++) acc[i][j] = 0.f;

    for (int k0 = 0; k0 < 256; k0 += 16) {
        float4 av = *(const float4*)&A[(size_t)(mt * 64 + ar) * 256 + k0 + ac];
        As[ac + 0][ar] = av.x; As[ac + 1][ar] = av.y;
        As[ac + 2][ar] = av.z; As[ac + 3][ar] = av.w;
        float4 bv = *(const float4*)&Bp[(size_t)(k0 + br) * 64 + bc];
        *(float4*)&Bs[br][bc] = bv;
        __syncthreads();
#pragma unroll
        for (int kk = 0; kk < 16; kk++) {
            float4 a4 = *(const float4*)&As[kk][ty * 4];
            float4 b4 = *(const float4*)&Bs[kk][tx * 4];
            acc[0][0] += a4.x * b4.x; acc[0][1] += a4.x * b4.y; acc[0][2] += a4.x * b4.z; acc[0][3] += a4.x * b4.w;
            acc[1][0] += a4.y * b4.x; acc[1][1] += a4.y * b4.y; acc[1][2] += a4.y * b4.z; acc[1][3] += a4.y * b4.w;
            acc[2][0] += a4.z * b4.x; acc[2][1] += a4.z * b4.y; acc[2][2] += a4.z * b4.z; acc[2][3] += a4.z * b4.w;
            acc[3][0] += a4.w * b4.x; acc[3][1] += a4.w * b4.y; acc[3][2] += a4.w * b4.z; acc[3][3] += a4.w * b4.w;
        }
        __syncthreads();
    }
    // transposed fp16 epilogue: W3T[d][m] = acc, m = mt*64+ty*4+i, d = tx*4+j
#pragma unroll
    for (int i = 0; i < 4; i++) {
        int m = mt * 64 + ty * 4 + i;
#pragma unroll
        for (int j = 0; j < 4; j++) {
            int d = tx * 4 + j;
            C[(size_t)d * 256 + m] = __float2half(acc[i][j]);
        }
    }
}

// ================= flash W2 on tensor cores =================
__global__ __launch_bounds__(256) void flash_w2_mma() {
    __shared__ __align__(16) __half sql[128][72];
    __shared__ __align__(16) __half sk[64][72];
    __shared__ __align__(16) __half svT[64][72];

    int tid = threadIdx.x, lane = tid & 31, w = tid >> 5;
    int chunk = blockIdx.x, mblk = blockIdx.y, bh = blockIdx.z;
    int lr = lane & 15, lh = lane >> 4;

    const __half* qlh = g_qlh + (size_t)(bh * MLM + mblk * 128) * 64;
#pragma unroll
    for (int i = 0; i < 4; i++) {
        int idx = tid + i * 256;
        int r = idx >> 3, c = (idx & 7) * 8;
        *(uint4*)&sql[r][c] = *(const uint4*)&qlh[(size_t)r * 64 + c];
    }
    __syncthreads();
    unsigned qa[4][4];
#pragma unroll
    for (int ks = 0; ks < 4; ks++)
        ldm4(qa[ks], smem_u32(&sql[w * 16 + lr][ks * 16 + lh * 8]));

    float outacc[8][4];
#pragma unroll
    for (int i = 0; i < 8; i++)
#pragma unroll
        for (int c = 0; c < 4; c++) outacc[i][c] = 0.f;
    float rsA = 0.f, rsB = 0.f;

    const __half* kb = g_kh + (size_t)bh * NSEQ * 64;
    const __half* vb = g_vh + (size_t)bh * NSEQ * 64;

    for (int it = 0; it < 32; it++) {
        int s0 = chunk * 2048 + it * 64;
        __syncthreads();
#pragma unroll
        for (int i = 0; i < 2; i++) {
            int idx = tid + i * 256;
            int r = idx >> 3, c = (idx & 7) * 8;
            *(uint4*)&sk[r][c] = *(const uint4*)&kb[(size_t)(s0 + r) * 64 + c];
            uint4 vv = *(const uint4*)&vb[(size_t)(s0 + r) * 64 + c];
            __half vh[8];
            *(uint4*)vh = vv;
#pragma unroll
            for (int j = 0; j < 8; j++) svT[c + j][r] = vh[j];
        }
        __syncthreads();
        float sf[8][4];
#pragma unroll
        for (int i = 0; i < 8; i++)
#pragma unroll
            for (int c = 0; c < 4; c++) sf[i][c] = 0.f;
#pragma unroll
        for (int ks = 0; ks < 4; ks++) {
#pragma unroll
            for (int nf4 = 0; nf4 < 4; nf4++) {
                unsigned bbf[4];
                ldm4(bbf, smem_u32(&sk[nf4 * 16 + lr][ks * 16 + lh * 8]));
                mmaf16(sf[nf4 * 2], qa[ks], bbf[0], bbf[2]);
                mmaf16(sf[nf4 * 2 + 1], qa[ks], bbf[1], bbf[3]);
            }
        }
#pragma unroll
        for (int nf = 0; nf < 8; nf++) {
            sf[nf][0] = fexp(sf[nf][0]); sf[nf][1] = fexp(sf[nf][1]);
            sf[nf][2] = fexp(sf[nf][2]); sf[nf][3] = fexp(sf[nf][3]);
            rsA += sf[nf][0] + sf[nf][1];
            rsB += sf[nf][2] + sf[nf][3];
        }
#pragma unroll
        for (int kk = 0; kk < 4; kk++) {
            unsigned pa[4];
            pa[0] = packh2(sf[2 * kk][0], sf[2 * kk][1]);
            pa[1] = packh2(sf[2 * kk][2], sf[2 * kk][3]);
            pa[2] = packh2(sf[2 * kk + 1][0], sf[2 * kk + 1][1]);
            pa[3] = packh2(sf[2 * kk + 1][2], sf[2 * kk + 1][3]);
#pragma unroll
            for (int nf4 = 0; nf4 < 4; nf4++) {
                unsigned bbf[4];
                ldm4(bbf, smem_u32(&svT[nf4 * 16 + lr][kk * 16 + lh * 8]));
                mmaf16(outacc[nf4 * 2], pa, bbf[0], bbf[2]);
                mmaf16(outacc[nf4 * 2 + 1], pa, bbf[1], bbf[3]);
            }
        }
    }
    rsA += __shfl_xor_sync(0xffffffffu, rsA, 1);
    rsA += __shfl_xor_sync(0xffffffffu, rsA, 2);
    rsB += __shfl_xor_sync(0xffffffffu, rsB, 1);
    rsB += __shfl_xor_sync(0xffffffffu, rsB, 2);

    int rA = mblk * 128 + w * 16 + (lane >> 2);
    int rB = rA + 8;
    float* wpA = g_Wpart + (size_t)((bh * 4 + chunk) * MLM + rA) * 64;
    float* wpB = g_Wpart + (size_t)((bh * 4 + chunk) * MLM + rB) * 64;
#pragma unroll
    for (int nf = 0; nf < 8; nf++) {
        int d = nf * 8 + (lane & 3) * 2;
        *(float2*)&wpA[d] = make_float2(outacc[nf][0], outacc[nf][1]);
        *(float2*)&wpB[d] = make_float2(outacc[nf][2], outacc[nf][3]);
    }
    if ((lane & 3) == 0) {
        g_Spart[(bh * 4 + chunk) * MLM + rA] = rsA;
        g_Spart[(bh * 4 + chunk) * MLM + rB] = rsB;
    }
}

__global__ void combine_w2_kernel() {
    int idx = blockIdx.x * 256 + threadIdx.x;
    int bh = idx >> 14;
    int m = (idx >> 6) & 255;
    int d = idx & 63;
    float num = 0.f, den = 0.f;
#pragma unroll
    for (int c = 0; c < 4; c++) {
        num += g_Wpart[(size_t)((bh * 4 + c) * MLM + m) * 64 + d];
        den += g_Spart[(bh * 4 + c) * MLM + m];
    }
    g_W2[(bh * MLM + m) * 64 + d] = num / den;
}

// ================= attn1 + conv on tensor cores (writes fp16 to g_A16) =================
__global__ __launch_bounds__(256) void attn1_mma(const float* __restrict__ convw) {
    extern __shared__ char smx[];
    __half (*sq)[72]  = (__half(*)[72])(smx);
    __half (*skl)[72] = (__half(*)[72])(smx + 18432);
    __half (*swT)[72] = (__half(*)[72])(smx + 27648);
    __half (*sv)[72]  = (__half(*)[72])(smx + 36864);
    float* cw = (float*)(smx + 59904);

    int tid = threadIdx.x, lane = tid & 31, w = tid >> 5;
    int ntile = blockIdx.x, bh = blockIdx.y;
    int h = bh & 7, bb2 = bh >> 3;
    int n0 = ntile * 128;
    int lr = lane & 15, lh = lane >> 4;

    if (tid < KSZ) cw[tid] = convw[h * KSZ + tid];

    const __half* qb = g_qh + ((size_t)bh * NSEQ + n0) * 64;
#pragma unroll
    for (int i = 0; i < 4; i++) {
        int idx = tid + i * 256;
        int r = idx >> 3, c = (idx & 7) * 8;
        *(uint4*)&sq[r][c] = *(const uint4*)&qb[(size_t)r * 64 + c];
    }
    const __half* vb2 = g_vh + (size_t)bh * NSEQ * 64;
#pragma unroll
    for (int i = 0; i < 5; i++) {
        int idx = tid + i * 256;
        int r = idx >> 3, c = (idx & 7) * 8;
        int gr = n0 - 16 + r;
        uint4 z = make_uint4(0u, 0u, 0u, 0u);
        if (gr >= 0 && gr < NSEQ) z = *(const uint4*)&vb2[(size_t)gr * 64 + c];
        *(uint4*)&sv[r][c] = z;
    }
    __syncthreads();

    unsigned qa[4][4];
#pragma unroll
    for (int ks = 0; ks < 4; ks++)
        ldm4(qa[ks], smem_u32(&sq[w * 16 + lr][ks * 16 + lh * 8]));

    float outacc[8][4];
#pragma unroll
    for (int i = 0; i < 8; i++)
#pragma unroll
        for (int c = 0; c < 4; c++) outacc[i][c] = 0.f;
    float rsA = 0.f, rsB = 0.f;

    const __half* klb = g_klh + (size_t)bh * MLM * 64;
    const __half* w3tb = g_W3T + (size_t)bh * 64 * 256;

    for (int lc = 0; lc < 4; lc++) {
        __syncthreads();
#pragma unroll
        for (int i = 0; i < 2; i++) {
            int idx = tid + i * 256;
            int r = idx >> 3, c = (idx & 7) * 8;
            *(uint4*)&skl[r][c] = *(const uint4*)&klb[(size_t)(lc * 64 + r) * 64 + c];
            *(uint4*)&swT[r][c] = *(const uint4*)&w3tb[(size_t)r * 256 + lc * 64 + c];
        }
        __syncthreads();
        float sf[8][4];
#pragma unroll
        for (int i = 0; i < 8; i++)
#pragma unroll
            for (int c = 0; c < 4; c++) sf[i][c] = 0.f;
#pragma unroll
        for (int ks = 0; ks < 4; ks++) {
#pragma unroll
            for (int nf4 = 0; nf4 < 4; nf4++) {
                unsigned bbf[4];
                ldm4(bbf, smem_u32(&skl[nf4 * 16 + lr][ks * 16 + lh * 8]));
                mmaf16(sf[nf4 * 2], qa[ks], bbf[0], bbf[2]);
                mmaf16(sf[nf4 * 2 + 1], qa[ks], bbf[1], bbf[3]);
            }
        }
#pragma unroll
        for (int nf = 0; nf < 8; nf++) {
            sf[nf][0] = fexp(sf[nf][0]); sf[nf][1] = fexp(sf[nf][1]);
            sf[nf][2] = fexp(sf[nf][2]); sf[nf][3] = fexp(sf[nf][3]);
            rsA += sf[nf][0] + sf[nf][1];
            rsB += sf[nf][2] + sf[nf][3];
        }
#pragma unroll
        for (int kk = 0; kk < 4; kk++) {
            unsigned pa[4];
            pa[0] = packh2(sf[2 * kk][0], sf[2 * kk][1]);
            pa[1] = packh2(sf[2 * kk][2], sf[2 * kk][3]);
            pa[2] = packh2(sf[2 * kk + 1][0], sf[2 * kk + 1][1]);
            pa[3] = packh2(sf[2 * kk + 1][2], sf[2 * kk + 1][3]);
#pragma unroll
            for (int nf4 = 0; nf4 < 4; nf4++) {
                unsigned bbf[4];
                ldm4(bbf, smem_u32(&swT[nf4 * 16 + lr][kk * 16 + lh * 8]));
                mmaf16(outacc[nf4 * 2], pa, bbf[0], bbf[2]);
                mmaf16(outacc[nf4 * 2 + 1], pa, bbf[1], bbf[3]);
            }
        }
    }
    rsA += __shfl_xor_sync(0xffffffffu, rsA, 1);
    rsA += __shfl_xor_sync(0xffffffffu, rsA, 2);
    rsB += __shfl_xor_sync(0xffffffffu, rsB, 1);
    rsB += __shfl_xor_sync(0xffffffffu, rsB, 2);
    float invA = 1.f / rsA, invB = 1.f / rsB;

    int lrA = w * 16 + (lane >> 2);
#pragma unroll
    for (int nf = 0; nf < 8; nf++) {
        int d = nf * 8 + (lane & 3) * 2;
        float a0 = 0.f, a1 = 0.f, b0 = 0.f, b1 = 0.f;
#pragma unroll
        for (int t = 0; t < KSZ; t++) {
            float wv = cw[t];
            float2 fA = __half22float2(*(__half2*)&sv[lrA + t][d]);
            float2 fB = __half22float2(*(__half2*)&sv[lrA + 8 + t][d]);
            a0 = fmaf(wv, fA.x, a0); a1 = fmaf(wv, fA.y, a1);
            b0 = fmaf(wv, fB.x, b0); b1 = fmaf(wv, fB.y, b1);
        }
        outacc[nf][0] = outacc[nf][0] * invA + a0;
        outacc[nf][1] = outacc[nf][1] * invA + a1;
        outacc[nf][2] = outacc[nf][2] * invB + b0;
        outacc[nf][3] = outacc[nf][3] * invB + b1;
    }

    int nA = n0 + lrA, nB = nA + 8;
    __half* oA = g_A16 + (size_t)(bb2 * NSEQ + nA) * 512 + h * 64;
    __half* oB = g_A16 + (size_t)(bb2 * NSEQ + nB) * 512 + h * 64;
#pragma unroll
    for (int nf = 0; nf < 8; nf++) {
        int d = nf * 8 + (lane & 3) * 2;
        *(__half2*)&oA[d] = __floats2half2_rn(outacc[nf][0], outacc[nf][1]);
        *(__half2*)&oB[d] = __floats2half2_rn(outacc[nf][2], outacc[nf][3]);
    }
}

// ================= host launcher (two-stream overlap) =================
extern "C" void kernel_launch(void* const* d_in, const int* in_sizes, int n_in,
                              void* d_out, int out_size) {
    const float* x     = (const float*)d_in[0];
    const float* ln_g  = (const float*)d_in[1];
    const float* ln_b  = (const float*)d_in[2];
    const float* W_qkv = (const float*)d_in[3];
    const float* W_out = (const float*)d_in[4];
    const float* b_out = (const float*)d_in[5];
    const float* convw = (const float*)d_in[6];
    float* out = (float*)d_out;

    static cudaStream_t sB = nullptr;
    static cudaEvent_t eFork = nullptr, eLm = nullptr, eJoin = nullptr;
    if (!sB) {
        cudaStreamCreateWithFlags(&sB, cudaStreamNonBlocking);
        cudaEventCreateWithFlags(&eFork, cudaEventDisableTiming);
        cudaEventCreateWithFlags(&eLm, cudaEventDisableTiming);
        cudaEventCreateWithFlags(&eJoin, cudaEventDisableTiming);
        cudaFuncSetAttribute(attn1_mma, cudaFuncAttributeMaxDynamicSharedMemorySize, 60416);
        cudaFuncSetAttribute(gemm_lm_kernel, cudaFuncAttributeMaxDynamicSharedMemorySize, 81920);
        cudaFuncSetAttribute(gemm16_kernel, cudaFuncAttributeMaxDynamicSharedMemorySize, 73728);
        cudaFuncSetAttribute(attn2_kernel, cudaFuncAttributeMaxDynamicSharedMemorySize, 65536);
    }

    __nv_bfloat16 *bqh, *bql;
    cudaGetSymbolAddress((void**)&bqh, g_Bqh);
    cudaGetSymbolAddress((void**)&bql, g_Bql);
    __half *b16q, *b16o;
    cudaGetSymbolAddress((void**)&b16q, g_B16q);
    cudaGetSymbolAddress((void**)&b16o, g_B16o);

    ln_kernel<<<Bb * NSEQ, 128>>>(x, ln_g, ln_b);  // g_xn + g_A16 + resets

    // ---- fork ----
    cudaEventRecord(eFork, 0);
    cudaStreamWaitEvent(sB, eFork, 0);

    // Chain B (stream sB): landmark path -> attn2 -> z0 -> persistent pinv
    xnlm_conv_kernel<<<1024, 256, 0, sB>>>();
    convW_kernel<<<dim3(48, 16), 1024, 0, sB>>>(W_qkv, 1536, bqh, bql);
    gemm_lm_kernel<<<dim3(8, 4), 256, 81920, sB>>>(bqh, bql);
    cudaEventRecord(eLm, sB);
    attn2_kernel<<<dim3(4, 16), 256, 65536, sB>>>();
    colmax_kernel<<<16, 256, 0, sB>>>();
    z0_kernel<<<4096, 256, 0, sB>>>();
    pinv_persist<<<dim3(4, 2, 16), 256, 0, sB>>>();
    cudaEventRecord(eJoin, sB);

    // Chain A (default stream): qkv GEMM -> flash_w2 -> combine
    convW16_kernel<<<dim3(48, 16), 1024>>>(W_qkv, 1536, b16q);
    convW16_kernel<<<dim3(16, 16), 1024>>>(W_out, 512, b16o);
    gemm16_kernel<<<dim3(12, 128), 256, 73728>>>(b16q, 0, nullptr, nullptr);
    cudaStreamWaitEvent(0, eLm, 0);   // flash_w2 needs g_qlh
    flash_w2_mma<<<dim3(4, 2, 16), 256>>>();
    combine_w2_kernel<<<1024, 256>>>();

    // ---- join ----
    cudaStreamWaitEvent(0, eJoin, 0);  // W3 needs Za from pinv
    gemm_w3_kernel<<<dim3(1, 4, 16), 256>>>();  // writes g_W3T fp16 transposed directly
    attn1_mma<<<dim3(64, 16), 256, 60416>>>(convw);

    gemm16_kernel<<<dim3(4, 128), 256, 73728>>>(b16o, 1, b_out, out);
}

// round 15
// speedup vs baseline: 1.4687x; 1.0268x over previous
#include <cuda_runtime.h>
#include <cuda_bf16.h>
#include <cuda_fp16.h>

#define Bb    2
#define NSEQ  8192
#define DIMV  512
#define NH    8
#define BHn   16
#define DHd   64
#define MLM   256
#define LGRP  32
#define KSZ   33
#define PADc  16
#define SCALE 0.125f

// ================= static device scratch =================
__device__ float g_xn[(size_t)Bb * NSEQ * DIMV];
__device__ float g_ql[BHn * MLM * DHd];
__device__ float g_kl[BHn * MLM * DHd];
__device__ float g_attn2[BHn * MLM * MLM];
__device__ float g_Y[BHn * MLM * MLM];
__device__ float g_P[BHn * MLM * MLM];
__device__ float g_Qm[BHn * MLM * MLM];
__device__ float g_Za[BHn * MLM * MLM];
__device__ float g_Zb[BHn * MLM * MLM];
__device__ float g_W2[BHn * MLM * DHd];
__device__ float g_Wpart[(size_t)BHn * 4 * MLM * DHd];
__device__ float g_Spart[BHn * 4 * MLM];
__device__ int   g_maxc_bits;
__device__ unsigned g_bar;

// bf16 hi/lo buffers (landmark GEMM)
__device__ __nv_bfloat16 g_Ahi[512 * 512];
__device__ __nv_bfloat16 g_Alo[512 * 512];
__device__ __nv_bfloat16 g_Bqh[1536 * 512];
__device__ __nv_bfloat16 g_Bql[1536 * 512];

// fp16 buffers
__device__ __half g_A16[(size_t)Bb * NSEQ * DIMV];
__device__ __half g_B16q[1536 * 512];
__device__ __half g_B16o[512 * 512];
__device__ __half g_qh[(size_t)BHn * NSEQ * DHd];
__device__ __half g_kh[(size_t)BHn * NSEQ * DHd];
__device__ __half g_vh[(size_t)BHn * NSEQ * DHd];
__device__ __half g_qlh[BHn * MLM * DHd];
__device__ __half g_klh[BHn * MLM * DHd];
__device__ __half g_W3T[BHn * DHd * MLM];

// ================= mma.sync helpers =================
__device__ __forceinline__ unsigned smem_u32(const void* p) {
    unsigned a;
    asm("{ .reg .u64 t; cvta.to.shared.u64 t, %1; cvt.u32.u64 %0, t; }" : "=r"(a) : "l"(p));
    return a;
}
__device__ __forceinline__ void ldm4(unsigned* r, unsigned addr) {
    asm volatile("ldmatrix.sync.aligned.m8n8.x4.shared.b16 {%0,%1,%2,%3}, [%4];"
        : "=r"(r[0]), "=r"(r[1]), "=r"(r[2]), "=r"(r[3]) : "r"(addr));
}
__device__ __forceinline__ void mma16816(float* c, const unsigned* a, unsigned b0, unsigned b1) {
    asm volatile("mma.sync.aligned.m16n8k16.row.col.f32.bf16.bf16.f32 "
        "{%0,%1,%2,%3}, {%4,%5,%6,%7}, {%8,%9}, {%0,%1,%2,%3};"
        : "+f"(c[0]), "+f"(c[1]), "+f"(c[2]), "+f"(c[3])
        : "r"(a[0]), "r"(a[1]), "r"(a[2]), "r"(a[3]), "r"(b0), "r"(b1));
}
__device__ __forceinline__ void mmaf16(float* c, const unsigned* a, unsigned b0, unsigned b1) {
    asm volatile("mma.sync.aligned.m16n8k16.row.col.f32.f16.f16.f32 "
        "{%0,%1,%2,%3}, {%4,%5,%6,%7}, {%8,%9}, {%0,%1,%2,%3};"
        : "+f"(c[0]), "+f"(c[1]), "+f"(c[2]), "+f"(c[3])
        : "r"(a[0]), "r"(a[1]), "r"(a[2]), "r"(a[3]), "r"(b0), "r"(b1));
}
__device__ __forceinline__ void cpasync16(unsigned dst, const void* src) {
    asm volatile("cp.async.cg.shared.global [%0], [%1], 16;" :: "r"(dst), "l"(src));
}
#define CP_COMMIT() asm volatile("cp.async.commit_group;" ::: "memory")
__device__ __forceinline__ unsigned packh2(float a, float b) {
    __half2 h = __floats2half2_rn(a, b);
    return *(unsigned*)&h;
}
__device__ __forceinline__ float fexp(float x) {
    float t = x * 1.44269504f;
    float r = rintf(t);
    float f = t - r;
    float p = 1.33336e-3f;
    p = fmaf(p, f, 9.61813e-3f);
    p = fmaf(p, f, 5.55041e-2f);
    p = fmaf(p, f, 2.40226507e-1f);
    p = fmaf(p, f, 6.93147181e-1f);
    p = fmaf(p, f, 1.0f);
    int e = (int)r;
    return p * __int_as_float((e + 127) << 23);
}

// ================= layernorm (writes fp32 + fp16; also resets globals) =================
__global__ __launch_bounds__(128) void ln_kernel(const float* __restrict__ x,
                                                 const float* __restrict__ gam,
                                                 const float* __restrict__ bet) {
    if (blockIdx.x == 0 && threadIdx.x == 0) { g_maxc_bits = 0; g_bar = 0u; }
    int row = blockIdx.x;
    int tid = threadIdx.x;
    float4 v = ((const float4*)x)[(size_t)row * 128 + tid];
    float s1 = v.x + v.y + v.z + v.w;
    float s2 = v.x * v.x + v.y * v.y + v.z * v.z + v.w * v.w;
#pragma unroll
    for (int o = 16; o; o >>= 1) {
        s1 += __shfl_xor_sync(0xffffffffu, s1, o);
        s2 += __shfl_xor_sync(0xffffffffu, s2, o);
    }
    __shared__ float r1[4], r2[4];
    int w = tid >> 5;
    if ((tid & 31) == 0) { r1[w] = s1; r2[w] = s2; }
    __syncthreads();
    s1 = r1[0] + r1[1] + r1[2] + r1[3];
    s2 = r2[0] + r2[1] + r2[2] + r2[3];
    float mean = s1 * (1.f / 512.f);
    float var  = s2 * (1.f / 512.f) - mean * mean;
    float rstd = rsqrtf(var + 1e-5f);
    float4 g4 = ((const float4*)gam)[tid];
    float4 b4 = ((const float4*)bet)[tid];
    float4 o;
    o.x = (v.x - mean) * rstd * g4.x + b4.x;
    o.y = (v.y - mean) * rstd * g4.y + b4.y;
    o.z = (v.z - mean) * rstd * g4.z + b4.z;
    o.w = (v.w - mean) * rstd * g4.w + b4.w;
    ((float4*)g_xn)[(size_t)row * 128 + tid] = o;
    __half2* ph = (__half2*)(g_A16 + (size_t)row * 512 + tid * 4);
    ph[0] = __floats2half2_rn(o.x, o.y);
    ph[1] = __floats2half2_rn(o.z, o.w);
}

// ================= fused: group means of xn -> bf16 hi/lo =================
__global__ void xnlm_conv_kernel() {
    int idx = blockIdx.x * 256 + threadIdx.x;
    int row = idx >> 9;
    int d = idx & 511;
    int b = row >> 8, m = row & 255;
    const float* p = g_xn + ((size_t)(b * NSEQ) + m * LGRP) * DIMV + d;
    float s = 0.f;
#pragma unroll
    for (int i = 0; i < LGRP; i++) s += p[(size_t)i * DIMV];
    float val = s * (1.f / LGRP);
    __nv_bfloat16 h = __float2bfloat16(val);
    g_Ahi[idx] = h;
    g_Alo[idx] = __float2bfloat16(val - __bfloat162float(h));
}

// ================= converters =================
__global__ __launch_bounds__(1024) void convW_kernel(const float* __restrict__ W, int N,
                                                     __nv_bfloat16* __restrict__ BThi,
                                                     __nv_bfloat16* __restrict__ BTlo) {
    __shared__ float sh[32][33];
    int n0 = blockIdx.x * 32, k0 = blockIdx.y * 32;
    int tx = threadIdx.x & 31, ty = threadIdx.x >> 5;
    sh[ty][tx] = W[(size_t)(k0 + ty) * N + n0 + tx];
    __syncthreads();
    float x = sh[tx][ty];
    __nv_bfloat16 h = __float2bfloat16(x);
    __nv_bfloat16 l = __float2bfloat16(x - __bfloat162float(h));
    BThi[(size_t)(n0 + ty) * 512 + k0 + tx] = h;
    BTlo[(size_t)(n0 + ty) * 512 + k0 + tx] = l;
}

__global__ __launch_bounds__(1024) void convW16_kernel(const float* __restrict__ W, int N,
                                                       __half* __restrict__ BT) {
    __shared__ float sh[32][33];
    int n0 = blockIdx.x * 32, k0 = blockIdx.y * 32;
    int tx = threadIdx.x & 31, ty = threadIdx.x >> 5;
    sh[ty][tx] = W[(size_t)(k0 + ty) * N + n0 + tx];
    __syncthreads();
    BT[(size_t)(n0 + ty) * 512 + k0 + tx] = __float2half(sh[tx][ty]);
}

// ================= fp16 single-pass dense GEMM (cp.async double-buffered) =================
// ntOff: N-tile offset (tiles of 128) so qkv can be split into kv / q launches.
__global__ __launch_bounds__(256) void gemm16_kernel(
    const __half* __restrict__ gBbase, int mode, int ntOff,
    const float* __restrict__ bout, float* __restrict__ outp) {
    extern __shared__ char smdyn[];
    unsigned sbase = smem_u32(smdyn);
    int tid = threadIdx.x, lane = tid & 31, wid = tid >> 5;
    int wm = wid & 3, wn = wid >> 2;
    int mBase = blockIdx.y * 128, nBase = (blockIdx.x + ntOff) * 128;
    int lr = lane & 15, lh = lane >> 4;

    const __half* gA = g_A16 + (size_t)mBase * 512;
    const __half* gB = gBbase + (size_t)nBase * 512;

    float acc[2][8][4];
#pragma unroll
    for (int i = 0; i < 2; i++)
#pragma unroll
        for (int j = 0; j < 8; j++)
#pragma unroll
            for (int c = 0; c < 4; c++) acc[i][j][c] = 0.f;

    int r_ld = tid >> 1;
    int q2 = (tid & 1) * 4;

    auto load_stage = [&](int ch, unsigned st) {
#pragma unroll
        for (int u = 0; u < 4; u++) {
            unsigned soff = (unsigned)r_ld * 144u + (q2 + u) * 16u;
            size_t goff = (size_t)r_ld * 512 + ch * 64 + (q2 + u) * 8;
            cpasync16(sbase + st + soff, gA + goff);
            cpasync16(sbase + st + 18432u + soff, gB + goff);
        }
        CP_COMMIT();
    };

    load_stage(0, 0u);

    for (int ch = 0; ch < 8; ch++) {
        unsigned st = (unsigned)(ch & 1) * 36864u;
        if (ch + 1 < 8) {
            load_stage(ch + 1, (unsigned)((ch + 1) & 1) * 36864u);
            asm volatile("cp.async.wait_group 1;" ::: "memory");
        } else {
            asm volatile("cp.async.wait_group 0;" ::: "memory");
        }
        __syncthreads();

        unsigned aA = sbase + st;
        unsigned aB = aA + 18432u;
#pragma unroll
        for (int ks = 0; ks < 4; ks++) {
            unsigned kc2 = (unsigned)(ks * 16 + lh * 8) * 2u;
            unsigned ah[2][4];
#pragma unroll
            for (int mi = 0; mi < 2; mi++) {
                unsigned rowA = (unsigned)(wm * 32 + mi * 16 + lr) * 144u;
                ldm4(ah[mi], aA + rowA + kc2);
            }
#pragma unroll
            for (int nt = 0; nt < 4; nt++) {
                unsigned rowB = (unsigned)(wn * 64 + nt * 16 + lr) * 144u;
                unsigned bf[4];
                ldm4(bf, aB + rowB + kc2);
#pragma unroll
                for (int mi = 0; mi < 2; mi++) {
#pragma unroll
                    for (int ns = 0; ns < 2; ns++)
                        mmaf16(acc[mi][nt * 2 + ns], ah[mi], bf[ns], bf[ns + 2]);
                }
            }
        }
        __syncthreads();
    }

    int r0 = mBase + wm * 32 + (lane >> 2);
    if (mode == 0) {
        int sec = nBase >> 9;
        float sc = (sec == 0) ? SCALE : 1.f;
        __half* hdst = (sec == 0) ? g_qh : ((sec == 1) ? g_kh : g_vh);
        int h = ((nBase + wn * 64) >> 6) & 7;
#pragma unroll
        for (int mi = 0; mi < 2; mi++) {
#pragma unroll
            for (int jn = 0; jn < 8; jn++) {
                int d = jn * 8 + (lane & 3) * 2;
#pragma unroll
                for (int half = 0; half < 2; half++) {
                    int gr = r0 + mi * 16 + half * 8;
                    int bb = gr >> 13, n = gr & 8191;
                    size_t off = ((size_t)(bb * 8 + h) * NSEQ + n) * 64 + d;
                    *(__half2*)&hdst[off] = __floats2half2_rn(acc[mi][jn][half * 2] * sc,
                                                              acc[mi][jn][half * 2 + 1] * sc);
                }
            }
        }
    } else {
#pragma unroll
        for (int mi = 0; mi < 2; mi++) {
#pragma unroll
            for (int jn = 0; jn < 8; jn++) {
                int gc = nBase + wn * 64 + jn * 8 + (lane & 3) * 2;
#pragma unroll
                for (int half = 0; half < 2; half++) {
                    int gr = r0 + mi * 16 + half * 8;
                    float2 bo = *(const float2*)&bout[gc];
                    float2 xv = *(const float2*)&g_xn[(size_t)gr * 512 + gc];
                    float2 o = make_float2(acc[mi][jn][half * 2] + bo.x + xv.x,
                                           acc[mi][jn][half * 2 + 1] + bo.y + xv.y);
                    *(float2*)&outp[(size_t)gr * 512 + gc] = o;
                }
            }
        }
    }
}

// ================= bf16 split landmark GEMM (M=512, N=1024) =================
__global__ __launch_bounds__(256) void gemm_lm_kernel(
    const __nv_bfloat16* __restrict__ BThi, const __nv_bfloat16* __restrict__ BTlo) {
    extern __shared__ char smdyn[];
    unsigned sbase = smem_u32(smdyn);
    int tid = threadIdx.x, lane = tid & 31, wid = tid >> 5;
    int wm = wid & 3, wn = wid >> 2;
    int mBase = blockIdx.y * 128, nBase = blockIdx.x * 128;
    int lr = lane & 15, lh = lane >> 4;

    const __nv_bfloat16* gsrc[4];
    gsrc[0] = g_Ahi + (size_t)mBase * 512;
    gsrc[1] = g_Alo + (size_t)mBase * 512;
    gsrc[2] = BThi + (size_t)nBase * 512;
    gsrc[3] = BTlo + (size_t)nBase * 512;

    float acc[2][8][4];
#pragma unroll
    for (int i = 0; i < 2; i++)
#pragma unroll
        for (int j = 0; j < 8; j++)
#pragma unroll
            for (int c = 0; c < 4; c++) acc[i][j][c] = 0.f;

    int r_ld0 = tid >> 2, q_ld = tid & 3;
    unsigned so0 = (unsigned)r_ld0 * 80u + q_ld * 16u;
    unsigned so1 = (unsigned)(r_ld0 + 64) * 80u + q_ld * 16u;

    {
        size_t go0 = (size_t)r_ld0 * 512 + q_ld * 8;
        size_t go1 = (size_t)(r_ld0 + 64) * 512 + q_ld * 8;
#pragma unroll
        for (int a = 0; a < 4; a++) {
            cpasync16(sbase + a * 10240u + so0, gsrc[a] + go0);
            cpasync16(sbase + a * 10240u + so1, gsrc[a] + go1);
        }
        CP_COMMIT();
    }

    for (int ch = 0; ch < 16; ch++) {
        unsigned st = (unsigned)(ch & 1) * 40960u;
        if (ch + 1 < 16) {
            unsigned stn = (unsigned)((ch + 1) & 1) * 40960u;
            size_t go0 = (size_t)r_ld0 * 512 + (ch + 1) * 32 + q_ld * 8;
            size_t go1 = (size_t)(r_ld0 + 64) * 512 + (ch + 1) * 32 + q_ld * 8;
#pragma unroll
            for (int a = 0; a < 4; a++) {
                cpasync16(sbase + stn + a * 10240u + so0, gsrc[a] + go0);
                cpasync16(sbase + stn + a * 10240u + so1, gsrc[a] + go1);
            }
            CP_COMMIT();
            asm volatile("cp.async.wait_group 1;" ::: "memory");
        } else {
            asm volatile("cp.async.wait_group 0;" ::: "memory");
        }
        __syncthreads();

        unsigned aAh = sbase + st;
        unsigned aAl = aAh + 10240u;
        unsigned aBh = aAh + 20480u;
        unsigned aBl = aAh + 30720u;
#pragma unroll
        for (int ks = 0; ks < 2; ks++) {
            unsigned kc2 = (unsigned)(ks * 16 + lh * 8) * 2u;
            unsigned ah[2][4], al[2][4];
#pragma unroll
            for (int mi = 0; mi < 2; mi++) {
                unsigned rowA = (unsigned)(wm * 32 + mi * 16 + lr) * 80u;
                ldm4(ah[mi], aAh + rowA + kc2);
                ldm4(al[mi], aAl + rowA + kc2);
            }
#pragma unroll
            for (int nt = 0; nt < 4; nt++) {
                unsigned rowB = (unsigned)(wn * 64 + nt * 16 + lr) * 80u;
                unsigned bh[4], bl[4];
                ldm4(bh, aBh + rowB + kc2);
                ldm4(bl, aBl + rowB + kc2);
#pragma unroll
                for (int mi = 0; mi < 2; mi++) {
#pragma unroll
                    for (int ns = 0; ns < 2; ns++) {
                        float* cc = acc[mi][nt * 2 + ns];
                        mma16816(cc, ah[mi], bh[ns], bh[ns + 2]);
                        mma16816(cc, ah[mi], bl[ns], bl[ns + 2]);
                        mma16816(cc, al[mi], bh[ns], bh[ns + 2]);
                    }
                }
            }
        }
        __syncthreads();
    }

    int r0 = mBase + wm * 32 + (lane >> 2);
    int sec = nBase >> 9;
    float sc = (sec == 0) ? SCALE : 1.f;
    float* dst = (sec == 0) ? g_ql : g_kl;
    __half* hdst = (sec == 0) ? g_qlh : g_klh;
    int h = ((nBase + wn * 64) >> 6) & 7;
#pragma unroll
    for (int mi = 0; mi < 2; mi++) {
#pragma unroll
        for (int jn = 0; jn < 8; jn++) {
            int d = jn * 8 + (lane & 3) * 2;
#pragma unroll
            for (int half = 0; half < 2; half++) {
                int gr = r0 + mi * 16 + half * 8;
                int bb = gr >> 8, m = gr & 255;
                float2 o = make_float2(acc[mi][jn][half * 2] * sc,
                                       acc[mi][jn][half * 2 + 1] * sc);
                size_t off = ((size_t)(bb * 8 + h) * MLM + m) * 64 + d;
                *(float2*)&dst[off] = o;
                *(__half2*)&hdst[off] = __floats2half2_rn(o.x, o.y);
            }
        }
    }
}

// ================= attn2 = softmax(q_l k_l^T), 64 CTAs =================
__global__ __launch_bounds__(256) void attn2_kernel() {
    extern __shared__ float sklf[];
    int rt = blockIdx.x, bh = blockIdx.y;
    int tid = threadIdx.x;
    int row = rt * 64 + (tid >> 2);
    int cg = tid & 3;

    const float4* klsrc = (const float4*)(g_kl + (size_t)bh * MLM * 64);
    float4* kld = (float4*)sklf;
#pragma unroll
    for (int i = 0; i < 16; i++) kld[tid + i * 256] = klsrc[tid + i * 256];

    float4 q[16];
    const float4* qp = (const float4*)(g_ql + (size_t)(bh * MLM + row) * 64);
#pragma unroll
    for (int i = 0; i < 16; i++) q[i] = qp[i];
    __syncthreads();

    float p[64];
    float sum = 0.f;
    const float4* klb = (const float4*)sklf + cg * 64 * 16;
    for (int j = 0; j < 64; j++) {
        const float4* kr = klb + j * 16;
        float s = 0.f;
#pragma unroll
        for (int d = 0; d < 16; d++) {
            float4 a = q[d], b = kr[d];
            s += a.x * b.x + a.y * b.y + a.z * b.z + a.w * b.w;
        }
        p[j] = __expf(s);
        sum += p[j];
    }
    sum += __shfl_xor_sync(0xffffffffu, sum, 1);
    sum += __shfl_xor_sync(0xffffffffu, sum, 2);
    float inv = 1.f / sum;
    float* arow = g_attn2 + (size_t)bh * 65536 + (size_t)row * 256 + cg * 64;
#pragma unroll
    for (int j = 0; j < 64; j += 4)
        *(float4*)&arow[j] = make_float4(p[j] * inv, p[j + 1] * inv,
                                         p[j + 2] * inv, p[j + 3] * inv);
}

// ================= max column-sum of attn2 =================
__global__ __launch_bounds__(256) void colmax_kernel() {
    int bh = blockIdx.x;
    int j = threadIdx.x;
    const float* a = g_attn2 + (size_t)bh * 65536;
    float s = 0.f;
    for (int m2 = 0; m2 < 256; m2++) s += a[m2 * 256 + j];
    __shared__ float red[256];
    red[j] = s;
    __syncthreads();
    for (int o = 128; o; o >>= 1) {
        if (j < o) red[j] = fmaxf(red[j], red[j + o]);
        __syncthreads();
    }
    if (j == 0) atomicMax(&g_maxc_bits, __float_as_int(red[0]));
}

__global__ void z0_kernel() {
    int idx = blockIdx.x * 256 + threadIdx.x;
    int bh = idx >> 16;
    int i = (idx >> 8) & 255;
    int j = idx & 255;
    float scale = 1.f / __int_as_float(g_maxc_bits);
    g_Za[idx] = g_attn2[(bh << 16) + (j << 8) + i] * scale;
}

// ================= buffer selector =================
__device__ __forceinline__ float* pickBuf(int id) {
    switch (id) {
        case 0: return g_attn2;
        case 1: return g_Y;
        case 2: return g_P;
        case 3: return g_Qm;
        case 4: return g_Za;
        default: return g_Zb;
    }
}

// ================= persistent pinv with register-prefetch pipelining =================
struct PinvSmem {
    __nv_bfloat16 Ah[128][40];
    __nv_bfloat16 Al[128][40];
    __nv_bfloat16 Bh[64][40];
    __nv_bfloat16 Bl[64][40];
};

__device__ __forceinline__ void gbarrier(int step) {
    __syncthreads();
    if (threadIdx.x == 0) {
        __threadfence();
        atomicAdd(&g_bar, 1u);
        unsigned target = 128u * (unsigned)step;
        while (*(volatile unsigned*)&g_bar < target) { }
    }
    __syncthreads();
}

__device__ void pinv_gemm(PinvSmem& S, int cId, int aId, int bId,
                          float beta, float sgn, float alpha, bool full,
                          int mBase, int nBase, int bh) {
    const float* A = pickBuf(aId) + (size_t)bh * 65536;
    const float* B = pickBuf(bId) + (size_t)bh * 65536;
    float*       C = pickBuf(cId) + (size_t)bh * 65536;

    int tid = threadIdx.x, lane = tid & 31, w = tid >> 5;
    int wm = w & 3, wn = w >> 2;
    int lr = lane & 15, lh = lane >> 4;

    float acc[2][4][4];
#pragma unroll
    for (int i = 0; i < 2; i++)
#pragma unroll
        for (int j = 0; j < 4; j++)
#pragma unroll
            for (int c = 0; c < 4; c++) acc[i][j][c] = 0.f;

    float4 rA[4];
    float rB[8];
    auto loadA = [&](int ch, float4* ra) {
#pragma unroll
        for (int i = 0; i < 4; i++) {
            int idx = tid + i * 256;
            int r = idx >> 3, c4 = (idx & 7) * 4;
            ra[i] = __ldcg((const float4*)&A[(size_t)(mBase + r) * 256 + ch * 32 + c4]);
        }
    };
    auto loadB = [&](int ch, float* rb) {
#pragma unroll
        for (int kl = 0; kl < 4; kl++) {
            int gk = ch * 32 + w * 4 + kl;
#pragma unroll
            for (int nh = 0; nh < 2; nh++) {
                int n = nh * 32 + lane;
                rb[kl * 2 + nh] = __ldcg(&B[(size_t)gk * 256 + nBase + n]);
            }
        }
    };

    loadA(0, rA);
    loadB(0, rB);

    for (int ch = 0; ch < 8; ch++) {
        if (ch) __syncthreads();
#pragma unroll
        for (int i = 0; i < 4; i++) {
            int idx = tid + i * 256;
            int r = idx >> 3, c4 = (idx & 7) * 4;
            float4 v = rA[i];
            __nv_bfloat16 h0 = __float2bfloat16(v.x), h1 = __float2bfloat16(v.y);
            __nv_bfloat16 h2 = __float2bfloat16(v.z), h3 = __float2bfloat16(v.w);
            S.Ah[r][c4 + 0] = h0; S.Ah[r][c4 + 1] = h1;
            S.Ah[r][c4 + 2] = h2; S.Ah[r][c4 + 3] = h3;
            if (full) {
                S.Al[r][c4 + 0] = __float2bfloat16(v.x - __bfloat162float(h0));
                S.Al[r][c4 + 1] = __float2bfloat16(v.y - __bfloat162float(h1));
                S.Al[r][c4 + 2] = __float2bfloat16(v.z - __bfloat162float(h2));
                S.Al[r][c4 + 3] = __float2bfloat16(v.w - __bfloat162float(h3));
            }
        }
#pragma unroll
        for (int kl = 0; kl < 4; kl++) {
            int gk = ch * 32 + w * 4 + kl;
#pragma unroll
            for (int nh = 0; nh < 2; nh++) {
                int n = nh * 32 + lane;
                float v = rB[kl * 2 + nh];
                v = sgn * v + ((gk == nBase + n) ? beta : 0.f);
                __nv_bfloat16 h = __float2bfloat16(v);
                S.Bh[n][w * 4 + kl] = h;
                if (full) S.Bl[n][w * 4 + kl] = __float2bfloat16(v - __bfloat162float(h));
            }
        }
        float4 rA2[4];
        float rB2[8];
        if (ch + 1 < 8) {
            loadA(ch + 1, rA2);
            loadB(ch + 1, rB2);
        }
        __syncthreads();
#pragma unroll
        for (int ks = 0; ks < 2; ks++) {
            int kc = ks * 16 + lh * 8;
            unsigned ah[2][4], al[2][4];
#pragma unroll
            for (int mi = 0; mi < 2; mi++) {
                int rowA = wm * 32 + mi * 16 + lr;
                ldm4(ah[mi], smem_u32(&S.Ah[rowA][kc]));
                if (full) ldm4(al[mi], smem_u32(&S.Al[rowA][kc]));
            }
#pragma unroll
            for (int nt = 0; nt < 2; nt++) {
                int rowB = wn * 32 + nt * 16 + lr;
                unsigned bhf[4], blf[4];
                ldm4(bhf, smem_u32(&S.Bh[rowB][kc]));
                if (full) ldm4(blf, smem_u32(&S.Bl[rowB][kc]));
#pragma unroll
                for (int mi = 0; mi < 2; mi++) {
#pragma unroll
                    for (int ns = 0; ns < 2; ns++) {
                        float* cc = acc[mi][nt * 2 + ns];
                        mma16816(cc, ah[mi], bhf[ns], bhf[ns + 2]);
                        if (full) {
                            mma16816(cc, ah[mi], blf[ns], blf[ns + 2]);
                            mma16816(cc, al[mi], bhf[ns], bhf[ns + 2]);
                        }
                    }
                }
            }
        }
        if (ch + 1 < 8) {
#pragma unroll
            for (int i = 0; i < 4; i++) rA[i] = rA2[i];
#pragma unroll
            for (int i = 0; i < 8; i++) rB[i] = rB2[i];
        }
    }
#pragma unroll
    for (int mi = 0; mi < 2; mi++) {
#pragma unroll
        for (int jn = 0; jn < 4; jn++) {
            int gc = nBase + wn * 32 + jn * 8 + (lane & 3) * 2;
#pragma unroll
            for (int half = 0; half < 2; half++) {
                int gr = mBase + wm * 32 + mi * 16 + (lane >> 2) + half * 8;
                float2 o = make_float2(acc[mi][jn][half * 2] * alpha,
                                       acc[mi][jn][half * 2 + 1] * alpha);
                *(float2*)&C[(size_t)gr * 256 + gc] = o;
            }
        }
    }
}

__global__ __launch_bounds__(256) void pinv_persist() {
    __shared__ PinvSmem S;
    int bh = blockIdx.z;
    int mBase = blockIdx.y * 128, nBase = blockIdx.x * 64;
    int step = 0;
    for (int it = 0; it < 6; it++) {
        bool full = (it == 5);
        int zc = 4 + (it & 1), zn = 5 - (it & 1);
        pinv_gemm(S, 1, 0, zc, 0.f, 1.f, 1.f, full, mBase, nBase, bh);
        gbarrier(++step);
        pinv_gemm(S, 2, 1, 1, 7.f, -1.f, 1.f, full, mBase, nBase, bh);
        gbarrier(++step);
        pinv_gemm(S, 3, 1, 2, 15.f, -1.f, 1.f, full, mBase, nBase, bh);
        gbarrier(++step);
        pinv_gemm(S, zn, zc, 3, 13.f, -1.f, 0.25f, full, mBase, nBase, bh);
        gbarrier(++step);
    }
}

// ================= W3 GEMM: W3T(fp16, transposed) = Za @ W2 =================
__global__ __launch_bounds__(256) void gemm_w3_kernel() {
    int bh = blockIdx.z, mt = blockIdx.y;
    const float* A  = g_Za + (size_t)bh * 65536;
    const float* Bp = g_W2 + (size_t)bh * 256 * 64;
    __half*      C  = g_W3T + (size_t)bh * 64 * 256;
    __shared__ float As[16][64];
    __shared__ float Bs[16][64];
    int tid = threadIdx.x;
    int ar = tid >> 2, ac = (tid & 3) * 4;
    int br = tid >> 4, bc = (tid & 15) * 4;
    int ty = tid >> 4, tx = tid & 15;
    float acc[4][4];
#pragma unroll
    for (int i = 0; i < 4; i++)
#pragma unroll
        for (int j = 0; j < 4; j++) acc[i][j] = 0.f;

    for (int k0 = 0; k0 < 256; k0 += 16) {
        float4 av = *(const float4*)&A[(size_t)(mt * 64 + ar) * 256 + k0 + ac];
        As[ac + 0][ar] = av.x; As[ac + 1][ar] = av.y;
        As[ac + 2][ar] = av.z; As[ac + 3][ar] = av.w;
        float4 bv = *(const float4*)&Bp[(size_t)(k0 + br) * 64 + bc];
        *(float4*)&Bs[br][bc] = bv;
        __syncthreads();
#pragma unroll
        for (int kk = 0; kk < 16; kk++) {
            float4 a4 = *(const float4*)&As[kk][ty * 4];
            float4 b4 = *(const float4*)&Bs[kk][tx * 4];
            acc[0][0] += a4.x * b4.x; acc[0][1] += a4.x * b4.y; acc[0][2] += a4.x * b4.z; acc[0][3] += a4.x * b4.w;
            acc[1][0] += a4.y * b4.x; acc[1][1] += a4.y * b4.y; acc[1][2] += a4.y * b4.z; acc[1][3] += a4.y * b4.w;
            acc[2][0] += a4.z * b4.x; acc[2][1] += a4.z * b4.y; acc[2][2] += a4.z * b4.z; acc[2][3] += a4.z * b4.w;
            acc[3][0] += a4.w * b4.x; acc[3][1] += a4.w * b4.y; acc[3][2] += a4.w * b4.z; acc[3][3] += a4.w * b4.w;
        }
        __syncthreads();
    }
#pragma unroll
    for (int i = 0; i < 4; i++) {
        int m = mt * 64 + ty * 4 + i;
#pragma unroll
        for (int j = 0; j < 4; j++) {
            int d = tx * 4 + j;
            C[(size_t)d * 256 + m] = __float2half(acc[i][j]);
        }
    }
}

// ================= flash W2 on tensor cores =================
__global__ __launch_bounds__(256) void flash_w2_mma() {
    __shared__ __align__(16) __half sql[128][72];
    __shared__ __align__(16) __half sk[64][72];
    __shared__ __align__(16) __half svT[64][72];

    int tid = threadIdx.x, lane = tid & 31, w = tid >> 5;
    int chunk = blockIdx.x, mblk = blockIdx.y, bh = blockIdx.z;
    int lr = lane & 15, lh = lane >> 4;

    const __half* qlh = g_qlh + (size_t)(bh * MLM + mblk * 128) * 64;
#pragma unroll
    for (int i = 0; i < 4; i++) {
        int idx = tid + i * 256;
        int r = idx >> 3, c = (idx & 7) * 8;
        *(uint4*)&sql[r][c] = *(const uint4*)&qlh[(size_t)r * 64 + c];
    }
    __syncthreads();
    unsigned qa[4][4];
#pragma unroll
    for (int ks = 0; ks < 4; ks++)
        ldm4(qa[ks], smem_u32(&sql[w * 16 + lr][ks * 16 + lh * 8]));

    float outacc[8][4];
#pragma unroll
    for (int i = 0; i < 8; i++)
#pragma unroll
        for (int c = 0; c < 4; c++) outacc[i][c] = 0.f;
    float rsA = 0.f, rsB = 0.f;

    const __half* kb = g_kh + (size_t)bh * NSEQ * 64;
    const __half* vb = g_vh + (size_t)bh * NSEQ * 64;

    for (int it = 0; it < 32; it++) {
        int s0 = chunk * 2048 + it * 64;
        __syncthreads();
#pragma unroll
        for (int i = 0; i < 2; i++) {
            int idx = tid + i * 256;
            int r = idx >> 3, c = (idx & 7) * 8;
            *(uint4*)&sk[r][c] = *(const uint4*)&kb[(size_t)(s0 + r) * 64 + c];
            uint4 vv = *(const uint4*)&vb[(size_t)(s0 + r) * 64 + c];
            __half vh[8];
            *(uint4*)vh = vv;
#pragma unroll
            for (int j = 0; j < 8; j++) svT[c + j][r] = vh[j];
        }
        __syncthreads();
        float sf[8][4];
#pragma unroll
        for (int i = 0; i < 8; i++)
#pragma unroll
            for (int c = 0; c < 4; c++) sf[i][c] = 0.f;
#pragma unroll
        for (int ks = 0; ks < 4; ks++) {
#pragma unroll
            for (int nf4 = 0; nf4 < 4; nf4++) {
                unsigned bbf[4];
                ldm4(bbf, smem_u32(&sk[nf4 * 16 + lr][ks * 16 + lh * 8]));
                mmaf16(sf[nf4 * 2], qa[ks], bbf[0], bbf[2]);
                mmaf16(sf[nf4 * 2 + 1], qa[ks], bbf[1], bbf[3]);
            }
        }
#pragma unroll
        for (int nf = 0; nf < 8; nf++) {
            sf[nf][0] = fexp(sf[nf][0]); sf[nf][1] = fexp(sf[nf][1]);
            sf[nf][2] = fexp(sf[nf][2]); sf[nf][3] = fexp(sf[nf][3]);
            rsA += sf[nf][0] + sf[nf][1];
            rsB += sf[nf][2] + sf[nf][3];
        }
#pragma unroll
        for (int kk = 0; kk < 4; kk++) {
            unsigned pa[4];
            pa[0] = packh2(sf[2 * kk][0], sf[2 * kk][1]);
            pa[1] = packh2(sf[2 * kk][2], sf[2 * kk][3]);
            pa[2] = packh2(sf[2 * kk + 1][0], sf[2 * kk + 1][1]);
            pa[3] = packh2(sf[2 * kk + 1][2], sf[2 * kk + 1][3]);
#pragma unroll
            for (int nf4 = 0; nf4 < 4; nf4++) {
                unsigned bbf[4];
                ldm4(bbf, smem_u32(&svT[nf4 * 16 + lr][kk * 16 + lh * 8]));
                mmaf16(outacc[nf4 * 2], pa, bbf[0], bbf[2]);
                mmaf16(outacc[nf4 * 2 + 1], pa, bbf[1], bbf[3]);
            }
        }
    }
    rsA += __shfl_xor_sync(0xffffffffu, rsA, 1);
    rsA += __shfl_xor_sync(0xffffffffu, rsA, 2);
    rsB += __shfl_xor_sync(0xffffffffu, rsB, 1);
    rsB += __shfl_xor_sync(0xffffffffu, rsB, 2);

    int rA = mblk * 128 + w * 16 + (lane >> 2);
    int rB = rA + 8;
    float* wpA = g_Wpart + (size_t)((bh * 4 + chunk) * MLM + rA) * 64;
    float* wpB = g_Wpart + (size_t)((bh * 4 + chunk) * MLM + rB) * 64;
#pragma unroll
    for (int nf = 0; nf < 8; nf++) {
        int d = nf * 8 + (lane & 3) * 2;
        *(float2*)&wpA[d] = make_float2(outacc[nf][0], outacc[nf][1]);
        *(float2*)&wpB[d] = make_float2(outacc[nf][2], outacc[nf][3]);
    }
    if ((lane & 3) == 0) {
        g_Spart[(bh * 4 + chunk) * MLM + rA] = rsA;
        g_Spart[(bh * 4 + chunk) * MLM + rB] = rsB;
    }
}

__global__ void combine_w2_kernel() {
    int idx = blockIdx.x * 256 + threadIdx.x;
    int bh = idx >> 14;
    int m = (idx >> 6) & 255;
    int d = idx & 63;
    float num = 0.f, den = 0.f;
#pragma unroll
    for (int c = 0; c < 4; c++) {
        num += g_Wpart[(size_t)((bh * 4 + c) * MLM + m) * 64 + d];
        den += g_Spart[(bh * 4 + c) * MLM + m];
    }
    g_W2[(bh * MLM + m) * 64 + d] = num / den;
}

// ================= attn1 + conv on tensor cores (writes fp16 to g_A16) =================
__global__ __launch_bounds__(256) void attn1_mma(const float* __restrict__ convw) {
    extern __shared__ char smx[];
    __half (*sq)[72]  = (__half(*)[72])(smx);
    __half (*skl)[72] = (__half(*)[72])(smx + 18432);
    __half (*swT)[72] = (__half(*)[72])(smx + 27648);
    __half (*sv)[72]  = (__half(*)[72])(smx + 36864);
    float* cw = (float*)(smx + 59904);

    int tid = threadIdx.x, lane = tid & 31, w = tid >> 5;
    int ntile = blockIdx.x, bh = blockIdx.y;
    int h = bh & 7, bb2 = bh >> 3;
    int n0 = ntile * 128;
    int lr = lane & 15, lh = lane >> 4;

    if (tid < KSZ) cw[tid] = convw[h * KSZ + tid];

    const __half* qb = g_qh + ((size_t)bh * NSEQ + n0) * 64;
#pragma unroll
    for (int i = 0; i < 4; i++) {
        int idx = tid + i * 256;
        int r = idx >> 3, c = (idx & 7) * 8;
        *(uint4*)&sq[r][c] = *(const uint4*)&qb[(size_t)r * 64 + c];
    }
    const __half* vb2 = g_vh + (size_t)bh * NSEQ * 64;
#pragma unroll
    for (int i = 0; i < 5; i++) {
        int idx = tid + i * 256;
        int r = idx >> 3, c = (idx & 7) * 8;
        int gr = n0 - 16 + r;
        uint4 z = make_uint4(0u, 0u, 0u, 0u);
        if (gr >= 0 && gr < NSEQ) z = *(const uint4*)&vb2[(size_t)gr * 64 + c];
        *(uint4*)&sv[r][c] = z;
    }
    __syncthreads();

    unsigned qa[4][4];
#pragma unroll
    for (int ks = 0; ks < 4; ks++)
        ldm4(qa[ks], smem_u32(&sq[w * 16 + lr][ks * 16 + lh * 8]));

    float outacc[8][4];
#pragma unroll
    for (int i = 0; i < 8; i++)
#pragma unroll
        for (int c = 0; c < 4; c++) outacc[i][c] = 0.f;
    float rsA = 0.f, rsB = 0.f;

    const __half* klb = g_klh + (size_t)bh * MLM * 64;
    const __half* w3tb = g_W3T + (size_t)bh * 64 * 256;

    for (int lc = 0; lc < 4; lc++) {
        __syncthreads();
#pragma unroll
        for (int i = 0; i < 2; i++) {
            int idx = tid + i * 256;
            int r = idx >> 3, c = (idx & 7) * 8;
            *(uint4*)&skl[r][c] = *(const uint4*)&klb[(size_t)(lc * 64 + r) * 64 + c];
            *(uint4*)&swT[r][c] = *(const uint4*)&w3tb[(size_t)r * 256 + lc * 64 + c];
        }
        __syncthreads();
        float sf[8][4];
#pragma unroll
        for (int i = 0; i < 8; i++)
#pragma unroll
            for (int c = 0; c < 4; c++) sf[i][c] = 0.f;
#pragma unroll
        for (int ks = 0; ks < 4; ks++) {
#pragma unroll
            for (int nf4 = 0; nf4 < 4; nf4++) {
                unsigned bbf[4];
                ldm4(bbf, smem_u32(&skl[nf4 * 16 + lr][ks * 16 + lh * 8]));
                mmaf16(sf[nf4 * 2], qa[ks], bbf[0], bbf[2]);
                mmaf16(sf[nf4 * 2 + 1], qa[ks], bbf[1], bbf[3]);
            }
        }
#pragma unroll
        for (int nf = 0; nf < 8; nf++) {
            sf[nf][0] = fexp(sf[nf][0]); sf[nf][1] = fexp(sf[nf][1]);
            sf[nf][2] = fexp(sf[nf][2]); sf[nf][3] = fexp(sf[nf][3]);
            rsA += sf[nf][0] + sf[nf][1];
            rsB += sf[nf][2] + sf[nf][3];
        }
#pragma unroll
        for (int kk = 0; kk < 4; kk++) {
            unsigned pa[4];
            pa[0] = packh2(sf[2 * kk][0], sf[2 * kk][1]);
            pa[1] = packh2(sf[2 * kk][2], sf[2 * kk][3]);
            pa[2] = packh2(sf[2 * kk + 1][0], sf[2 * kk + 1][1]);
            pa[3] = packh2(sf[2 * kk + 1][2], sf[2 * kk + 1][3]);
#pragma unroll
            for (int nf4 = 0; nf4 < 4; nf4++) {
                unsigned bbf[4];
                ldm4(bbf, smem_u32(&swT[nf4 * 16 + lr][kk * 16 + lh * 8]));
                mmaf16(outacc[nf4 * 2], pa, bbf[0], bbf[2]);
                mmaf16(outacc[nf4 * 2 + 1], pa, bbf[1], bbf[3]);
            }
        }
    }
    rsA += __shfl_xor_sync(0xffffffffu, rsA, 1);
    rsA += __shfl_xor_sync(0xffffffffu, rsA, 2);
    rsB += __shfl_xor_sync(0xffffffffu, rsB, 1);
    rsB += __shfl_xor_sync(0xffffffffu, rsB, 2);
    float invA = 1.f / rsA, invB = 1.f / rsB;

    int lrA = w * 16 + (lane >> 2);
#pragma unroll
    for (int nf = 0; nf < 8; nf++) {
        int d = nf * 8 + (lane & 3) * 2;
        float a0 = 0.f, a1 = 0.f, b0 = 0.f, b1 = 0.f;
#pragma unroll
        for (int t = 0; t < KSZ; t++) {
            float wv = cw[t];
            float2 fA = __half22float2(*(__half2*)&sv[lrA + t][d]);
            float2 fB = __half22float2(*(__half2*)&sv[lrA + 8 + t][d]);
            a0 = fmaf(wv, fA.x, a0); a1 = fmaf(wv, fA.y, a1);
            b0 = fmaf(wv, fB.x, b0); b1 = fmaf(wv, fB.y, b1);
        }
        outacc[nf][0] = outacc[nf][0] * invA + a0;
        outacc[nf][1] = outacc[nf][1] * invA + a1;
        outacc[nf][2] = outacc[nf][2] * invB + b0;
        outacc[nf][3] = outacc[nf][3] * invB + b1;
    }

    int nA = n0 + lrA, nB = nA + 8;
    __half* oA = g_A16 + (size_t)(bb2 * NSEQ + nA) * 512 + h * 64;
    __half* oB = g_A16 + (size_t)(bb2 * NSEQ + nB) * 512 + h * 64;
#pragma unroll
    for (int nf = 0; nf < 8; nf++) {
        int d = nf * 8 + (lane & 3) * 2;
        *(__half2*)&oA[d] = __floats2half2_rn(outacc[nf][0], outacc[nf][1]);
        *(__half2*)&oB[d] = __floats2half2_rn(outacc[nf][2], outacc[nf][3]);
    }
}

// ================= host launcher (three-stream overlap) =================
extern "C" void kernel_launch(void* const* d_in, const int* in_sizes, int n_in,
                              void* d_out, int out_size) {
    const float* x     = (const float*)d_in[0];
    const float* ln_g  = (const float*)d_in[1];
    const float* ln_b  = (const float*)d_in[2];
    const float* W_qkv = (const float*)d_in[3];
    const float* W_out = (const float*)d_in[4];
    const float* b_out = (const float*)d_in[5];
    const float* convw = (const float*)d_in[6];
    float* out = (float*)d_out;

    static cudaStream_t sB = nullptr, sC = nullptr;
    static cudaEvent_t eFork = nullptr, eLm = nullptr, eJoin = nullptr,
                       eKV = nullptr, eW2 = nullptr;
    if (!sB) {
        cudaStreamCreateWithFlags(&sB, cudaStreamNonBlocking);
        cudaStreamCreateWithFlags(&sC, cudaStreamNonBlocking);
        cudaEventCreateWithFlags(&eFork, cudaEventDisableTiming);
        cudaEventCreateWithFlags(&eLm, cudaEventDisableTiming);
        cudaEventCreateWithFlags(&eJoin, cudaEventDisableTiming);
        cudaEventCreateWithFlags(&eKV, cudaEventDisableTiming);
        cudaEventCreateWithFlags(&eW2, cudaEventDisableTiming);
        cudaFuncSetAttribute(attn1_mma, cudaFuncAttributeMaxDynamicSharedMemorySize, 60416);
        cudaFuncSetAttribute(gemm_lm_kernel, cudaFuncAttributeMaxDynamicSharedMemorySize, 81920);
        cudaFuncSetAttribute(gemm16_kernel, cudaFuncAttributeMaxDynamicSharedMemorySize, 73728);
        cudaFuncSetAttribute(attn2_kernel, cudaFuncAttributeMaxDynamicSharedMemorySize, 65536);
    }

    __nv_bfloat16 *bqh, *bql;
    cudaGetSymbolAddress((void**)&bqh, g_Bqh);
    cudaGetSymbolAddress((void**)&bql, g_Bql);
    __half *b16q, *b16o;
    cudaGetSymbolAddress((void**)&b16q, g_B16q);
    cudaGetSymbolAddress((void**)&b16o, g_B16o);

    ln_kernel<<<Bb * NSEQ, 128>>>(x, ln_g, ln_b);  // g_xn + g_A16 + resets

    // ---- fork ----
    cudaEventRecord(eFork, 0);
    cudaStreamWaitEvent(sB, eFork, 0);

    // Chain B (stream sB): landmark path -> attn2 -> z0 -> persistent pinv
    xnlm_conv_kernel<<<1024, 256, 0, sB>>>();
    convW_kernel<<<dim3(48, 16), 1024, 0, sB>>>(W_qkv, 1536, bqh, bql);
    gemm_lm_kernel<<<dim3(8, 4), 256, 81920, sB>>>(bqh, bql);
    cudaEventRecord(eLm, sB);
    attn2_kernel<<<dim3(4, 16), 256, 65536, sB>>>();
    colmax_kernel<<<16, 256, 0, sB>>>();
    z0_kernel<<<4096, 256, 0, sB>>>();
    pinv_persist<<<dim3(4, 2, 16), 256, 0, sB>>>();
    cudaEventRecord(eJoin, sB);

    // Chain A (default stream): kv GEMM first, then q GEMM (overlaps flash_w2)
    convW16_kernel<<<dim3(48, 16), 1024>>>(W_qkv, 1536, b16q);
    gemm16_kernel<<<dim3(8, 128), 256, 73728>>>(b16q, 0, 4, nullptr, nullptr);  // k, v
    cudaEventRecord(eKV, 0);
    gemm16_kernel<<<dim3(4, 128), 256, 73728>>>(b16q, 0, 0, nullptr, nullptr);  // q
    convW16_kernel<<<dim3(16, 16), 1024>>>(W_out, 512, b16o);

    // Chain C (stream sC): flash_w2 as soon as kv + landmarks are ready
    cudaStreamWaitEvent(sC, eKV, 0);
    cudaStreamWaitEvent(sC, eLm, 0);
    flash_w2_mma<<<dim3(4, 2, 16), 256, 0, sC>>>();
    combine_w2_kernel<<<1024, 256, 0, sC>>>();
    cudaEventRecord(eW2, sC);

    // ---- join on default stream ----
    cudaStreamWaitEvent(0, eW2, 0);
    cudaStreamWaitEvent(0, eJoin, 0);
    gemm_w3_kernel<<<dim3(1, 4, 16), 256>>>();
    attn1_mma<<<dim3(64, 16), 256, 60416>>>(convw);

    gemm16_kernel<<<dim3(4, 128), 256, 73728>>>(b16o, 1, 0, b_out, out);
}

// round 16
// speedup vs baseline: 1.5304x; 1.0420x over previous
#include <cuda_runtime.h>
#include <cuda_bf16.h>
#include <cuda_fp16.h>

#define Bb    2
#define NSEQ  8192
#define DIMV  512
#define NH    8
#define BHn   16
#define DHd   64
#define MLM   256
#define LGRP  32
#define KSZ   33
#define PADc  16
#define SCALE 0.125f

// ================= static device scratch =================
__device__ float g_xn[(size_t)Bb * NSEQ * DIMV];
__device__ float g_ql[BHn * MLM * DHd];
__device__ float g_kl[BHn * MLM * DHd];
__device__ float g_attn2[BHn * MLM * MLM];
__device__ float g_Y[BHn * MLM * MLM];
__device__ float g_P[BHn * MLM * MLM];
__device__ float g_Qm[BHn * MLM * MLM];
__device__ float g_Za[BHn * MLM * MLM];
__device__ float g_Zb[BHn * MLM * MLM];
__device__ float g_W2[BHn * MLM * DHd];
__device__ float g_Wpart[(size_t)BHn * 4 * MLM * DHd];
__device__ float g_Spart[BHn * 4 * MLM];
__device__ int   g_maxc_bits;
__device__ unsigned g_bar;

// bf16 hi/lo buffers (landmark GEMM)
__device__ __nv_bfloat16 g_Ahi[512 * 512];
__device__ __nv_bfloat16 g_Alo[512 * 512];
__device__ __nv_bfloat16 g_Bqh[1536 * 512];
__device__ __nv_bfloat16 g_Bql[1536 * 512];

// fp16 buffers
__device__ __half g_A16[(size_t)Bb * NSEQ * DIMV];
__device__ __half g_B16q[1536 * 512];
__device__ __half g_B16o[512 * 512];
__device__ __half g_qh[(size_t)BHn * NSEQ * DHd];
__device__ __half g_kh[(size_t)BHn * NSEQ * DHd];
__device__ __half g_vh[(size_t)BHn * NSEQ * DHd];
__device__ __half g_qlh[BHn * MLM * DHd];
__device__ __half g_klh[BHn * MLM * DHd];
__device__ __half g_W3h[BHn * MLM * DHd];   // row-major [m][d] fp16

// ================= mma.sync helpers =================
__device__ __forceinline__ unsigned smem_u32(const void* p) {
    unsigned a;
    asm("{ .reg .u64 t; cvta.to.shared.u64 t, %1; cvt.u32.u64 %0, t; }" : "=r"(a) : "l"(p));
    return a;
}
__device__ __forceinline__ void ldm4(unsigned* r, unsigned addr) {
    asm volatile("ldmatrix.sync.aligned.m8n8.x4.shared.b16 {%0,%1,%2,%3}, [%4];"
        : "=r"(r[0]), "=r"(r[1]), "=r"(r[2]), "=r"(r[3]) : "r"(addr));
}
__device__ __forceinline__ void ldm4t(unsigned* r, unsigned addr) {
    asm volatile("ldmatrix.sync.aligned.m8n8.x4.trans.shared.b16 {%0,%1,%2,%3}, [%4];"
        : "=r"(r[0]), "=r"(r[1]), "=r"(r[2]), "=r"(r[3]) : "r"(addr));
}
__device__ __forceinline__ void mma16816(float* c, const unsigned* a, unsigned b0, unsigned b1) {
    asm volatile("mma.sync.aligned.m16n8k16.row.col.f32.bf16.bf16.f32 "
        "{%0,%1,%2,%3}, {%4,%5,%6,%7}, {%8,%9}, {%0,%1,%2,%3};"
        : "+f"(c[0]), "+f"(c[1]), "+f"(c[2]), "+f"(c[3])
        : "r"(a[0]), "r"(a[1]), "r"(a[2]), "r"(a[3]), "r"(b0), "r"(b1));
}
__device__ __forceinline__ void mmaf16(float* c, const unsigned* a, unsigned b0, unsigned b1) {
    asm volatile("mma.sync.aligned.m16n8k16.row.col.f32.f16.f16.f32 "
        "{%0,%1,%2,%3}, {%4,%5,%6,%7}, {%8,%9}, {%0,%1,%2,%3};"
        : "+f"(c[0]), "+f"(c[1]), "+f"(c[2]), "+f"(c[3])
        : "r"(a[0]), "r"(a[1]), "r"(a[2]), "r"(a[3]), "r"(b0), "r"(b1));
}
__device__ __forceinline__ void cpasync16(unsigned dst, const void* src) {
    asm volatile("cp.async.cg.shared.global [%0], [%1], 16;" :: "r"(dst), "l"(src));
}
#define CP_COMMIT() asm volatile("cp.async.commit_group;" ::: "memory")
__device__ __forceinline__ unsigned packh2(float a, float b) {
    __half2 h = __floats2half2_rn(a, b);
    return *(unsigned*)&h;
}
__device__ __forceinline__ float fexp(float x) {
    float t = x * 1.44269504f;
    float r = rintf(t);
    float f = t - r;
    float p = 1.33336e-3f;
    p = fmaf(p, f, 9.61813e-3f);
    p = fmaf(p, f, 5.55041e-2f);
    p = fmaf(p, f, 2.40226507e-1f);
    p = fmaf(p, f, 6.93147181e-1f);
    p = fmaf(p, f, 1.0f);
    int e = (int)r;
    return p * __int_as_float((e + 127) << 23);
}

// ================= layernorm (writes fp32 + fp16; also resets globals) =================
__global__ __launch_bounds__(128) void ln_kernel(const float* __restrict__ x,
                                                 const float* __restrict__ gam,
                                                 const float* __restrict__ bet) {
    if (blockIdx.x == 0 && threadIdx.x == 0) { g_maxc_bits = 0; g_bar = 0u; }
    int row = blockIdx.x;
    int tid = threadIdx.x;
    float4 v = ((const float4*)x)[(size_t)row * 128 + tid];
    float s1 = v.x + v.y + v.z + v.w;
    float s2 = v.x * v.x + v.y * v.y + v.z * v.z + v.w * v.w;
#pragma unroll
    for (int o = 16; o; o >>= 1) {
        s1 += __shfl_xor_sync(0xffffffffu, s1, o);
        s2 += __shfl_xor_sync(0xffffffffu, s2, o);
    }
    __shared__ float r1[4], r2[4];
    int w = tid >> 5;
    if ((tid & 31) == 0) { r1[w] = s1; r2[w] = s2; }
    __syncthreads();
    s1 = r1[0] + r1[1] + r1[2] + r1[3];
    s2 = r2[0] + r2[1] + r2[2] + r2[3];
    float mean = s1 * (1.f / 512.f);
    float var  = s2 * (1.f / 512.f) - mean * mean;
    float rstd = rsqrtf(var + 1e-5f);
    float4 g4 = ((const float4*)gam)[tid];
    float4 b4 = ((const float4*)bet)[tid];
    float4 o;
    o.x = (v.x - mean) * rstd * g4.x + b4.x;
    o.y = (v.y - mean) * rstd * g4.y + b4.y;
    o.z = (v.z - mean) * rstd * g4.z + b4.z;
    o.w = (v.w - mean) * rstd * g4.w + b4.w;
    ((float4*)g_xn)[(size_t)row * 128 + tid] = o;
    __half2* ph = (__half2*)(g_A16 + (size_t)row * 512 + tid * 4);
    ph[0] = __floats2half2_rn(o.x, o.y);
    ph[1] = __floats2half2_rn(o.z, o.w);
}

// ================= fused: group means of xn -> bf16 hi/lo =================
__global__ void xnlm_conv_kernel() {
    int idx = blockIdx.x * 256 + threadIdx.x;
    int row = idx >> 9;
    int d = idx & 511;
    int b = row >> 8, m = row & 255;
    const float* p = g_xn + ((size_t)(b * NSEQ) + m * LGRP) * DIMV + d;
    float s = 0.f;
#pragma unroll
    for (int i = 0; i < LGRP; i++) s += p[(size_t)i * DIMV];
    float val = s * (1.f / LGRP);
    __nv_bfloat16 h = __float2bfloat16(val);
    g_Ahi[idx] = h;
    g_Alo[idx] = __float2bfloat16(val - __bfloat162float(h));
}

// ================= converters =================
__global__ __launch_bounds__(1024) void convW_kernel(const float* __restrict__ W, int N,
                                                     __nv_bfloat16* __restrict__ BThi,
                                                     __nv_bfloat16* __restrict__ BTlo) {
    __shared__ float sh[32][33];
    int n0 = blockIdx.x * 32, k0 = blockIdx.y * 32;
    int tx = threadIdx.x & 31, ty = threadIdx.x >> 5;
    sh[ty][tx] = W[(size_t)(k0 + ty) * N + n0 + tx];
    __syncthreads();
    float x = sh[tx][ty];
    __nv_bfloat16 h = __float2bfloat16(x);
    __nv_bfloat16 l = __float2bfloat16(x - __bfloat162float(h));
    BThi[(size_t)(n0 + ty) * 512 + k0 + tx] = h;
    BTlo[(size_t)(n0 + ty) * 512 + k0 + tx] = l;
}

__global__ __launch_bounds__(1024) void convW16_kernel(const float* __restrict__ W, int N,
                                                       __half* __restrict__ BT) {
    __shared__ float sh[32][33];
    int n0 = blockIdx.x * 32, k0 = blockIdx.y * 32;
    int tx = threadIdx.x & 31, ty = threadIdx.x >> 5;
    sh[ty][tx] = W[(size_t)(k0 + ty) * N + n0 + tx];
    __syncthreads();
    BT[(size_t)(n0 + ty) * 512 + k0 + tx] = __float2half(sh[tx][ty]);
}

// ================= fp16 single-pass dense GEMM (cp.async double-buffered) =================
__global__ __launch_bounds__(256) void gemm16_kernel(
    const __half* __restrict__ gBbase, int mode, int ntOff,
    const float* __restrict__ bout, float* __restrict__ outp) {
    extern __shared__ char smdyn[];
    unsigned sbase = smem_u32(smdyn);
    int tid = threadIdx.x, lane = tid & 31, wid = tid >> 5;
    int wm = wid & 3, wn = wid >> 2;
    int mBase = blockIdx.y * 128, nBase = (blockIdx.x + ntOff) * 128;
    int lr = lane & 15, lh = lane >> 4;

    const __half* gA = g_A16 + (size_t)mBase * 512;
    const __half* gB = gBbase + (size_t)nBase * 512;

    float acc[2][8][4];
#pragma unroll
    for (int i = 0; i < 2; i++)
#pragma unroll
        for (int j = 0; j < 8; j++)
#pragma unroll
            for (int c = 0; c < 4; c++) acc[i][j][c] = 0.f;

    int r_ld = tid >> 1;
    int q2 = (tid & 1) * 4;

    auto load_stage = [&](int ch, unsigned st) {
#pragma unroll
        for (int u = 0; u < 4; u++) {
            unsigned soff = (unsigned)r_ld * 144u + (q2 + u) * 16u;
            size_t goff = (size_t)r_ld * 512 + ch * 64 + (q2 + u) * 8;
            cpasync16(sbase + st + soff, gA + goff);
            cpasync16(sbase + st + 18432u + soff, gB + goff);
        }
        CP_COMMIT();
    };

    load_stage(0, 0u);

    for (int ch = 0; ch < 8; ch++) {
        unsigned st = (unsigned)(ch & 1) * 36864u;
        if (ch + 1 < 8) {
            load_stage(ch + 1, (unsigned)((ch + 1) & 1) * 36864u);
            asm volatile("cp.async.wait_group 1;" ::: "memory");
        } else {
            asm volatile("cp.async.wait_group 0;" ::: "memory");
        }
        __syncthreads();

        unsigned aA = sbase + st;
        unsigned aB = aA + 18432u;
#pragma unroll
        for (int ks = 0; ks < 4; ks++) {
            unsigned kc2 = (unsigned)(ks * 16 + lh * 8) * 2u;
            unsigned ah[2][4];
#pragma unroll
            for (int mi = 0; mi < 2; mi++) {
                unsigned rowA = (unsigned)(wm * 32 + mi * 16 + lr) * 144u;
                ldm4(ah[mi], aA + rowA + kc2);
            }
#pragma unroll
            for (int nt = 0; nt < 4; nt++) {
                unsigned rowB = (unsigned)(wn * 64 + nt * 16 + lr) * 144u;
                unsigned bf[4];
                ldm4(bf, aB + rowB + kc2);
#pragma unroll
                for (int mi = 0; mi < 2; mi++) {
#pragma unroll
                    for (int ns = 0; ns < 2; ns++)
                        mmaf16(acc[mi][nt * 2 + ns], ah[mi], bf[ns], bf[ns + 2]);
                }
            }
        }
        __syncthreads();
    }

    int r0 = mBase + wm * 32 + (lane >> 2);
    if (mode == 0) {
        int sec = nBase >> 9;
        float sc = (sec == 0) ? SCALE : 1.f;
        __half* hdst = (sec == 0) ? g_qh : ((sec == 1) ? g_kh : g_vh);
        int h = ((nBase + wn * 64) >> 6) & 7;
#pragma unroll
        for (int mi = 0; mi < 2; mi++) {
#pragma unroll
            for (int jn = 0; jn < 8; jn++) {
                int d = jn * 8 + (lane & 3) * 2;
#pragma unroll
                for (int half = 0; half < 2; half++) {
                    int gr = r0 + mi * 16 + half * 8;
                    int bb = gr >> 13, n = gr & 8191;
                    size_t off = ((size_t)(bb * 8 + h) * NSEQ + n) * 64 + d;
                    *(__half2*)&hdst[off] = __floats2half2_rn(acc[mi][jn][half * 2] * sc,
                                                              acc[mi][jn][half * 2 + 1] * sc);
                }
            }
        }
    } else {
#pragma unroll
        for (int mi = 0; mi < 2; mi++) {
#pragma unroll
            for (int jn = 0; jn < 8; jn++) {
                int gc = nBase + wn * 64 + jn * 8 + (lane & 3) * 2;
#pragma unroll
                for (int half = 0; half < 2; half++) {
                    int gr = r0 + mi * 16 + half * 8;
                    float2 bo = *(const float2*)&bout[gc];
                    float2 xv = *(const float2*)&g_xn[(size_t)gr * 512 + gc];
                    float2 o = make_float2(acc[mi][jn][half * 2] + bo.x + xv.x,
                                           acc[mi][jn][half * 2 + 1] + bo.y + xv.y);
                    *(float2*)&outp[(size_t)gr * 512 + gc] = o;
                }
            }
        }
    }
}

// ================= bf16 split landmark GEMM (M=512, N=1024) =================
__global__ __launch_bounds__(256) void gemm_lm_kernel(
    const __nv_bfloat16* __restrict__ BThi, const __nv_bfloat16* __restrict__ BTlo) {
    extern __shared__ char smdyn[];
    unsigned sbase = smem_u32(smdyn);
    int tid = threadIdx.x, lane = tid & 31, wid = tid >> 5;
    int wm = wid & 3, wn = wid >> 2;
    int mBase = blockIdx.y * 128, nBase = blockIdx.x * 128;
    int lr = lane & 15, lh = lane >> 4;

    const __nv_bfloat16* gsrc[4];
    gsrc[0] = g_Ahi + (size_t)mBase * 512;
    gsrc[1] = g_Alo + (size_t)mBase * 512;
    gsrc[2] = BThi + (size_t)nBase * 512;
    gsrc[3] = BTlo + (size_t)nBase * 512;

    float acc[2][8][4];
#pragma unroll
    for (int i = 0; i < 2; i++)
#pragma unroll
        for (int j = 0; j < 8; j++)
#pragma unroll
            for (int c = 0; c < 4; c++) acc[i][j][c] = 0.f;

    int r_ld0 = tid >> 2, q_ld = tid & 3;
    unsigned so0 = (unsigned)r_ld0 * 80u + q_ld * 16u;
    unsigned so1 = (unsigned)(r_ld0 + 64) * 80u + q_ld * 16u;

    {
        size_t go0 = (size_t)r_ld0 * 512 + q_ld * 8;
        size_t go1 = (size_t)(r_ld0 + 64) * 512 + q_ld * 8;
#pragma unroll
        for (int a = 0; a < 4; a++) {
            cpasync16(sbase + a * 10240u + so0, gsrc[a] + go0);
            cpasync16(sbase + a * 10240u + so1, gsrc[a] + go1);
        }
        CP_COMMIT();
    }

    for (int ch = 0; ch < 16; ch++) {
        unsigned st = (unsigned)(ch & 1) * 40960u;
        if (ch + 1 < 16) {
            unsigned stn = (unsigned)((ch + 1) & 1) * 40960u;
            size_t go0 = (size_t)r_ld0 * 512 + (ch + 1) * 32 + q_ld * 8;
            size_t go1 = (size_t)(r_ld0 + 64) * 512 + (ch + 1) * 32 + q_ld * 8;
#pragma unroll
            for (int a = 0; a < 4; a++) {
                cpasync16(sbase + stn + a * 10240u + so0, gsrc[a] + go0);
                cpasync16(sbase + stn + a * 10240u + so1, gsrc[a] + go1);
            }
            CP_COMMIT();
            asm volatile("cp.async.wait_group 1;" ::: "memory");
        } else {
            asm volatile("cp.async.wait_group 0;" ::: "memory");
        }
        __syncthreads();

        unsigned aAh = sbase + st;
        unsigned aAl = aAh + 10240u;
        unsigned aBh = aAh + 20480u;
        unsigned aBl = aAh + 30720u;
#pragma unroll
        for (int ks = 0; ks < 2; ks++) {
            unsigned kc2 = (unsigned)(ks * 16 + lh * 8) * 2u;
            unsigned ah[2][4], al[2][4];
#pragma unroll
            for (int mi = 0; mi < 2; mi++) {
                unsigned rowA = (unsigned)(wm * 32 + mi * 16 + lr) * 80u;
                ldm4(ah[mi], aAh + rowA + kc2);
                ldm4(al[mi], aAl + rowA + kc2);
            }
#pragma unroll
            for (int nt = 0; nt < 4; nt++) {
                unsigned rowB = (unsigned)(wn * 64 + nt * 16 + lr) * 80u;
                unsigned bh[4], bl[4];
                ldm4(bh, aBh + rowB + kc2);
                ldm4(bl, aBl + rowB + kc2);
#pragma unroll
                for (int mi = 0; mi < 2; mi++) {
#pragma unroll
                    for (int ns = 0; ns < 2; ns++) {
                        float* cc = acc[mi][nt * 2 + ns];
                        mma16816(cc, ah[mi], bh[ns], bh[ns + 2]);
                        mma16816(cc, ah[mi], bl[ns], bl[ns + 2]);
                        mma16816(cc, al[mi], bh[ns], bh[ns + 2]);
                    }
                }
            }
        }
        __syncthreads();
    }

    int r0 = mBase + wm * 32 + (lane >> 2);
    int sec = nBase >> 9;
    float sc = (sec == 0) ? SCALE : 1.f;
    float* dst = (sec == 0) ? g_ql : g_kl;
    __half* hdst = (sec == 0) ? g_qlh : g_klh;
    int h = ((nBase + wn * 64) >> 6) & 7;
#pragma unroll
    for (int mi = 0; mi < 2; mi++) {
#pragma unroll
        for (int jn = 0; jn < 8; jn++) {
            int d = jn * 8 + (lane & 3) * 2;
#pragma unroll
            for (int half = 0; half < 2; half++) {
                int gr = r0 + mi * 16 + half * 8;
                int bb = gr >> 8, m = gr & 255;
                float2 o = make_float2(acc[mi][jn][half * 2] * sc,
                                       acc[mi][jn][half * 2 + 1] * sc);
                size_t off = ((size_t)(bb * 8 + h) * MLM + m) * 64 + d;
                *(float2*)&dst[off] = o;
                *(__half2*)&hdst[off] = __floats2half2_rn(o.x, o.y);
            }
        }
    }
}

// ================= attn2 = softmax(q_l k_l^T), 64 CTAs =================
__global__ __launch_bounds__(256) void attn2_kernel() {
    extern __shared__ float sklf[];
    int rt = blockIdx.x, bh = blockIdx.y;
    int tid = threadIdx.x;
    int row = rt * 64 + (tid >> 2);
    int cg = tid & 3;

    const float4* klsrc = (const float4*)(g_kl + (size_t)bh * MLM * 64);
    float4* kld = (float4*)sklf;
#pragma unroll
    for (int i = 0; i < 16; i++) kld[tid + i * 256] = klsrc[tid + i * 256];

    float4 q[16];
    const float4* qp = (const float4*)(g_ql + (size_t)(bh * MLM + row) * 64);
#pragma unroll
    for (int i = 0; i < 16; i++) q[i] = qp[i];
    __syncthreads();

    float p[64];
    float sum = 0.f;
    const float4* klb = (const float4*)sklf + cg * 64 * 16;
    for (int j = 0; j < 64; j++) {
        const float4* kr = klb + j * 16;
        float s = 0.f;
#pragma unroll
        for (int d = 0; d < 16; d++) {
            float4 a = q[d], b = kr[d];
            s += a.x * b.x + a.y * b.y + a.z * b.z + a.w * b.w;
        }
        p[j] = __expf(s);
        sum += p[j];
    }
    sum += __shfl_xor_sync(0xffffffffu, sum, 1);
    sum += __shfl_xor_sync(0xffffffffu, sum, 2);
    float inv = 1.f / sum;
    float* arow = g_attn2 + (size_t)bh * 65536 + (size_t)row * 256 + cg * 64;
#pragma unroll
    for (int j = 0; j < 64; j += 4)
        *(float4*)&arow[j] = make_float4(p[j] * inv, p[j + 1] * inv,
                                         p[j + 2] * inv, p[j + 3] * inv);
}

// ================= max column-sum of attn2 =================
__global__ __launch_bounds__(256) void colmax_kernel() {
    int bh = blockIdx.x;
    int j = threadIdx.x;
    const float* a = g_attn2 + (size_t)bh * 65536;
    float s = 0.f;
    for (int m2 = 0; m2 < 256; m2++) s += a[m2 * 256 + j];
    __shared__ float red[256];
    red[j] = s;
    __syncthreads();
    for (int o = 128; o; o >>= 1) {
        if (j < o) red[j] = fmaxf(red[j], red[j + o]);
        __syncthreads();
    }
    if (j == 0) atomicMax(&g_maxc_bits, __float_as_int(red[0]));
}

__global__ void z0_kernel() {
    int idx = blockIdx.x * 256 + threadIdx.x;
    int bh = idx >> 16;
    int i = (idx >> 8) & 255;
    int j = idx & 255;
    float scale = 1.f / __int_as_float(g_maxc_bits);
    g_Za[idx] = g_attn2[(bh << 16) + (j << 8) + i] * scale;
}

// ================= buffer selector =================
__device__ __forceinline__ float* pickBuf(int id) {
    switch (id) {
        case 0: return g_attn2;
        case 1: return g_Y;
        case 2: return g_P;
        case 3: return g_Qm;
        case 4: return g_Za;
        default: return g_Zb;
    }
}

// ================= persistent pinv with register-prefetch pipelining =================
struct PinvSmem {
    __nv_bfloat16 Ah[128][40];
    __nv_bfloat16 Al[128][40];
    __nv_bfloat16 Bh[64][40];
    __nv_bfloat16 Bl[64][40];
};

__device__ __forceinline__ void gbarrier(int step) {
    __syncthreads();
    if (threadIdx.x == 0) {
        __threadfence();
        atomicAdd(&g_bar, 1u);
        unsigned target = 128u * (unsigned)step;
        while (*(volatile unsigned*)&g_bar < target) { }
    }
    __syncthreads();
}

__device__ void pinv_gemm(PinvSmem& S, int cId, int aId, int bId,
                          float beta, float sgn, float alpha, bool full,
                          int mBase, int nBase, int bh) {
    const float* A = pickBuf(aId) + (size_t)bh * 65536;
    const float* B = pickBuf(bId) + (size_t)bh * 65536;
    float*       C = pickBuf(cId) + (size_t)bh * 65536;

    int tid = threadIdx.x, lane = tid & 31, w = tid >> 5;
    int wm = w & 3, wn = w >> 2;
    int lr = lane & 15, lh = lane >> 4;

    float acc[2][4][4];
#pragma unroll
    for (int i = 0; i < 2; i++)
#pragma unroll
        for (int j = 0; j < 4; j++)
#pragma unroll
            for (int c = 0; c < 4; c++) acc[i][j][c] = 0.f;

    float4 rA[4];
    float rB[8];
    auto loadA = [&](int ch, float4* ra) {
#pragma unroll
        for (int i = 0; i < 4; i++) {
            int idx = tid + i * 256;
            int r = idx >> 3, c4 = (idx & 7) * 4;
            ra[i] = __ldcg((const float4*)&A[(size_t)(mBase + r) * 256 + ch * 32 + c4]);
        }
    };
    auto loadB = [&](int ch, float* rb) {
#pragma unroll
        for (int kl = 0; kl < 4; kl++) {
            int gk = ch * 32 + w * 4 + kl;
#pragma unroll
            for (int nh = 0; nh < 2; nh++) {
                int n = nh * 32 + lane;
                rb[kl * 2 + nh] = __ldcg(&B[(size_t)gk * 256 + nBase + n]);
            }
        }
    };

    loadA(0, rA);
    loadB(0, rB);

    for (int ch = 0; ch < 8; ch++) {
        if (ch) __syncthreads();
#pragma unroll
        for (int i = 0; i < 4; i++) {
            int idx = tid + i * 256;
            int r = idx >> 3, c4 = (idx & 7) * 4;
            float4 v = rA[i];
            __nv_bfloat16 h0 = __float2bfloat16(v.x), h1 = __float2bfloat16(v.y);
            __nv_bfloat16 h2 = __float2bfloat16(v.z), h3 = __float2bfloat16(v.w);
            S.Ah[r][c4 + 0] = h0; S.Ah[r][c4 + 1] = h1;
            S.Ah[r][c4 + 2] = h2; S.Ah[r][c4 + 3] = h3;
            if (full) {
                S.Al[r][c4 + 0] = __float2bfloat16(v.x - __bfloat162float(h0));
                S.Al[r][c4 + 1] = __float2bfloat16(v.y - __bfloat162float(h1));
                S.Al[r][c4 + 2] = __float2bfloat16(v.z - __bfloat162float(h2));
                S.Al[r][c4 + 3] = __float2bfloat16(v.w - __bfloat162float(h3));
            }
        }
#pragma unroll
        for (int kl = 0; kl < 4; kl++) {
            int gk = ch * 32 + w * 4 + kl;
#pragma unroll
            for (int nh = 0; nh < 2; nh++) {
                int n = nh * 32 + lane;
                float v = rB[kl * 2 + nh];
                v = sgn * v + ((gk == nBase + n) ? beta : 0.f);
                __nv_bfloat16 h = __float2bfloat16(v);
                S.Bh[n][w * 4 + kl] = h;
                if (full) S.Bl[n][w * 4 + kl] = __float2bfloat16(v - __bfloat162float(h));
            }
        }
        float4 rA2[4];
        float rB2[8];
        if (ch + 1 < 8) {
            loadA(ch + 1, rA2);
            loadB(ch + 1, rB2);
        }
        __syncthreads();
#pragma unroll
        for (int ks = 0; ks < 2; ks++) {
            int kc = ks * 16 + lh * 8;
            unsigned ah[2][4], al[2][4];
#pragma unroll
            for (int mi = 0; mi < 2; mi++) {
                int rowA = wm * 32 + mi * 16 + lr;
                ldm4(ah[mi], smem_u32(&S.Ah[rowA][kc]));
                if (full) ldm4(al[mi], smem_u32(&S.Al[rowA][kc]));
            }
#pragma unroll
            for (int nt = 0; nt < 2; nt++) {
                int rowB = wn * 32 + nt * 16 + lr;
                unsigned bhf[4], blf[4];
                ldm4(bhf, smem_u32(&S.Bh[rowB][kc]));
                if (full) ldm4(blf, smem_u32(&S.Bl[rowB][kc]));
#pragma unroll
                for (int mi = 0; mi < 2; mi++) {
#pragma unroll
                    for (int ns = 0; ns < 2; ns++) {
                        float* cc = acc[mi][nt * 2 + ns];
                        mma16816(cc, ah[mi], bhf[ns], bhf[ns + 2]);
                        if (full) {
                            mma16816(cc, ah[mi], blf[ns], blf[ns + 2]);
                            mma16816(cc, al[mi], bhf[ns], bhf[ns + 2]);
                        }
                    }
                }
            }
        }
        if (ch + 1 < 8) {
#pragma unroll
            for (int i = 0; i < 4; i++) rA[i] = rA2[i];
#pragma unroll
            for (int i = 0; i < 8; i++) rB[i] = rB2[i];
        }
    }
#pragma unroll
    for (int mi = 0; mi < 2; mi++) {
#pragma unroll
        for (int jn = 0; jn < 4; jn++) {
            int gc = nBase + wn * 32 + jn * 8 + (lane & 3) * 2;
#pragma unroll
            for (int half = 0; half < 2; half++) {
                int gr = mBase + wm * 32 + mi * 16 + (lane >> 2) + half * 8;
                float2 o = make_float2(acc[mi][jn][half * 2] * alpha,
                                       acc[mi][jn][half * 2 + 1] * alpha);
                *(float2*)&C[(size_t)gr * 256 + gc] = o;
            }
        }
    }
}

__global__ __launch_bounds__(256) void pinv_persist() {
    __shared__ PinvSmem S;
    int bh = blockIdx.z;
    int mBase = blockIdx.y * 128, nBase = blockIdx.x * 64;
    int step = 0;
    for (int it = 0; it < 6; it++) {
        bool full = (it == 5);
        int zc = 4 + (it & 1), zn = 5 - (it & 1);
        pinv_gemm(S, 1, 0, zc, 0.f, 1.f, 1.f, full, mBase, nBase, bh);
        gbarrier(++step);
        pinv_gemm(S, 2, 1, 1, 7.f, -1.f, 1.f, full, mBase, nBase, bh);
        gbarrier(++step);
        pinv_gemm(S, 3, 1, 2, 15.f, -1.f, 1.f, full, mBase, nBase, bh);
        gbarrier(++step);
        pinv_gemm(S, zn, zc, 3, 13.f, -1.f, 0.25f, full, mBase, nBase, bh);
        gbarrier(++step);
    }
}

// ================= W3 GEMM: W3h(fp16, row-major [m][d]) = Za @ W2 =================
__global__ __launch_bounds__(256) void gemm_w3_kernel() {
    int bh = blockIdx.z, mt = blockIdx.y;
    const float* A  = g_Za + (size_t)bh * 65536;
    const float* Bp = g_W2 + (size_t)bh * 256 * 64;
    __half*      C  = g_W3h + (size_t)bh * 256 * 64;
    __shared__ float As[16][64];
    __shared__ float Bs[16][64];
    int tid = threadIdx.x;
    int ar = tid >> 2, ac = (tid & 3) * 4;
    int br = tid >> 4, bc = (tid & 15) * 4;
    int ty = tid >> 4, tx = tid & 15;
    float acc[4][4];
#pragma unroll
    for (int i = 0; i < 4; i++)
#pragma unroll
        for (int j = 0; j < 4; j++) acc[i][j] = 0.f;

    for (int k0 = 0; k0 < 256; k0 += 16) {
        float4 av = *(const float4*)&A[(size_t)(mt * 64 + ar) * 256 + k0 + ac];
        As[ac + 0][ar] = av.x; As[ac + 1][ar] = av.y;
        As[ac + 2][ar] = av.z; As[ac + 3][ar] = av.w;
        float4 bv = *(const float4*)&Bp[(size_t)(k0 + br) * 64 + bc];
        *(float4*)&Bs[br][bc] = bv;
        __syncthreads();
#pragma unroll
        for (int kk = 0; kk < 16; kk++) {
            float4 a4 = *(const float4*)&As[kk][ty * 4];
            float4 b4 = *(const float4*)&Bs[kk][tx * 4];
            acc[0][0] += a4.x * b4.x; acc[0][1] += a4.x * b4.y; acc[0][2] += a4.x * b4.z; acc[0][3] += a4.x * b4.w;
            acc[1][0] += a4.y * b4.x; acc[1][1] += a4.y * b4.y; acc[1][2] += a4.y * b4.z; acc[1][3] += a4.y * b4.w;
            acc[2][0] += a4.z * b4.x; acc[2][1] += a4.z * b4.y; acc[2][2] += a4.z * b4.z; acc[2][3] += a4.z * b4.w;
            acc[3][0] += a4.w * b4.x; acc[3][1] += a4.w * b4.y; acc[3][2] += a4.w * b4.z; acc[3][3] += a4.w * b4.w;
        }
        __syncthreads();
    }
#pragma unroll
    for (int i = 0; i < 4; i++) {
        int m = mt * 64 + ty * 4 + i;
        __half2 h01 = __floats2half2_rn(acc[i][0], acc[i][1]);
        __half2 h23 = __floats2half2_rn(acc[i][2], acc[i][3]);
        *(__half2*)&C[(size_t)m * 64 + tx * 4] = h01;
        *(__half2*)&C[(size_t)m * 64 + tx * 4 + 2] = h23;
    }
}

// ================= flash W2 on tensor cores (trans-ldmatrix for V) =================
__global__ __launch_bounds__(256) void flash_w2_mma() {
    __shared__ __align__(16) __half sql[128][72];
    __shared__ __align__(16) __half sk[64][72];
    __shared__ __align__(16) __half sv[64][72];

    int tid = threadIdx.x, lane = tid & 31, w = tid >> 5;
    int chunk = blockIdx.x, mblk = blockIdx.y, bh = blockIdx.z;
    int lr = lane & 15, lh = lane >> 4;

    const __half* qlh = g_qlh + (size_t)(bh * MLM + mblk * 128) * 64;
#pragma unroll
    for (int i = 0; i < 4; i++) {
        int idx = tid + i * 256;
        int r = idx >> 3, c = (idx & 7) * 8;
        *(uint4*)&sql[r][c] = *(const uint4*)&qlh[(size_t)r * 64 + c];
    }
    __syncthreads();
    unsigned qa[4][4];
#pragma unroll
    for (int ks = 0; ks < 4; ks++)
        ldm4(qa[ks], smem_u32(&sql[w * 16 + lr][ks * 16 + lh * 8]));

    float outacc[8][4];
#pragma unroll
    for (int i = 0; i < 8; i++)
#pragma unroll
        for (int c = 0; c < 4; c++) outacc[i][c] = 0.f;
    float rsA = 0.f, rsB = 0.f;

    const __half* kb = g_kh + (size_t)bh * NSEQ * 64;
    const __half* vb = g_vh + (size_t)bh * NSEQ * 64;

    for (int it = 0; it < 32; it++) {
        int s0 = chunk * 2048 + it * 64;
        __syncthreads();
#pragma unroll
        for (int i = 0; i < 2; i++) {
            int idx = tid + i * 256;
            int r = idx >> 3, c = (idx & 7) * 8;
            *(uint4*)&sk[r][c] = *(const uint4*)&kb[(size_t)(s0 + r) * 64 + c];
            *(uint4*)&sv[r][c] = *(const uint4*)&vb[(size_t)(s0 + r) * 64 + c];
        }
        __syncthreads();
        float sf[8][4];
#pragma unroll
        for (int i = 0; i < 8; i++)
#pragma unroll
            for (int c = 0; c < 4; c++) sf[i][c] = 0.f;
#pragma unroll
        for (int ks = 0; ks < 4; ks++) {
#pragma unroll
            for (int nf4 = 0; nf4 < 4; nf4++) {
                unsigned bbf[4];
                ldm4(bbf, smem_u32(&sk[nf4 * 16 + lr][ks * 16 + lh * 8]));
                mmaf16(sf[nf4 * 2], qa[ks], bbf[0], bbf[2]);
                mmaf16(sf[nf4 * 2 + 1], qa[ks], bbf[1], bbf[3]);
            }
        }
#pragma unroll
        for (int nf = 0; nf < 8; nf++) {
            sf[nf][0] = fexp(sf[nf][0]); sf[nf][1] = fexp(sf[nf][1]);
            sf[nf][2] = fexp(sf[nf][2]); sf[nf][3] = fexp(sf[nf][3]);
            rsA += sf[nf][0] + sf[nf][1];
            rsB += sf[nf][2] + sf[nf][3];
        }
#pragma unroll
        for (int kk = 0; kk < 4; kk++) {
            unsigned pa[4];
            pa[0] = packh2(sf[2 * kk][0], sf[2 * kk][1]);
            pa[1] = packh2(sf[2 * kk][2], sf[2 * kk][3]);
            pa[2] = packh2(sf[2 * kk + 1][0], sf[2 * kk + 1][1]);
            pa[3] = packh2(sf[2 * kk + 1][2], sf[2 * kk + 1][3]);
#pragma unroll
            for (int nf4 = 0; nf4 < 4; nf4++) {
                unsigned bbf[4];
                ldm4t(bbf, smem_u32(&sv[kk * 16 + lr][nf4 * 16 + lh * 8]));
                mmaf16(outacc[nf4 * 2], pa, bbf[0], bbf[1]);
                mmaf16(outacc[nf4 * 2 + 1], pa, bbf[2], bbf[3]);
            }
        }
    }
    rsA += __shfl_xor_sync(0xffffffffu, rsA, 1);
    rsA += __shfl_xor_sync(0xffffffffu, rsA, 2);
    rsB += __shfl_xor_sync(0xffffffffu, rsB, 1);
    rsB += __shfl_xor_sync(0xffffffffu, rsB, 2);

    int rA = mblk * 128 + w * 16 + (lane >> 2);
    int rB = rA + 8;
    float* wpA = g_Wpart + (size_t)((bh * 4 + chunk) * MLM + rA) * 64;
    float* wpB = g_Wpart + (size_t)((bh * 4 + chunk) * MLM + rB) * 64;
#pragma unroll
    for (int nf = 0; nf < 8; nf++) {
        int d = nf * 8 + (lane & 3) * 2;
        *(float2*)&wpA[d] = make_float2(outacc[nf][0], outacc[nf][1]);
        *(float2*)&wpB[d] = make_float2(outacc[nf][2], outacc[nf][3]);
    }
    if ((lane & 3) == 0) {
        g_Spart[(bh * 4 + chunk) * MLM + rA] = rsA;
        g_Spart[(bh * 4 + chunk) * MLM + rB] = rsB;
    }
}

__global__ void combine_w2_kernel() {
    int idx = blockIdx.x * 256 + threadIdx.x;
    int bh = idx >> 14;
    int m = (idx >> 6) & 255;
    int d = idx & 63;
    float num = 0.f, den = 0.f;
#pragma unroll
    for (int c = 0; c < 4; c++) {
        num += g_Wpart[(size_t)((bh * 4 + c) * MLM + m) * 64 + d];
        den += g_Spart[(bh * 4 + c) * MLM + m];
    }
    g_W2[(bh * MLM + m) * 64 + d] = num / den;
}

// ================= attn1 + conv (double-buffered tiles, trans-ldmatrix for W3) =======
__global__ __launch_bounds__(256) void attn1_mma(const float* __restrict__ convw) {
    extern __shared__ char smx[];
    __half (*sq)[72]  = (__half(*)[72])(smx);                 // 128 rows
    __half (*skl)[72] = (__half(*)[72])(smx + 18432);         // 2 x 64 rows
    __half (*sw3)[72] = (__half(*)[72])(smx + 36864);         // 2 x 64 rows
    __half (*sv)[72]  = (__half(*)[72])(smx + 55296);         // 160 rows
    float* cw = (float*)(smx + 78336);

    int tid = threadIdx.x, lane = tid & 31, w = tid >> 5;
    int ntile = blockIdx.x, bh = blockIdx.y;
    int h = bh & 7, bb2 = bh >> 3;
    int n0 = ntile * 128;
    int lr = lane & 15, lh = lane >> 4;

    if (tid < KSZ) cw[tid] = convw[h * KSZ + tid];

    const __half* klb = g_klh + (size_t)bh * MLM * 64;
    const __half* w3b = g_W3h + (size_t)bh * MLM * 64;

    auto load_tile = [&](int lc) {
        int b = lc & 1;
#pragma unroll
        for (int u = 0; u < 2; u++) {
            int idx = tid + u * 256;          // 0..511
            int r = idx >> 3, c8 = idx & 7;   // 8 16B-units per 64-half row
            unsigned so = smem_u32(&skl[b * 64 + r][0]) + c8 * 16u;
            cpasync16(so, klb + (size_t)(lc * 64 + r) * 64 + c8 * 8);
            unsigned so2 = smem_u32(&sw3[b * 64 + r][0]) + c8 * 16u;
            cpasync16(so2, w3b + (size_t)(lc * 64 + r) * 64 + c8 * 8);
        }
        CP_COMMIT();
    };
    load_tile(0);

    const __half* qb = g_qh + ((size_t)bh * NSEQ + n0) * 64;
#pragma unroll
    for (int i = 0; i < 4; i++) {
        int idx = tid + i * 256;
        int r = idx >> 3, c = (idx & 7) * 8;
        *(uint4*)&sq[r][c] = *(const uint4*)&qb[(size_t)r * 64 + c];
    }
    const __half* vb2 = g_vh + (size_t)bh * NSEQ * 64;
#pragma unroll
    for (int i = 0; i < 5; i++) {
        int idx = tid + i * 256;
        int r = idx >> 3, c = (idx & 7) * 8;
        int gr = n0 - 16 + r;
        uint4 z = make_uint4(0u, 0u, 0u, 0u);
        if (gr >= 0 && gr < NSEQ) z = *(const uint4*)&vb2[(size_t)gr * 64 + c];
        *(uint4*)&sv[r][c] = z;
    }
    __syncthreads();

    unsigned qa[4][4];
#pragma unroll
    for (int ks = 0; ks < 4; ks++)
        ldm4(qa[ks], smem_u32(&sq[w * 16 + lr][ks * 16 + lh * 8]));

    float outacc[8][4];
#pragma unroll
    for (int i = 0; i < 8; i++)
#pragma unroll
        for (int c = 0; c < 4; c++) outacc[i][c] = 0.f;
    float rsA = 0.f, rsB = 0.f;

    for (int lc = 0; lc < 4; lc++) {
        __syncthreads();                       // prior compute done; safe to refill
        if (lc + 1 < 4) {
            load_tile(lc + 1);
            asm volatile("cp.async.wait_group 1;" ::: "memory");
        } else {
            asm volatile("cp.async.wait_group 0;" ::: "memory");
        }
        __syncthreads();
        int bsel = (lc & 1) * 64;

        float sf[8][4];
#pragma unroll
        for (int i = 0; i < 8; i++)
#pragma unroll
            for (int c = 0; c < 4; c++) sf[i][c] = 0.f;
#pragma unroll
        for (int ks = 0; ks < 4; ks++) {
#pragma unroll
            for (int nf4 = 0; nf4 < 4; nf4++) {
                unsigned bbf[4];
                ldm4(bbf, smem_u32(&skl[bsel + nf4 * 16 + lr][ks * 16 + lh * 8]));
                mmaf16(sf[nf4 * 2], qa[ks], bbf[0], bbf[2]);
                mmaf16(sf[nf4 * 2 + 1], qa[ks], bbf[1], bbf[3]);
            }
        }
#pragma unroll
        for (int nf = 0; nf < 8; nf++) {
            sf[nf][0] = fexp(sf[nf][0]); sf[nf][1] = fexp(sf[nf][1]);
            sf[nf][2] = fexp(sf[nf][2]); sf[nf][3] = fexp(sf[nf][3]);
            rsA += sf[nf][0] + sf[nf][1];
            rsB += sf[nf][2] + sf[nf][3];
        }
#pragma unroll
        for (int kk = 0; kk < 4; kk++) {
            unsigned pa[4];
            pa[0] = packh2(sf[2 * kk][0], sf[2 * kk][1]);
            pa[1] = packh2(sf[2 * kk][2], sf[2 * kk][3]);
            pa[2] = packh2(sf[2 * kk + 1][0], sf[2 * kk + 1][1]);
            pa[3] = packh2(sf[2 * kk + 1][2], sf[2 * kk + 1][3]);
#pragma unroll
            for (int nf4 = 0; nf4 < 4; nf4++) {
                unsigned bbf[4];
                ldm4t(bbf, smem_u32(&sw3[bsel + kk * 16 + lr][nf4 * 16 + lh * 8]));
                mmaf16(outacc[nf4 * 2], pa, bbf[0], bbf[1]);
                mmaf16(outacc[nf4 * 2 + 1], pa, bbf[2], bbf[3]);
            }
        }
    }
    rsA += __shfl_xor_sync(0xffffffffu, rsA, 1);
    rsA += __shfl_xor_sync(0xffffffffu, rsA, 2);
    rsB += __shfl_xor_sync(0xffffffffu, rsB, 1);
    rsB += __shfl_xor_sync(0xffffffffu, rsB, 2);
    float invA = 1.f / rsA, invB = 1.f / rsB;

    int lrA = w * 16 + (lane >> 2);
#pragma unroll
    for (int nf = 0; nf < 8; nf++) {
        int d = nf * 8 + (lane & 3) * 2;
        float a0 = 0.f, a1 = 0.f, b0 = 0.f, b1 = 0.f;
#pragma unroll
        for (int t = 0; t < KSZ; t++) {
            float wv = cw[t];
            float2 fA = __half22float2(*(__half2*)&sv[lrA + t][d]);
            float2 fB = __half22float2(*(__half2*)&sv[lrA + 8 + t][d]);
            a0 = fmaf(wv, fA.x, a0); a1 = fmaf(wv, fA.y, a1);
            b0 = fmaf(wv, fB.x, b0); b1 = fmaf(wv, fB.y, b1);
        }
        outacc[nf][0] = outacc[nf][0] * invA + a0;
        outacc[nf][1] = outacc[nf][1] * invA + a1;
        outacc[nf][2] = outacc[nf][2] * invB + b0;
        outacc[nf][3] = outacc[nf][3] * invB + b1;
    }

    int nA = n0 + lrA, nB = nA + 8;
    __half* oA = g_A16 + (size_t)(bb2 * NSEQ + nA) * 512 + h * 64;
    __half* oB = g_A16 + (size_t)(bb2 * NSEQ + nB) * 512 + h * 64;
#pragma unroll
    for (int nf = 0; nf < 8; nf++) {
        int d = nf * 8 + (lane & 3) * 2;
        *(__half2*)&oA[d] = __floats2half2_rn(outacc[nf][0], outacc[nf][1]);
        *(__half2*)&oB[d] = __floats2half2_rn(outacc[nf][2], outacc[nf][3]);
    }
}

// ================= host launcher (three-stream overlap) =================
extern "C" void kernel_launch(void* const* d_in, const int* in_sizes, int n_in,
                              void* d_out, int out_size) {
    const float* x     = (const float*)d_in[0];
    const float* ln_g  = (const float*)d_in[1];
    const float* ln_b  = (const float*)d_in[2];
    const float* W_qkv = (const float*)d_in[3];
    const float* W_out = (const float*)d_in[4];
    const float* b_out = (const float*)d_in[5];
    const float* convw = (const float*)d_in[6];
    float* out = (float*)d_out;

    static cudaStream_t sB = nullptr, sC = nullptr;
    static cudaEvent_t eFork = nullptr, eLm = nullptr, eJoin = nullptr,
                       eKV = nullptr, eW2 = nullptr;
    if (!sB) {
        cudaStreamCreateWithFlags(&sB, cudaStreamNonBlocking);
        cudaStreamCreateWithFlags(&sC, cudaStreamNonBlocking);
        cudaEventCreateWithFlags(&eFork, cudaEventDisableTiming);
        cudaEventCreateWithFlags(&eLm, cudaEventDisableTiming);
        cudaEventCreateWithFlags(&eJoin, cudaEventDisableTiming);
        cudaEventCreateWithFlags(&eKV, cudaEventDisableTiming);
        cudaEventCreateWithFlags(&eW2, cudaEventDisableTiming);
        cudaFuncSetAttribute(attn1_mma, cudaFuncAttributeMaxDynamicSharedMemorySize, 78720);
        cudaFuncSetAttribute(gemm_lm_kernel, cudaFuncAttributeMaxDynamicSharedMemorySize, 81920);
        cudaFuncSetAttribute(gemm16_kernel, cudaFuncAttributeMaxDynamicSharedMemorySize, 73728);
        cudaFuncSetAttribute(attn2_kernel, cudaFuncAttributeMaxDynamicSharedMemorySize, 65536);
    }

    __nv_bfloat16 *bqh, *bql;
    cudaGetSymbolAddress((void**)&bqh, g_Bqh);
    cudaGetSymbolAddress((void**)&bql, g_Bql);
    __half *b16q, *b16o;
    cudaGetSymbolAddress((void**)&b16q, g_B16q);
    cudaGetSymbolAddress((void**)&b16o, g_B16o);

    ln_kernel<<<Bb * NSEQ, 128>>>(x, ln_g, ln_b);  // g_xn + g_A16 + resets

    // ---- fork ----
    cudaEventRecord(eFork, 0);
    cudaStreamWaitEvent(sB, eFork, 0);

    // Chain B (stream sB): landmark path -> attn2 -> z0 -> persistent pinv
    xnlm_conv_kernel<<<1024, 256, 0, sB>>>();
    convW_kernel<<<dim3(32, 16), 1024, 0, sB>>>(W_qkv, 1536, bqh, bql);  // q|k cols only
    gemm_lm_kernel<<<dim3(8, 4), 256, 81920, sB>>>(bqh, bql);
    cudaEventRecord(eLm, sB);
    attn2_kernel<<<dim3(4, 16), 256, 65536, sB>>>();
    colmax_kernel<<<16, 256, 0, sB>>>();
    z0_kernel<<<4096, 256, 0, sB>>>();
    pinv_persist<<<dim3(4, 2, 16), 256, 0, sB>>>();
    cudaEventRecord(eJoin, sB);

    // Chain A (default stream): kv GEMM first, then q GEMM (overlaps flash_w2)
    convW16_kernel<<<dim3(48, 16), 1024>>>(W_qkv, 1536, b16q);
    gemm16_kernel<<<dim3(8, 128), 256, 73728>>>(b16q, 0, 4, nullptr, nullptr);  // k, v
    cudaEventRecord(eKV, 0);
    gemm16_kernel<<<dim3(4, 128), 256, 73728>>>(b16q, 0, 0, nullptr, nullptr);  // q
    convW16_kernel<<<dim3(16, 16), 1024>>>(W_out, 512, b16o);

    // Chain C (stream sC): flash_w2 as soon as kv + landmarks are ready
    cudaStreamWaitEvent(sC, eKV, 0);
    cudaStreamWaitEvent(sC, eLm, 0);
    flash_w2_mma<<<dim3(4, 2, 16), 256, 0, sC>>>();
    combine_w2_kernel<<<1024, 256, 0, sC>>>();
    cudaEventRecord(eW2, sC);

    // ---- join on default stream ----
    cudaStreamWaitEvent(0, eW2, 0);
    cudaStreamWaitEvent(0, eJoin, 0);
    gemm_w3_kernel<<<dim3(1, 4, 16), 256>>>();   // writes g_W3h [m][d] fp16
    attn1_mma<<<dim3(64, 16), 256, 78720>>>(convw);

    gemm16_kernel<<<dim3(4, 128), 256, 73728>>>(b16o, 1, 0, b_out, out);
}